// round 1
// baseline (speedup 1.0000x reference)
#include <cuda_runtime.h>
#include <math.h>

// Problem dims
#define BB 4
#define LL 2048
#define DD 1024
#define HH 16
#define HD 64          // head dim (KD == VD == 64)
#define MM (BB * LL)   // 8192 rows

// ------------------------- scratch (static device globals; no allocs) ---------
__device__ float g_Q[MM * DD];
__device__ float g_K[MM * DD];
__device__ float g_V[MM * DD];
__device__ float g_O[MM * DD];
__device__ float g_R[MM * DD];

// ------------------------- SGEMM: C = A@B + bias (+ residual) ----------------
// A [M,K] row-major, B [K,N] row-major. BM=BN=128, BK=8, 256 threads, 8x8 micro.
__global__ __launch_bounds__(256) void sgemm_bias_kernel(
    const float* __restrict__ A, const float* __restrict__ Bw,
    const float* __restrict__ bias, const float* __restrict__ R,
    float* __restrict__ C, int M, int N, int K)
{
    const int BM = 128, BN = 128, BK = 8;
    __shared__ float As[BK][BM];
    __shared__ float Bs[BK][BN];

    const int tid = threadIdx.x;
    const int bx = blockIdx.x, by = blockIdx.y;
    const int ty = tid >> 4, tx = tid & 15;

    const int aRow = tid >> 1;
    const int aCol = (tid & 1) * 4;
    const int bRow = tid >> 5;
    const int bCol = (tid & 31) * 4;

    const float* Ab = A + (size_t)(by * BM) * K;
    const float* Bb = Bw + bx * BN;

    float acc[8][8];
#pragma unroll
    for (int i = 0; i < 8; i++)
#pragma unroll
        for (int j = 0; j < 8; j++) acc[i][j] = 0.f;

    for (int kb = 0; kb < K; kb += BK) {
        float4 a4 = *(const float4*)(Ab + (size_t)aRow * K + kb + aCol);
        As[aCol + 0][aRow] = a4.x;
        As[aCol + 1][aRow] = a4.y;
        As[aCol + 2][aRow] = a4.z;
        As[aCol + 3][aRow] = a4.w;
        *(float4*)&Bs[bRow][bCol] =
            *(const float4*)(Bb + (size_t)(kb + bRow) * N + bCol);
        __syncthreads();

#pragma unroll
        for (int k = 0; k < BK; k++) {
            float ra[8], rb[8];
            *(float4*)(ra)     = *(float4*)&As[k][ty * 8];
            *(float4*)(ra + 4) = *(float4*)&As[k][ty * 8 + 4];
            *(float4*)(rb)     = *(float4*)&Bs[k][tx * 8];
            *(float4*)(rb + 4) = *(float4*)&Bs[k][tx * 8 + 4];
#pragma unroll
            for (int i = 0; i < 8; i++)
#pragma unroll
                for (int j = 0; j < 8; j++)
                    acc[i][j] = fmaf(ra[i], rb[j], acc[i][j]);
        }
        __syncthreads();
    }

    float bv[8];
    *(float4*)(bv)     = *(const float4*)(bias + bx * BN + tx * 8);
    *(float4*)(bv + 4) = *(const float4*)(bias + bx * BN + tx * 8 + 4);

#pragma unroll
    for (int i = 0; i < 8; i++) {
        const size_t row = (size_t)(by * BM + ty * 8 + i);
        const size_t off = row * N + bx * BN + tx * 8;
#pragma unroll
        for (int jj = 0; jj < 8; jj += 4) {
            float4 c;
            c.x = acc[i][jj + 0] + bv[jj + 0];
            c.y = acc[i][jj + 1] + bv[jj + 1];
            c.z = acc[i][jj + 2] + bv[jj + 2];
            c.w = acc[i][jj + 3] + bv[jj + 3];
            if (R) {
                float4 r = *(const float4*)(R + off + jj);
                c.x += r.x; c.y += r.y; c.z += r.z; c.w += r.w;
            }
            *(float4*)(C + off + jj) = c;
        }
    }
}

// ------------------------- Flash attention (fp32, non-causal) -----------------
// Per CTA: one (b,h), 128 queries; loop over 64-key blocks with online softmax.
// Thread layout 16x16: rows ty*8..+7, cols tx*4..+3.
// smem: Qt [64][128] (scaled by 1/8, transposed), KP shared region
// (K transposed stride 65 -> reused for P transposed stride 129), Vs [64][64].
#define AT_BQ 128
#define AT_BK 64
#define SM_QT (64 * 128)
#define SM_KP (64 * 129)
#define SM_VS (64 * 64)
#define ATTN_SMEM_BYTES ((SM_QT + SM_KP + SM_VS) * sizeof(float))

__global__ __launch_bounds__(256, 2) void attn_kernel(
    const float* __restrict__ Q, const float* __restrict__ K,
    const float* __restrict__ V, float* __restrict__ O)
{
    extern __shared__ float sm[];
    float* Qt = sm;                 // stride 128
    float* KP = sm + SM_QT;         // K: stride 65, P: stride 129
    float* Vs = KP + SM_KP;         // stride 64

    const int tid = threadIdx.x;
    const int ty = tid >> 4, tx = tid & 15;
    const int bh = blockIdx.y;
    const int b = bh >> 4;          // H = 16
    const int h = bh & 15;
    const int q0 = blockIdx.x * AT_BQ;
    const size_t base = (size_t)b * LL * DD + (size_t)h * HD;

    // Load Q tile transposed, pre-scaled by 1/sqrt(64) = 0.125
#pragma unroll
    for (int it = 0; it < 8; it++) {
        int fidx = tid + it * 256;          // 0..2047 float4s
        int r = fidx >> 4;
        int d4 = (fidx & 15) * 4;
        float4 v = *(const float4*)(Q + base + (size_t)(q0 + r) * DD + d4);
        Qt[(d4 + 0) * 128 + r] = v.x * 0.125f;
        Qt[(d4 + 1) * 128 + r] = v.y * 0.125f;
        Qt[(d4 + 2) * 128 + r] = v.z * 0.125f;
        Qt[(d4 + 3) * 128 + r] = v.w * 0.125f;
    }

    float m[8], l[8], o[8][4];
#pragma unroll
    for (int i = 0; i < 8; i++) {
        m[i] = -1e30f; l[i] = 0.f;
#pragma unroll
        for (int j = 0; j < 4; j++) o[i][j] = 0.f;
    }

    for (int c0 = 0; c0 < LL; c0 += AT_BK) {
        // load K (transposed, stride 65) and V (row-major, stride 64)
#pragma unroll
        for (int it = 0; it < 4; it++) {
            int fidx = tid + it * 256;      // 0..1023 float4s
            int c = fidx >> 4;
            int d4 = (fidx & 15) * 4;
            const size_t gro = base + (size_t)(c0 + c) * DD + d4;
            float4 kv = *(const float4*)(K + gro);
            KP[(d4 + 0) * 65 + c] = kv.x;
            KP[(d4 + 1) * 65 + c] = kv.y;
            KP[(d4 + 2) * 65 + c] = kv.z;
            KP[(d4 + 3) * 65 + c] = kv.w;
            *(float4*)(Vs + c * 64 + d4) = *(const float4*)(V + gro);
        }
        __syncthreads();

        // S = (Q/8) @ K^T  : per-thread 8x4 tile
        float Sv[8][4];
#pragma unroll
        for (int i = 0; i < 8; i++)
#pragma unroll
            for (int j = 0; j < 4; j++) Sv[i][j] = 0.f;

#pragma unroll 4
        for (int d = 0; d < 64; d++) {
            float rq[8], rk[4];
            const float* qrow = Qt + d * 128 + ty * 8;
            const float* krow = KP + d * 65 + tx * 4;
#pragma unroll
            for (int i = 0; i < 8; i++) rq[i] = qrow[i];
#pragma unroll
            for (int j = 0; j < 4; j++) rk[j] = krow[j];
#pragma unroll
            for (int i = 0; i < 8; i++)
#pragma unroll
                for (int j = 0; j < 4; j++)
                    Sv[i][j] = fmaf(rq[i], rk[j], Sv[i][j]);
        }

        // online softmax per row (reduce across the 16 tx lanes, halfwarp)
#pragma unroll
        for (int i = 0; i < 8; i++) {
            float mx = fmaxf(fmaxf(Sv[i][0], Sv[i][1]), fmaxf(Sv[i][2], Sv[i][3]));
#pragma unroll
            for (int off = 8; off > 0; off >>= 1)
                mx = fmaxf(mx, __shfl_xor_sync(0xffffffffu, mx, off));
            float mnew = fmaxf(m[i], mx);
            float alpha = __expf(m[i] - mnew);
            m[i] = mnew;
            float rs = 0.f;
#pragma unroll
            for (int j = 0; j < 4; j++) {
                Sv[i][j] = __expf(Sv[i][j] - mnew);
                rs += Sv[i][j];
            }
#pragma unroll
            for (int off = 8; off > 0; off >>= 1)
                rs += __shfl_xor_sync(0xffffffffu, rs, off);
            l[i] = l[i] * alpha + rs;
#pragma unroll
            for (int j = 0; j < 4; j++) o[i][j] *= alpha;
        }
        __syncthreads();   // all S reads of KP done before P overwrites it

        // write P transposed: Pt[c][r], stride 129
#pragma unroll
        for (int j = 0; j < 4; j++)
#pragma unroll
            for (int i = 0; i < 8; i++)
                KP[(tx * 4 + j) * 129 + ty * 8 + i] = Sv[i][j];
        __syncthreads();

        // O += P @ V
#pragma unroll 4
        for (int c = 0; c < 64; c++) {
            float rp[8], rv[4];
            const float* prow = KP + c * 129 + ty * 8;
            const float* vrow = Vs + c * 64 + tx * 4;
#pragma unroll
            for (int i = 0; i < 8; i++) rp[i] = prow[i];
#pragma unroll
            for (int j = 0; j < 4; j++) rv[j] = vrow[j];
#pragma unroll
            for (int i = 0; i < 8; i++)
#pragma unroll
                for (int j = 0; j < 4; j++)
                    o[i][j] = fmaf(rp[i], rv[j], o[i][j]);
        }
        __syncthreads();   // protect KP/Vs before next block's loads
    }

    // normalize and store
#pragma unroll
    for (int i = 0; i < 8; i++) {
        float inv = 1.f / l[i];
        float4 v;
        v.x = o[i][0] * inv; v.y = o[i][1] * inv;
        v.z = o[i][2] * inv; v.w = o[i][3] * inv;
        *(float4*)(O + base + (size_t)(q0 + ty * 8 + i) * DD + tx * 4) = v;
    }
}

// ------------------------- LayerNorm --------------------------------------
__global__ __launch_bounds__(256) void ln_kernel(
    const float* __restrict__ X, const float* __restrict__ gamma,
    const float* __restrict__ beta, float* __restrict__ out)
{
    __shared__ float ssum[8], ssq[8];
    const int row = blockIdx.x;
    const int tid = threadIdx.x;
    const float* x = X + (size_t)row * DD;

    float4 v = *(const float4*)(x + tid * 4);
    float s = v.x + v.y + v.z + v.w;
    float q = v.x * v.x + v.y * v.y + v.z * v.z + v.w * v.w;
#pragma unroll
    for (int off = 16; off > 0; off >>= 1) {
        s += __shfl_xor_sync(0xffffffffu, s, off);
        q += __shfl_xor_sync(0xffffffffu, q, off);
    }
    if ((tid & 31) == 0) { ssum[tid >> 5] = s; ssq[tid >> 5] = q; }
    __syncthreads();
    float ts = 0.f, tq = 0.f;
#pragma unroll
    for (int i = 0; i < 8; i++) { ts += ssum[i]; tq += ssq[i]; }

    const float mean = ts * (1.f / DD);
    const float var = tq * (1.f / DD) - mean * mean;
    const float inv = rsqrtf(var + 1e-5f);

    float4 g = *(const float4*)(gamma + tid * 4);
    float4 bt = *(const float4*)(beta + tid * 4);
    float4 o4;
    o4.x = (v.x - mean) * inv * g.x + bt.x;
    o4.y = (v.y - mean) * inv * g.y + bt.y;
    o4.z = (v.z - mean) * inv * g.z + bt.z;
    o4.w = (v.w - mean) * inv * g.w + bt.w;
    *(float4*)(out + (size_t)row * DD + tid * 4) = o4;
}

// ------------------------- launch -----------------------------------------
extern "C" void kernel_launch(void* const* d_in, const int* in_sizes, int n_in,
                              void* d_out, int out_size)
{
    const float* X     = (const float*)d_in[0];
    const float* Wq    = (const float*)d_in[1];
    const float* bq    = (const float*)d_in[2];
    const float* Wk    = (const float*)d_in[3];
    const float* bk    = (const float*)d_in[4];
    const float* Wv    = (const float*)d_in[5];
    const float* bv    = (const float*)d_in[6];
    const float* Wo    = (const float*)d_in[7];
    const float* bo    = (const float*)d_in[8];
    const float* gamma = (const float*)d_in[9];
    const float* beta  = (const float*)d_in[10];
    float* out = (float*)d_out;

    float *Qp, *Kp, *Vp, *Op, *Rp;
    cudaGetSymbolAddress((void**)&Qp, g_Q);
    cudaGetSymbolAddress((void**)&Kp, g_K);
    cudaGetSymbolAddress((void**)&Vp, g_V);
    cudaGetSymbolAddress((void**)&Op, g_O);
    cudaGetSymbolAddress((void**)&Rp, g_R);

    cudaFuncSetAttribute(attn_kernel,
                         cudaFuncAttributeMaxDynamicSharedMemorySize,
                         (int)ATTN_SMEM_BYTES);

    dim3 gemm_grid(DD / 128, MM / 128);   // (8, 64)

    sgemm_bias_kernel<<<gemm_grid, 256>>>(X, Wq, bq, nullptr, Qp, MM, DD, DD);
    sgemm_bias_kernel<<<gemm_grid, 256>>>(X, Wk, bk, nullptr, Kp, MM, DD, DD);
    sgemm_bias_kernel<<<gemm_grid, 256>>>(X, Wv, bv, nullptr, Vp, MM, DD, DD);

    attn_kernel<<<dim3(LL / AT_BQ, BB * HH), 256, ATTN_SMEM_BYTES>>>(Qp, Kp, Vp, Op);

    sgemm_bias_kernel<<<gemm_grid, 256>>>(Op, Wo, bo, X, Rp, MM, DD, DD);

    ln_kernel<<<MM, 256>>>(Rp, gamma, beta, out);
}

// round 4
// speedup vs baseline: 2.3054x; 2.3054x over previous
#include <cuda_runtime.h>
#include <math.h>
#include <stdint.h>

// Problem dims
#define BB 4
#define LL 2048
#define DD 1024
#define HH 16
#define HD 64
#define MM (BB * LL)   // 8192

// ------------------------- scratch (static device globals) -------------------
__device__ float g_Q[MM * DD];
__device__ float g_K[MM * DD];
__device__ float g_V[MM * DD];
__device__ float g_O[MM * DD];
__device__ float g_R[MM * DD];

// ========================= helpers ==========================================
__device__ __forceinline__ uint32_t smem_u32(const void* p) {
    uint32_t a;
    asm("{ .reg .u64 t; cvta.to.shared.u64 t, %1; cvt.u32.u64 %0, t; }"
        : "=r"(a) : "l"(p));
    return a;
}

#define CP_ASYNC16(dst, src) \
    asm volatile("cp.async.ca.shared.global [%0], [%1], 16;" :: "r"(dst), "l"(src))
#define CP_COMMIT() asm volatile("cp.async.commit_group;")
#define CP_WAIT0()  asm volatile("cp.async.wait_group 0;")

// m16n8k8 tf32 mma: A row-major (m x k), B col-major (k x n), fp32 accum.
__device__ __forceinline__ void mma_tf32(float* c, const uint32_t* a, const uint32_t* b) {
    asm volatile(
        "mma.sync.aligned.m16n8k8.row.col.f32.tf32.tf32.f32 "
        "{%0,%1,%2,%3}, {%4,%5,%6,%7}, {%8,%9}, {%0,%1,%2,%3};"
        : "+f"(c[0]), "+f"(c[1]), "+f"(c[2]), "+f"(c[3])
        : "r"(a[0]), "r"(a[1]), "r"(a[2]), "r"(a[3]), "r"(b[0]), "r"(b[1]));
}

// ========================= tf32 mma GEMM ====================================
// C[M,N] = A[M,K] @ Bw[K,N] + bias (+ R). CTA 128x128, BK=32, 8 warps (64x32).
#define GSTR 36                     // padded float stride
#define GBUF (128 * GSTR)           // floats per (A|B) half: 4608
#define GEMM_SMEM (2 * 2 * GBUF * 4)  // 73728 bytes

__global__ __launch_bounds__(256, 2)
void gemm_mma(const float* __restrict__ A, const float* __restrict__ Bw,
              const float* __restrict__ bias, const float* __restrict__ R,
              float* __restrict__ C)
{
    extern __shared__ float sm[];
    const int tid = threadIdx.x;
    const int wid = tid >> 5, lane = tid & 31;
    const int g = lane >> 2, tig = lane & 3;
    const int wm = wid >> 2, wn = wid & 3;
    const int bx = blockIdx.x, by = blockIdx.y;
    const uint32_t sbase = smem_u32(sm);

    float* Abuf[2] = { sm,             sm + 2 * GBUF };
    float* Bbuf[2] = { sm + GBUF,      sm + 3 * GBUF };
    const uint32_t Aaddr[2] = { sbase, sbase + 2 * GBUF * 4 };

    // A tile cp.async mapping: 1024 float4s, 4 per thread
    // B tile mapping: n = tid&127, k-half = tid>>7
    const int bn = tid & 127;
    const int bk0 = (tid >> 7) * 16;

    // ---- prefetch tile 0 ----
    {
#pragma unroll
        for (int i = 0; i < 4; i++) {
            int f = tid + i * 256;
            int row = f >> 3, c4 = (f & 7) * 4;
            CP_ASYNC16(Aaddr[0] + (uint32_t)(row * GSTR + c4) * 4,
                       A + (size_t)(by * 128 + row) * DD + c4);
        }
        CP_COMMIT();
        float bst[16];
#pragma unroll
        for (int k = 0; k < 16; k++)
            bst[k] = Bw[(size_t)(bk0 + k) * DD + bx * 128 + bn];
        float* Bs = Bbuf[0] + bn * GSTR + bk0;
#pragma unroll
        for (int i = 0; i < 4; i++)
            *(float4*)(Bs + i * 4) = make_float4(bst[i*4], bst[i*4+1], bst[i*4+2], bst[i*4+3]);
        CP_WAIT0();
        __syncthreads();
    }

    float acc[4][4][4];
#pragma unroll
    for (int mt = 0; mt < 4; mt++)
#pragma unroll
        for (int nt = 0; nt < 4; nt++)
#pragma unroll
            for (int j = 0; j < 4; j++) acc[mt][nt][j] = 0.f;

    const int NKT = DD / 32;
    float bst[16];

    for (int kb = 0; kb < NKT; kb++) {
        const int buf = kb & 1;
        if (kb + 1 < NKT) {
            const int nb = buf ^ 1;
#pragma unroll
            for (int i = 0; i < 4; i++) {
                int f = tid + i * 256;
                int row = f >> 3, c4 = (f & 7) * 4;
                CP_ASYNC16(Aaddr[nb] + (uint32_t)(row * GSTR + c4) * 4,
                           A + (size_t)(by * 128 + row) * DD + (kb + 1) * 32 + c4);
            }
            CP_COMMIT();
#pragma unroll
            for (int k = 0; k < 16; k++)
                bst[k] = Bw[(size_t)((kb + 1) * 32 + bk0 + k) * DD + bx * 128 + bn];
        }

        // ---- compute current buffer ----
        const float* As = Abuf[buf];
        const float* Bs = Bbuf[buf];
#pragma unroll
        for (int ks = 0; ks < 4; ks++) {
            const int k = ks * 8;
            uint32_t af[4][4], bf[4][2];
#pragma unroll
            for (int mt = 0; mt < 4; mt++) {
                const int m0 = wm * 64 + mt * 16;
                af[mt][0] = __float_as_uint(As[(m0 + g    ) * GSTR + k + tig]);
                af[mt][1] = __float_as_uint(As[(m0 + g + 8) * GSTR + k + tig]);
                af[mt][2] = __float_as_uint(As[(m0 + g    ) * GSTR + k + tig + 4]);
                af[mt][3] = __float_as_uint(As[(m0 + g + 8) * GSTR + k + tig + 4]);
            }
#pragma unroll
            for (int nt = 0; nt < 4; nt++) {
                const int n0 = wn * 32 + nt * 8;
                bf[nt][0] = __float_as_uint(Bs[(n0 + g) * GSTR + k + tig]);
                bf[nt][1] = __float_as_uint(Bs[(n0 + g) * GSTR + k + tig + 4]);
            }
#pragma unroll
            for (int mt = 0; mt < 4; mt++)
#pragma unroll
                for (int nt = 0; nt < 4; nt++)
                    mma_tf32(acc[mt][nt], af[mt], bf[nt]);
        }

        if (kb + 1 < NKT) {
            float* Bd = Bbuf[buf ^ 1] + bn * GSTR + bk0;
#pragma unroll
            for (int i = 0; i < 4; i++)
                *(float4*)(Bd + i * 4) = make_float4(bst[i*4], bst[i*4+1], bst[i*4+2], bst[i*4+3]);
            CP_WAIT0();
        }
        __syncthreads();
    }

    // ---- epilogue ----
#pragma unroll
    for (int nt = 0; nt < 4; nt++) {
        const int col = bx * 128 + wn * 32 + nt * 8 + 2 * tig;
        const float b0 = bias[col], b1 = bias[col + 1];
#pragma unroll
        for (int mt = 0; mt < 4; mt++) {
            const int row = by * 128 + wm * 64 + mt * 16 + g;
            float2 v0 = make_float2(acc[mt][nt][0] + b0, acc[mt][nt][1] + b1);
            float2 v1 = make_float2(acc[mt][nt][2] + b0, acc[mt][nt][3] + b1);
            const size_t o0 = (size_t)row * DD + col;
            const size_t o1 = (size_t)(row + 8) * DD + col;
            if (R) {
                float2 r0 = *(const float2*)(R + o0);
                float2 r1 = *(const float2*)(R + o1);
                v0.x += r0.x; v0.y += r0.y; v1.x += r1.x; v1.y += r1.y;
            }
            *(float2*)(C + o0) = v0;
            *(float2*)(C + o1) = v1;
        }
    }
}

// ========================= tf32 mma flash attention ==========================
// Per CTA: 128 queries of one (b,h); 64-key blocks, online softmax.
// 8 warps, each owns 16 query rows.
#define ASTR 68
#define SQ_OFF 0                         // Qs: 128*68
#define SK_OFF (128 * ASTR)              // Ks: 64*68
#define SV_OFF (SK_OFF + 64 * ASTR)      // Vs: 64*68
#define SP_OFF (SV_OFF + 64 * ASTR)      // Ps: 128*68
#define ATT_SMEM ((SP_OFF + 128 * ASTR) * 4)   // 104448 bytes

__global__ __launch_bounds__(256, 2)
void attn_mma(const float* __restrict__ Q, const float* __restrict__ K,
              const float* __restrict__ V, float* __restrict__ O)
{
    extern __shared__ float sm[];
    float* Qs = sm + SQ_OFF;
    float* Ks = sm + SK_OFF;
    float* Vs = sm + SV_OFF;
    float* Ps = sm + SP_OFF;

    const int tid = threadIdx.x;
    const int wid = tid >> 5, lane = tid & 31;
    const int g = lane >> 2, tig = lane & 3;
    const int m0 = wid * 16;

    const int bh = blockIdx.y;
    const int b = bh >> 4, h = bh & 15;
    const int q0 = blockIdx.x * 128;
    const size_t base = (size_t)b * LL * DD + (size_t)h * HD;

    // load Q tile (scaled by 1/sqrt(64))
    {
        const int row = tid >> 1;
        const int d0 = (tid & 1) * 32;
        const float* src = Q + base + (size_t)(q0 + row) * DD + d0;
        float* dst = Qs + row * ASTR + d0;
#pragma unroll
        for (int i = 0; i < 8; i++) {
            float4 v = *(const float4*)(src + i * 4);
            v.x *= 0.125f; v.y *= 0.125f; v.z *= 0.125f; v.w *= 0.125f;
            *(float4*)(dst + i * 4) = v;
        }
    }

    float oacc[8][4];
    float mrow[2] = { -1e30f, -1e30f };
    float lrow[2] = { 0.f, 0.f };
#pragma unroll
    for (int nt = 0; nt < 8; nt++)
#pragma unroll
        for (int j = 0; j < 4; j++) oacc[nt][j] = 0.f;

    for (int c0 = 0; c0 < LL; c0 += 64) {
        // load K, V tiles (64 x 64)
        {
            const int row = tid >> 2;
            const int d0 = (tid & 3) * 16;
            const size_t go = base + (size_t)(c0 + row) * DD + d0;
#pragma unroll
            for (int i = 0; i < 4; i++) {
                *(float4*)(Ks + row * ASTR + d0 + i * 4) = *(const float4*)(K + go + i * 4);
                *(float4*)(Vs + row * ASTR + d0 + i * 4) = *(const float4*)(V + go + i * 4);
            }
        }
        __syncthreads();

        // ---- S = Q @ K^T ----
        float sacc[8][4];
#pragma unroll
        for (int nt = 0; nt < 8; nt++)
#pragma unroll
            for (int j = 0; j < 4; j++) sacc[nt][j] = 0.f;

#pragma unroll
        for (int ks = 0; ks < 8; ks++) {
            const int k = ks * 8;
            uint32_t aq[4];
            aq[0] = __float_as_uint(Qs[(m0 + g    ) * ASTR + k + tig]);
            aq[1] = __float_as_uint(Qs[(m0 + g + 8) * ASTR + k + tig]);
            aq[2] = __float_as_uint(Qs[(m0 + g    ) * ASTR + k + tig + 4]);
            aq[3] = __float_as_uint(Qs[(m0 + g + 8) * ASTR + k + tig + 4]);
#pragma unroll
            for (int nt = 0; nt < 8; nt++) {
                uint32_t bk[2];
                bk[0] = __float_as_uint(Ks[(nt * 8 + g) * ASTR + k + tig]);
                bk[1] = __float_as_uint(Ks[(nt * 8 + g) * ASTR + k + tig + 4]);
                mma_tf32(sacc[nt], aq, bk);
            }
        }

        // ---- online softmax (rows g and g+8; 4 lanes per row share cols) ----
#pragma unroll
        for (int r = 0; r < 2; r++) {
            const int j0 = r * 2;
            float mx = -1e30f;
#pragma unroll
            for (int nt = 0; nt < 8; nt++)
                mx = fmaxf(mx, fmaxf(sacc[nt][j0], sacc[nt][j0 + 1]));
            mx = fmaxf(mx, __shfl_xor_sync(0xffffffffu, mx, 1));
            mx = fmaxf(mx, __shfl_xor_sync(0xffffffffu, mx, 2));
            const float mnew = fmaxf(mrow[r], mx);
            const float alpha = __expf(mrow[r] - mnew);
            mrow[r] = mnew;
            float rs = 0.f;
#pragma unroll
            for (int nt = 0; nt < 8; nt++) {
                sacc[nt][j0]     = __expf(sacc[nt][j0]     - mnew);
                sacc[nt][j0 + 1] = __expf(sacc[nt][j0 + 1] - mnew);
                rs += sacc[nt][j0] + sacc[nt][j0 + 1];
            }
            rs += __shfl_xor_sync(0xffffffffu, rs, 1);
            rs += __shfl_xor_sync(0xffffffffu, rs, 2);
            lrow[r] = lrow[r] * alpha + rs;
#pragma unroll
            for (int nt = 0; nt < 8; nt++) {
                oacc[nt][j0]     *= alpha;
                oacc[nt][j0 + 1] *= alpha;
            }
        }

        // ---- P -> smem (C-frag layout to A-frag layout round trip) ----
#pragma unroll
        for (int nt = 0; nt < 8; nt++) {
            const int col = nt * 8 + 2 * tig;
            *(float2*)(Ps + (m0 + g    ) * ASTR + col) = make_float2(sacc[nt][0], sacc[nt][1]);
            *(float2*)(Ps + (m0 + g + 8) * ASTR + col) = make_float2(sacc[nt][2], sacc[nt][3]);
        }
        __syncthreads();

        // ---- O += P @ V ----
#pragma unroll
        for (int ks = 0; ks < 8; ks++) {
            const int k = ks * 8;
            uint32_t ap[4];
            ap[0] = __float_as_uint(Ps[(m0 + g    ) * ASTR + k + tig]);
            ap[1] = __float_as_uint(Ps[(m0 + g + 8) * ASTR + k + tig]);
            ap[2] = __float_as_uint(Ps[(m0 + g    ) * ASTR + k + tig + 4]);
            ap[3] = __float_as_uint(Ps[(m0 + g + 8) * ASTR + k + tig + 4]);
#pragma unroll
            for (int nt = 0; nt < 8; nt++) {
                uint32_t bv[2];
                bv[0] = __float_as_uint(Vs[(k + tig    ) * ASTR + nt * 8 + g]);
                bv[1] = __float_as_uint(Vs[(k + tig + 4) * ASTR + nt * 8 + g]);
                mma_tf32(oacc[nt], ap, bv);
            }
        }
        __syncthreads();
    }

    // ---- normalize + store ----
    const float inv0 = 1.f / lrow[0];
    const float inv1 = 1.f / lrow[1];
#pragma unroll
    for (int nt = 0; nt < 8; nt++) {
        const int col = nt * 8 + 2 * tig;
        const size_t o0 = base + (size_t)(q0 + m0 + g    ) * DD + col;
        const size_t o1 = base + (size_t)(q0 + m0 + g + 8) * DD + col;
        *(float2*)(O + o0) = make_float2(oacc[nt][0] * inv0, oacc[nt][1] * inv0);
        *(float2*)(O + o1) = make_float2(oacc[nt][2] * inv1, oacc[nt][3] * inv1);
    }
}

// ------------------------- LayerNorm -----------------------------------------
__global__ __launch_bounds__(256) void ln_kernel(
    const float* __restrict__ X, const float* __restrict__ gamma,
    const float* __restrict__ beta, float* __restrict__ out)
{
    __shared__ float ssum[8], ssq[8];
    const int row = blockIdx.x;
    const int tid = threadIdx.x;
    const float* x = X + (size_t)row * DD;

    float4 v = *(const float4*)(x + tid * 4);
    float s = v.x + v.y + v.z + v.w;
    float q = v.x * v.x + v.y * v.y + v.z * v.z + v.w * v.w;
#pragma unroll
    for (int off = 16; off > 0; off >>= 1) {
        s += __shfl_xor_sync(0xffffffffu, s, off);
        q += __shfl_xor_sync(0xffffffffu, q, off);
    }
    if ((tid & 31) == 0) { ssum[tid >> 5] = s; ssq[tid >> 5] = q; }
    __syncthreads();
    float ts = 0.f, tq = 0.f;
#pragma unroll
    for (int i = 0; i < 8; i++) { ts += ssum[i]; tq += ssq[i]; }

    const float mean = ts * (1.f / DD);
    const float var = tq * (1.f / DD) - mean * mean;
    const float inv = rsqrtf(var + 1e-5f);

    float4 gmv = *(const float4*)(gamma + tid * 4);
    float4 btv = *(const float4*)(beta + tid * 4);
    float4 o4;
    o4.x = (v.x - mean) * inv * gmv.x + btv.x;
    o4.y = (v.y - mean) * inv * gmv.y + btv.y;
    o4.z = (v.z - mean) * inv * gmv.z + btv.z;
    o4.w = (v.w - mean) * inv * gmv.w + btv.w;
    *(float4*)(out + (size_t)row * DD + tid * 4) = o4;
}

// ------------------------- launch --------------------------------------------
extern "C" void kernel_launch(void* const* d_in, const int* in_sizes, int n_in,
                              void* d_out, int out_size)
{
    const float* X     = (const float*)d_in[0];
    const float* Wq    = (const float*)d_in[1];
    const float* bq    = (const float*)d_in[2];
    const float* Wk    = (const float*)d_in[3];
    const float* bk    = (const float*)d_in[4];
    const float* Wv    = (const float*)d_in[5];
    const float* bv    = (const float*)d_in[6];
    const float* Wo    = (const float*)d_in[7];
    const float* bo    = (const float*)d_in[8];
    const float* gamma = (const float*)d_in[9];
    const float* beta  = (const float*)d_in[10];
    float* out = (float*)d_out;

    float *Qp, *Kp, *Vp, *Op, *Rp;
    cudaGetSymbolAddress((void**)&Qp, g_Q);
    cudaGetSymbolAddress((void**)&Kp, g_K);
    cudaGetSymbolAddress((void**)&Vp, g_V);
    cudaGetSymbolAddress((void**)&Op, g_O);
    cudaGetSymbolAddress((void**)&Rp, g_R);

    cudaFuncSetAttribute(gemm_mma,
                         cudaFuncAttributeMaxDynamicSharedMemorySize, GEMM_SMEM);
    cudaFuncSetAttribute(attn_mma,
                         cudaFuncAttributeMaxDynamicSharedMemorySize, ATT_SMEM);

    dim3 gemm_grid(DD / 128, MM / 128);   // (8, 64)

    gemm_mma<<<gemm_grid, 256, GEMM_SMEM>>>(X, Wq, bq, nullptr, Qp);
    gemm_mma<<<gemm_grid, 256, GEMM_SMEM>>>(X, Wk, bk, nullptr, Kp);
    gemm_mma<<<gemm_grid, 256, GEMM_SMEM>>>(X, Wv, bv, nullptr, Vp);

    attn_mma<<<dim3(LL / 128, BB * HH), 256, ATT_SMEM>>>(Qp, Kp, Vp, Op);

    gemm_mma<<<gemm_grid, 256, GEMM_SMEM>>>(Op, Wo, bo, X, Rp);

    ln_kernel<<<MM, 256>>>(Rp, gamma, beta, out);
}

// round 6
// speedup vs baseline: 3.4301x; 1.4879x over previous
#include <cuda_runtime.h>
#include <cuda_bf16.h>
#include <math.h>
#include <stdint.h>

// Problem dims
#define BB 4
#define LL 2048
#define DD 1024
#define HH 16
#define HD 64
#define MM (BB * LL)   // 8192

// ------------------------- scratch (static device globals) -------------------
__device__ __nv_bfloat16 g_Xb[MM * DD];   // bf16 copy of input
__device__ __nv_bfloat16 g_Qb[MM * DD];
__device__ __nv_bfloat16 g_Kb[MM * DD];
__device__ __nv_bfloat16 g_Vb[MM * DD];
__device__ __nv_bfloat16 g_Ob[MM * DD];
__device__ float g_R[MM * DD];

// ========================= helpers ==========================================
__device__ __forceinline__ uint32_t smem_u32(const void* p) {
    uint32_t a;
    asm("{ .reg .u64 t; cvta.to.shared.u64 t, %1; cvt.u32.u64 %0, t; }"
        : "=r"(a) : "l"(p));
    return a;
}
#define CP_ASYNC16(dst, src) \
    asm volatile("cp.async.ca.shared.global [%0], [%1], 16;" :: "r"(dst), "l"(src))
#define CP_COMMIT() asm volatile("cp.async.commit_group;")
#define CP_WAIT0()  asm volatile("cp.async.wait_group 0;")

// pack two f32 -> bf16x2 (lo = first arg)
__device__ __forceinline__ uint32_t pack_bf16(float lo, float hi) {
    uint32_t r;
    asm("cvt.rn.bf16x2.f32 %0, %1, %2;" : "=r"(r) : "f"(hi), "f"(lo));
    return r;
}

// m16n8k16 bf16 mma, fp32 accum. A row-major, B col-major.
__device__ __forceinline__ void mma_bf16(float* c, const uint32_t* a, const uint32_t* b) {
    asm volatile(
        "mma.sync.aligned.m16n8k16.row.col.f32.bf16.bf16.f32 "
        "{%0,%1,%2,%3}, {%4,%5,%6,%7}, {%8,%9}, {%0,%1,%2,%3};"
        : "+f"(c[0]), "+f"(c[1]), "+f"(c[2]), "+f"(c[3])
        : "r"(a[0]), "r"(a[1]), "r"(a[2]), "r"(a[3]), "r"(b[0]), "r"(b[1]));
}

// ========================= fp32 -> bf16 convert =============================
__global__ __launch_bounds__(256) void cvt_kernel(const float* __restrict__ X,
                                                  __nv_bfloat16* __restrict__ Y)
{
    const int i = blockIdx.x * 256 + threadIdx.x;     // over float4s
    float4 v = ((const float4*)X)[i];
    uint2 o;
    o.x = pack_bf16(v.x, v.y);
    o.y = pack_bf16(v.z, v.w);
    ((uint2*)Y)[i] = o;
}

// ========================= bf16 mma GEMM ====================================
// C[M,N] = A[M,K]_bf16 @ Bw[K,N]_f32 + bias (+ R). CTA 128x128, BK=32, 8 warps.
// A smem: [128][32] bf16, padded row stride 40 bf16 (20 words).
// B smem: W transposed [n=128][k=32] bf16, stride 40.
#define GW 20                       // word stride
#define GBUFW (128 * GW)            // words per buffer: 2560

template <bool OUT_BF16>
__global__ __launch_bounds__(256, 2)
void gemm_bf16(const __nv_bfloat16* __restrict__ A, const float* __restrict__ Bw,
               const float* __restrict__ bias, const float* __restrict__ R,
               void* __restrict__ Cout)
{
    __shared__ uint32_t sm[4 * GBUFW];        // A0,B0,A1,B1 : 40960 bytes
    const uint32_t sbase = smem_u32(sm);

    const int tid = threadIdx.x;
    const int wid = tid >> 5, lane = tid & 31;
    const int g = lane >> 2, t = lane & 3;
    const int wm = wid >> 2, wn = wid & 3;
    const int bx = blockIdx.x, by = blockIdx.y;

    const uint32_t* Abuf[2] = { sm,             sm + 2 * GBUFW };
    const uint32_t* Bbuf[2] = { sm + GBUFW,     sm + 3 * GBUFW };
    uint32_t* Bst[2] = { sm + GBUFW, sm + 3 * GBUFW };
    const uint32_t Aaddr[2] = { sbase, sbase + 2 * GBUFW * 4 };

    // A cp.async mapping: 512 16B-chunks, 2 per thread
    const int arow = (tid + 0) >> 2 >> 0;  // see below
    // chunk c = tid + i*256 ; row = c>>2, ch = c&3
    // B gather: n = tid&127, khalf = tid>>7
    const int bn = tid & 127;
    const int bk0 = (tid >> 7) * 16;
    (void)arow;

    const __nv_bfloat16* Ab = A + (size_t)(by * 128) * DD;

    // ---- prefetch kb=0 ----
    {
#pragma unroll
        for (int i = 0; i < 2; i++) {
            int c = tid + i * 256;
            int row = c >> 2, ch = c & 3;
            CP_ASYNC16(Aaddr[0] + (uint32_t)(row * 80 + ch * 16),
                       Ab + (size_t)row * DD + ch * 8);
        }
        CP_COMMIT();
        float bv[16];
#pragma unroll
        for (int k = 0; k < 16; k++)
            bv[k] = Bw[(size_t)(bk0 + k) * DD + bx * 128 + bn];
        uint32_t* d = Bst[0] + bn * GW + bk0 / 2;
        uint4 p0, p1;
        p0.x = pack_bf16(bv[0], bv[1]);  p0.y = pack_bf16(bv[2], bv[3]);
        p0.z = pack_bf16(bv[4], bv[5]);  p0.w = pack_bf16(bv[6], bv[7]);
        p1.x = pack_bf16(bv[8], bv[9]);  p1.y = pack_bf16(bv[10], bv[11]);
        p1.z = pack_bf16(bv[12], bv[13]); p1.w = pack_bf16(bv[14], bv[15]);
        *(uint4*)(d) = p0;
        *(uint4*)(d + 4) = p1;
        CP_WAIT0();
        __syncthreads();
    }

    float acc[4][4][4];
#pragma unroll
    for (int mt = 0; mt < 4; mt++)
#pragma unroll
        for (int nt = 0; nt < 4; nt++)
#pragma unroll
            for (int j = 0; j < 4; j++) acc[mt][nt][j] = 0.f;

    const int NKT = DD / 32;
    float bv[16];

    for (int kb = 0; kb < NKT; kb++) {
        const int buf = kb & 1;
        if (kb + 1 < NKT) {
            const int nb = buf ^ 1;
#pragma unroll
            for (int i = 0; i < 2; i++) {
                int c = tid + i * 256;
                int row = c >> 2, ch = c & 3;
                CP_ASYNC16(Aaddr[nb] + (uint32_t)(row * 80 + ch * 16),
                           Ab + (size_t)row * DD + (kb + 1) * 32 + ch * 8);
            }
            CP_COMMIT();
#pragma unroll
            for (int k = 0; k < 16; k++)
                bv[k] = Bw[(size_t)((kb + 1) * 32 + bk0 + k) * DD + bx * 128 + bn];
        }

        const uint32_t* As = Abuf[buf];
        const uint32_t* Bs = Bbuf[buf];
#pragma unroll
        for (int ks = 0; ks < 2; ks++) {
            const int kw = ks * 8;          // word offset in row
            uint32_t af[4][4], bf[4][2];
#pragma unroll
            for (int mt = 0; mt < 4; mt++) {
                const int r0 = wm * 64 + mt * 16;
                af[mt][0] = As[(r0 + g    ) * GW + kw + t];
                af[mt][1] = As[(r0 + g + 8) * GW + kw + t];
                af[mt][2] = As[(r0 + g    ) * GW + kw + t + 4];
                af[mt][3] = As[(r0 + g + 8) * GW + kw + t + 4];
            }
#pragma unroll
            for (int nt = 0; nt < 4; nt++) {
                const int n0 = wn * 32 + nt * 8;
                bf[nt][0] = Bs[(n0 + g) * GW + kw + t];
                bf[nt][1] = Bs[(n0 + g) * GW + kw + t + 4];
            }
#pragma unroll
            for (int mt = 0; mt < 4; mt++)
#pragma unroll
                for (int nt = 0; nt < 4; nt++)
                    mma_bf16(acc[mt][nt], af[mt], bf[nt]);
        }

        if (kb + 1 < NKT) {
            uint32_t* d = Bst[buf ^ 1] + bn * GW + bk0 / 2;
            uint4 p0, p1;
            p0.x = pack_bf16(bv[0], bv[1]);  p0.y = pack_bf16(bv[2], bv[3]);
            p0.z = pack_bf16(bv[4], bv[5]);  p0.w = pack_bf16(bv[6], bv[7]);
            p1.x = pack_bf16(bv[8], bv[9]);  p1.y = pack_bf16(bv[10], bv[11]);
            p1.z = pack_bf16(bv[12], bv[13]); p1.w = pack_bf16(bv[14], bv[15]);
            *(uint4*)(d) = p0;
            *(uint4*)(d + 4) = p1;
            CP_WAIT0();
        }
        __syncthreads();
    }

    // ---- epilogue ----
#pragma unroll
    for (int nt = 0; nt < 4; nt++) {
        const int col = bx * 128 + wn * 32 + nt * 8 + 2 * t;
        const float b0 = bias[col], b1 = bias[col + 1];
#pragma unroll
        for (int mt = 0; mt < 4; mt++) {
            const int row = by * 128 + wm * 64 + mt * 16 + g;
            const size_t o0 = (size_t)row * DD + col;
            const size_t o1 = (size_t)(row + 8) * DD + col;
            float v00 = acc[mt][nt][0] + b0, v01 = acc[mt][nt][1] + b1;
            float v10 = acc[mt][nt][2] + b0, v11 = acc[mt][nt][3] + b1;
            if (OUT_BF16) {
                ((uint32_t*)Cout)[o0 / 2 * 0 + 0] = 0;  // placeholder avoided below
            }
            if (OUT_BF16) {
                *(uint32_t*)((__nv_bfloat16*)Cout + o0) = pack_bf16(v00, v01);
                *(uint32_t*)((__nv_bfloat16*)Cout + o1) = pack_bf16(v10, v11);
            } else {
                float* C = (float*)Cout;
                if (R) {
                    float2 r0 = *(const float2*)(R + o0);
                    float2 r1 = *(const float2*)(R + o1);
                    v00 += r0.x; v01 += r0.y; v10 += r1.x; v11 += r1.y;
                }
                *(float2*)(C + o0) = make_float2(v00, v01);
                *(float2*)(C + o1) = make_float2(v10, v11);
            }
        }
    }
}

// ========================= bf16 flash attention ==============================
// CTA: 128 queries of one (b,h); 64-key blocks; 8 warps x 16 rows.
// Qs [128][64] bf16 stride 72 ; Ks [64 keys][64 d] stride 72 ; Vt [64 d][64 keys] stride 72.
#define AW 36                                   // word stride (72 bf16)
#define QS_W 0
#define KS_W (128 * AW)                         // 4608
#define VT_W (KS_W + 64 * AW)                   // 6912
#define ATT_W (VT_W + 64 * AW)                  // 9216 words = 36864 B

__global__ __launch_bounds__(256, 2)
void attn_bf16(const __nv_bfloat16* __restrict__ Q, const __nv_bfloat16* __restrict__ K,
               const __nv_bfloat16* __restrict__ V, __nv_bfloat16* __restrict__ O)
{
    __shared__ uint32_t sm[ATT_W];
    const uint32_t sbase = smem_u32(sm);
    const uint32_t* Q32 = sm + QS_W;
    const uint32_t* K32 = sm + KS_W;
    const uint32_t* V32 = sm + VT_W;
    unsigned short* Vt16 = (unsigned short*)(sm + VT_W);

    const int tid = threadIdx.x;
    const int wid = tid >> 5, lane = tid & 31;
    const int g = lane >> 2, t = lane & 3;
    const int m0 = wid * 16;

    const int bh = blockIdx.y;
    const int b = bh >> 4, h = bh & 15;
    const int q0 = blockIdx.x * 128;
    const size_t base = (size_t)b * LL * DD + (size_t)h * HD;

    // Q tile: 128 rows x 128B, cp.async
    {
#pragma unroll
        for (int i = 0; i < 4; i++) {
            int c = tid + i * 256;
            int row = c >> 3, ch = c & 7;
            CP_ASYNC16(sbase + QS_W * 4 + (uint32_t)(row * 144 + ch * 16),
                       Q + base + (size_t)(q0 + row) * DD + ch * 8);
        }
        CP_COMMIT();
    }

    float oacc[8][4];
    float mrow[2] = { -1e30f, -1e30f };
    float lrow[2] = { 0.f, 0.f };
#pragma unroll
    for (int nt = 0; nt < 8; nt++)
#pragma unroll
        for (int j = 0; j < 4; j++) oacc[nt][j] = 0.f;

    const int vkey = tid & 63;
    const int vw0 = (tid >> 6) * 8;

    for (int c0 = 0; c0 < LL; c0 += 64) {
        // K tile: 64 rows x 128B via cp.async
#pragma unroll
        for (int i = 0; i < 2; i++) {
            int c = tid + i * 256;
            int row = c >> 3, ch = c & 7;
            CP_ASYNC16(sbase + KS_W * 4 + (uint32_t)(row * 144 + ch * 16),
                       K + base + (size_t)(c0 + row) * DD + ch * 8);
        }
        CP_COMMIT();
        // V tile transposed: thread reads 8 uint32 (16 d) of one key row
        {
            const uint32_t* vg = (const uint32_t*)(V + base + (size_t)(c0 + vkey) * DD) + vw0;
            uint32_t vv[8];
#pragma unroll
            for (int j = 0; j < 8; j++) vv[j] = vg[j];
#pragma unroll
            for (int j = 0; j < 8; j++) {
                const int d2 = (vw0 + j) * 2;
                Vt16[(d2    ) * 72 + vkey] = (unsigned short)(vv[j] & 0xffffu);
                Vt16[(d2 + 1) * 72 + vkey] = (unsigned short)(vv[j] >> 16);
            }
        }
        CP_WAIT0();
        __syncthreads();

        // ---- S = Q @ K^T (raw, scale folded into exp) ----
        float sacc[8][4];
#pragma unroll
        for (int nt = 0; nt < 8; nt++)
#pragma unroll
            for (int j = 0; j < 4; j++) sacc[nt][j] = 0.f;

#pragma unroll
        for (int ks = 0; ks < 4; ks++) {
            const int kw = ks * 8;
            uint32_t aq[4];
            aq[0] = Q32[(m0 + g    ) * AW + kw + t];
            aq[1] = Q32[(m0 + g + 8) * AW + kw + t];
            aq[2] = Q32[(m0 + g    ) * AW + kw + t + 4];
            aq[3] = Q32[(m0 + g + 8) * AW + kw + t + 4];
#pragma unroll
            for (int nt = 0; nt < 8; nt++) {
                uint32_t bk[2];
                bk[0] = K32[(nt * 8 + g) * AW + kw + t];
                bk[1] = K32[(nt * 8 + g) * AW + kw + t + 4];
                mma_bf16(sacc[nt], aq, bk);
            }
        }

        // ---- online softmax, scale 0.125 folded into exp ----
#pragma unroll
        for (int r = 0; r < 2; r++) {
            const int j0 = r * 2;
            float mx = -1e30f;
#pragma unroll
            for (int nt = 0; nt < 8; nt++)
                mx = fmaxf(mx, fmaxf(sacc[nt][j0], sacc[nt][j0 + 1]));
            mx = fmaxf(mx, __shfl_xor_sync(0xffffffffu, mx, 1));
            mx = fmaxf(mx, __shfl_xor_sync(0xffffffffu, mx, 2));
            const float mnew = fmaxf(mrow[r], mx);
            const float alpha = __expf((mrow[r] - mnew) * 0.125f);
            mrow[r] = mnew;
            float rs = 0.f;
#pragma unroll
            for (int nt = 0; nt < 8; nt++) {
                sacc[nt][j0]     = __expf((sacc[nt][j0]     - mnew) * 0.125f);
                sacc[nt][j0 + 1] = __expf((sacc[nt][j0 + 1] - mnew) * 0.125f);
                rs += sacc[nt][j0] + sacc[nt][j0 + 1];
            }
            rs += __shfl_xor_sync(0xffffffffu, rs, 1);
            rs += __shfl_xor_sync(0xffffffffu, rs, 2);
            lrow[r] = lrow[r] * alpha + rs;
#pragma unroll
            for (int nt = 0; nt < 8; nt++) {
                oacc[nt][j0]     *= alpha;
                oacc[nt][j0 + 1] *= alpha;
            }
        }

        // ---- O += P @ V : P fragments come straight from sacc registers ----
#pragma unroll
        for (int j = 0; j < 4; j++) {          // key chunks of 16
            uint32_t ap[4];
            ap[0] = pack_bf16(sacc[2 * j][0],     sacc[2 * j][1]);
            ap[1] = pack_bf16(sacc[2 * j][2],     sacc[2 * j][3]);
            ap[2] = pack_bf16(sacc[2 * j + 1][0], sacc[2 * j + 1][1]);
            ap[3] = pack_bf16(sacc[2 * j + 1][2], sacc[2 * j + 1][3]);
#pragma unroll
            for (int nt = 0; nt < 8; nt++) {
                uint32_t bv[2];
                bv[0] = V32[(nt * 8 + g) * AW + j * 8 + t];
                bv[1] = V32[(nt * 8 + g) * AW + j * 8 + t + 4];
                mma_bf16(oacc[nt], ap, bv);
            }
        }
        __syncthreads();
    }

    // ---- normalize + store (bf16) ----
    const float inv0 = 1.f / lrow[0];
    const float inv1 = 1.f / lrow[1];
#pragma unroll
    for (int nt = 0; nt < 8; nt++) {
        const int col = nt * 8 + 2 * t;
        const size_t o0 = base + (size_t)(q0 + m0 + g    ) * DD + col;
        const size_t o1 = base + (size_t)(q0 + m0 + g + 8) * DD + col;
        *(uint32_t*)(O + o0) = pack_bf16(oacc[nt][0] * inv0, oacc[nt][1] * inv0);
        *(uint32_t*)(O + o1) = pack_bf16(oacc[nt][2] * inv1, oacc[nt][3] * inv1);
    }
}

// ------------------------- LayerNorm -----------------------------------------
__global__ __launch_bounds__(256) void ln_kernel(
    const float* __restrict__ X, const float* __restrict__ gamma,
    const float* __restrict__ beta, float* __restrict__ out)
{
    __shared__ float ssum[8], ssq[8];
    const int row = blockIdx.x;
    const int tid = threadIdx.x;
    const float* x = X + (size_t)row * DD;

    float4 v = *(const float4*)(x + tid * 4);
    float s = v.x + v.y + v.z + v.w;
    float q = v.x * v.x + v.y * v.y + v.z * v.z + v.w * v.w;
#pragma unroll
    for (int off = 16; off > 0; off >>= 1) {
        s += __shfl_xor_sync(0xffffffffu, s, off);
        q += __shfl_xor_sync(0xffffffffu, q, off);
    }
    if ((tid & 31) == 0) { ssum[tid >> 5] = s; ssq[tid >> 5] = q; }
    __syncthreads();
    float ts = 0.f, tq = 0.f;
#pragma unroll
    for (int i = 0; i < 8; i++) { ts += ssum[i]; tq += ssq[i]; }

    const float mean = ts * (1.f / DD);
    const float var = tq * (1.f / DD) - mean * mean;
    const float inv = rsqrtf(var + 1e-5f);

    float4 gmv = *(const float4*)(gamma + tid * 4);
    float4 btv = *(const float4*)(beta + tid * 4);
    float4 o4;
    o4.x = (v.x - mean) * inv * gmv.x + btv.x;
    o4.y = (v.y - mean) * inv * gmv.y + btv.y;
    o4.z = (v.z - mean) * inv * gmv.z + btv.z;
    o4.w = (v.w - mean) * inv * gmv.w + btv.w;
    *(float4*)(out + (size_t)row * DD + tid * 4) = o4;
}

// ------------------------- launch --------------------------------------------
extern "C" void kernel_launch(void* const* d_in, const int* in_sizes, int n_in,
                              void* d_out, int out_size)
{
    const float* X     = (const float*)d_in[0];
    const float* Wq    = (const float*)d_in[1];
    const float* bq    = (const float*)d_in[2];
    const float* Wk    = (const float*)d_in[3];
    const float* bk    = (const float*)d_in[4];
    const float* Wv    = (const float*)d_in[5];
    const float* bv    = (const float*)d_in[6];
    const float* Wo    = (const float*)d_in[7];
    const float* bo    = (const float*)d_in[8];
    const float* gamma = (const float*)d_in[9];
    const float* beta  = (const float*)d_in[10];
    float* out = (float*)d_out;

    __nv_bfloat16 *Xb, *Qb, *Kb, *Vb, *Ob;
    float* Rp;
    cudaGetSymbolAddress((void**)&Xb, g_Xb);
    cudaGetSymbolAddress((void**)&Qb, g_Qb);
    cudaGetSymbolAddress((void**)&Kb, g_Kb);
    cudaGetSymbolAddress((void**)&Vb, g_Vb);
    cudaGetSymbolAddress((void**)&Ob, g_Ob);
    cudaGetSymbolAddress((void**)&Rp, g_R);

    dim3 gemm_grid(DD / 128, MM / 128);   // (8, 64)

    cvt_kernel<<<MM * DD / 4 / 256, 256>>>(X, Xb);

    gemm_bf16<true><<<gemm_grid, 256>>>(Xb, Wq, bq, nullptr, Qb);
    gemm_bf16<true><<<gemm_grid, 256>>>(Xb, Wk, bk, nullptr, Kb);
    gemm_bf16<true><<<gemm_grid, 256>>>(Xb, Wv, bv, nullptr, Vb);

    attn_bf16<<<dim3(LL / 128, BB * HH), 256>>>(Qb, Kb, Vb, Ob);

    gemm_bf16<false><<<gemm_grid, 256>>>(Ob, Wo, bo, X, Rp);

    ln_kernel<<<MM, 256>>>(Rp, gamma, beta, out);
}

// round 8
// speedup vs baseline: 4.0649x; 1.1851x over previous
#include <cuda_runtime.h>
#include <cuda_bf16.h>
#include <math.h>
#include <stdint.h>

// Problem dims
#define BB 4
#define LL 2048
#define DD 1024
#define HH 16
#define HD 64
#define MM (BB * LL)   // 8192

// ------------------------- scratch (static device globals) -------------------
__device__ __nv_bfloat16 g_Xb[MM * DD];
__device__ __nv_bfloat16 g_Qb[MM * DD];
__device__ __nv_bfloat16 g_Kb[MM * DD];
__device__ __nv_bfloat16 g_Vb[MM * DD];
__device__ __nv_bfloat16 g_Ob[MM * DD];
__device__ __nv_bfloat16 g_Wqt[DD * DD];
__device__ __nv_bfloat16 g_Wkt[DD * DD];
__device__ __nv_bfloat16 g_Wvt[DD * DD];
__device__ __nv_bfloat16 g_Wot[DD * DD];
__device__ float g_R[MM * DD];

// ========================= helpers ==========================================
__device__ __forceinline__ uint32_t smem_u32(const void* p) {
    uint32_t a;
    asm("{ .reg .u64 t; cvta.to.shared.u64 t, %1; cvt.u32.u64 %0, t; }"
        : "=r"(a) : "l"(p));
    return a;
}
#define CP_ASYNC16(dst, src) \
    asm volatile("cp.async.ca.shared.global [%0], [%1], 16;" :: "r"(dst), "l"(src))
#define CP_COMMIT() asm volatile("cp.async.commit_group;")
#define CP_WAIT1()  asm volatile("cp.async.wait_group 1;")

__device__ __forceinline__ uint32_t pack_bf16(float lo, float hi) {
    uint32_t r;
    asm("cvt.rn.bf16x2.f32 %0, %1, %2;" : "=r"(r) : "f"(hi), "f"(lo));
    return r;
}
__device__ __forceinline__ void mma_bf16(float* c, const uint32_t* a, const uint32_t* b) {
    asm volatile(
        "mma.sync.aligned.m16n8k16.row.col.f32.bf16.bf16.f32 "
        "{%0,%1,%2,%3}, {%4,%5,%6,%7}, {%8,%9}, {%0,%1,%2,%3};"
        : "+f"(c[0]), "+f"(c[1]), "+f"(c[2]), "+f"(c[3])
        : "r"(a[0]), "r"(a[1]), "r"(a[2]), "r"(a[3]), "r"(b[0]), "r"(b[1]));
}

// ========================= fp32 -> bf16 convert =============================
__global__ __launch_bounds__(256) void cvt_kernel(const float* __restrict__ X,
                                                  __nv_bfloat16* __restrict__ Y)
{
    const int i = blockIdx.x * 256 + threadIdx.x;
    float4 v = ((const float4*)X)[i];
    uint2 o;
    o.x = pack_bf16(v.x, v.y);
    o.y = pack_bf16(v.z, v.w);
    ((uint2*)Y)[i] = o;
}

// ======== weight transpose+convert: W[K][N] f32 -> Wt[N][K] bf16 ============
__global__ __launch_bounds__(256) void wtrans_kernel(const float* __restrict__ W,
                                                     __nv_bfloat16* __restrict__ Wt)
{
    __shared__ float tile[32][33];
    const int n0 = blockIdx.x * 32, k0 = blockIdx.y * 32;
    const int tx = threadIdx.x, ty = threadIdx.y;   // 32 x 8
#pragma unroll
    for (int i = 0; i < 32; i += 8)
        tile[ty + i][tx] = W[(size_t)(k0 + ty + i) * DD + n0 + tx];
    __syncthreads();
#pragma unroll
    for (int i = 0; i < 32; i += 8)
        Wt[(size_t)(n0 + ty + i) * DD + k0 + tx] = __float2bfloat16(tile[tx][ty + i]);
}

// ========================= bf16 mma GEMM (3-stage cp.async) ==================
// C[M,N] = A[M,K]_bf16 @ Wt[N,K]_bf16^T + bias (+ R). CTA 128x128, BK=32, 8 warps.
// Fragment loads: R6-proven scalar LDS over padded rows (GW=20 words/row).
#define GW 20                          // words per smem row (32 bf16 + pad)
#define GTILEW (128 * GW)              // 2560 words per tile
#define GEMM_SMEM (3 * 2 * GTILEW * 4) // 61440 B

template <bool OUT_BF16>
__global__ __launch_bounds__(256)
void gemm_bf16(const __nv_bfloat16* __restrict__ A, const __nv_bfloat16* __restrict__ Bt,
               const float* __restrict__ bias, const float* __restrict__ R,
               void* __restrict__ Cout)
{
    extern __shared__ uint32_t sm[];
    const uint32_t sbase = smem_u32(sm);

    const int tid = threadIdx.x;
    const int wid = tid >> 5, lane = tid & 31;
    const int g = lane >> 2, t = lane & 3;
    const int wm = wid >> 2, wn = wid & 3;
    const int bx = blockIdx.x, by = blockIdx.y;

    const __nv_bfloat16* Ab = A  + (size_t)(by * 128) * DD;
    const __nv_bfloat16* Bb = Bt + (size_t)(bx * 128) * DD;

    const int L_row = tid >> 2;             // 0..63
    const int L_ch  = (tid & 3) * 16;       // byte offset in row
    const int L_el  = (tid & 3) * 8;        // element offset

#define GEMM_ISSUE(kb, st) do {                                                  \
    const uint32_t ao_ = sbase + (uint32_t)(st) * 2 * GTILEW * 4;                \
    const uint32_t bo_ = ao_ + GTILEW * 4;                                       \
    _Pragma("unroll")                                                            \
    for (int i_ = 0; i_ < 2; i_++) {                                             \
        const int row_ = L_row + i_ * 64;                                        \
        CP_ASYNC16(ao_ + (uint32_t)(row_ * 80) + L_ch,                           \
                   Ab + (size_t)row_ * DD + (kb) * 32 + L_el);                   \
        CP_ASYNC16(bo_ + (uint32_t)(row_ * 80) + L_ch,                           \
                   Bb + (size_t)row_ * DD + (kb) * 32 + L_el);                   \
    }                                                                            \
} while (0)

    GEMM_ISSUE(0, 0); CP_COMMIT();
    GEMM_ISSUE(1, 1); CP_COMMIT();

    float acc[4][4][4];
#pragma unroll
    for (int mt = 0; mt < 4; mt++)
#pragma unroll
        for (int nt = 0; nt < 4; nt++)
#pragma unroll
            for (int j = 0; j < 4; j++) acc[mt][nt][j] = 0.f;

    const int NKT = DD / 32;
    for (int kb = 0; kb < NKT; kb++) {
        CP_WAIT1();
        __syncthreads();
        const int st = kb % 3;
        const uint32_t* As = sm + (size_t)st * 2 * GTILEW;
        const uint32_t* Bs = As + GTILEW;
#pragma unroll
        for (int ks = 0; ks < 2; ks++) {
            const int kw = ks * 8;
            uint32_t af[4][4], bf[4][2];
#pragma unroll
            for (int mt = 0; mt < 4; mt++) {
                const int r0 = wm * 64 + mt * 16;
                af[mt][0] = As[(r0 + g    ) * GW + kw + t];
                af[mt][1] = As[(r0 + g + 8) * GW + kw + t];
                af[mt][2] = As[(r0 + g    ) * GW + kw + t + 4];
                af[mt][3] = As[(r0 + g + 8) * GW + kw + t + 4];
            }
#pragma unroll
            for (int nt = 0; nt < 4; nt++) {
                const int n0 = wn * 32 + nt * 8;
                bf[nt][0] = Bs[(n0 + g) * GW + kw + t];
                bf[nt][1] = Bs[(n0 + g) * GW + kw + t + 4];
            }
#pragma unroll
            for (int mt = 0; mt < 4; mt++)
#pragma unroll
                for (int nt = 0; nt < 4; nt++)
                    mma_bf16(acc[mt][nt], af[mt], bf[nt]);
        }
        __syncthreads();
        if (kb + 2 < NKT) GEMM_ISSUE(kb + 2, (kb + 2) % 3);
        CP_COMMIT();
    }
#undef GEMM_ISSUE

    // ---- epilogue ----
#pragma unroll
    for (int nt = 0; nt < 4; nt++) {
        const int col = bx * 128 + wn * 32 + nt * 8 + 2 * t;
        const float b0 = bias[col], b1 = bias[col + 1];
#pragma unroll
        for (int mt = 0; mt < 4; mt++) {
            const int row = by * 128 + wm * 64 + mt * 16 + g;
            const size_t o0 = (size_t)row * DD + col;
            const size_t o1 = (size_t)(row + 8) * DD + col;
            float v00 = acc[mt][nt][0] + b0, v01 = acc[mt][nt][1] + b1;
            float v10 = acc[mt][nt][2] + b0, v11 = acc[mt][nt][3] + b1;
            if (OUT_BF16) {
                *(uint32_t*)((__nv_bfloat16*)Cout + o0) = pack_bf16(v00, v01);
                *(uint32_t*)((__nv_bfloat16*)Cout + o1) = pack_bf16(v10, v11);
            } else {
                float* C = (float*)Cout;
                if (R) {
                    float2 r0 = *(const float2*)(R + o0);
                    float2 r1 = *(const float2*)(R + o1);
                    v00 += r0.x; v01 += r0.y; v10 += r1.x; v11 += r1.y;
                }
                *(float2*)(C + o0) = make_float2(v00, v01);
                *(float2*)(C + o1) = make_float2(v10, v11);
            }
        }
    }
}

// ========================= bf16 flash attention ==============================
// R6-proven compute; K double-buffered via cp.async, Vt double-buffered in smem,
// V LDG for block i+1 issued before waiting on block i.
#define AW 36                                   // word stride (72 bf16, 144 B)
#define QW_OFF 0
#define KW_OFF (128 * AW)                       // Q: 128 rows
#define VW_OFF (KW_OFF + 2 * 64 * AW)           // K: 2 bufs x 64 rows
#define ATT_WORDS (VW_OFF + 2 * 64 * AW)        // V: 2 bufs x 64 rows -> 13824 w
#define ATT_SMEM (ATT_WORDS * 4)                // 55296 B

__global__ __launch_bounds__(256, 2)
void attn_bf16(const __nv_bfloat16* __restrict__ Q, const __nv_bfloat16* __restrict__ K,
               const __nv_bfloat16* __restrict__ V, __nv_bfloat16* __restrict__ O)
{
    extern __shared__ uint32_t sm[];
    const uint32_t sbase = smem_u32(sm);
    const uint32_t qaddr = sbase + QW_OFF * 4;
    const uint32_t kaddr = sbase + KW_OFF * 4;

    const int tid = threadIdx.x;
    const int wid = tid >> 5, lane = tid & 31;
    const int g = lane >> 2, t = lane & 3;
    const int m0 = wid * 16;

    const int bh = blockIdx.y;
    const int b = bh >> 4, h = bh & 15;
    const int q0 = blockIdx.x * 128;
    const size_t base = (size_t)b * LL * DD + (size_t)h * HD;

    const int vkey = tid & 63;
    const int vw0 = (tid >> 6) * 8;

    // ---- prologue: Q + K0 cp.async (group 0), V0 LDG ----
    {
#pragma unroll
        for (int i = 0; i < 4; i++) {
            const int c = tid + i * 256;
            const int row = c >> 3, ch = (c & 7) * 16, el = (c & 7) * 8;
            CP_ASYNC16(qaddr + (uint32_t)(row * 144) + ch,
                       Q + base + (size_t)(q0 + row) * DD + el);
        }
#pragma unroll
        for (int i = 0; i < 2; i++) {
            const int c = tid + i * 256;
            const int row = c >> 3, ch = (c & 7) * 16, el = (c & 7) * 8;
            CP_ASYNC16(kaddr + (uint32_t)(row * 144) + ch,
                       K + base + (size_t)row * DD + el);
        }
        CP_COMMIT();
    }
    uint32_t vreg[8];
    {
        const uint32_t* vg = (const uint32_t*)(V + base + (size_t)vkey * DD) + vw0;
#pragma unroll
        for (int j = 0; j < 8; j++) vreg[j] = vg[j];
    }

    float oacc[8][4];
    float mrow[2] = { -1e30f, -1e30f };
    float lrow[2] = { 0.f, 0.f };
#pragma unroll
    for (int nt = 0; nt < 8; nt++)
#pragma unroll
        for (int j = 0; j < 4; j++) oacc[nt][j] = 0.f;

    const int NBLK = LL / 64;
    for (int i = 0; i < NBLK; i++) {
        const int buf = i & 1;
        // STS-transpose this block's V registers into Vt[buf]
        {
            unsigned short* Vt16 = (unsigned short*)(sm + VW_OFF + buf * 64 * AW);
#pragma unroll
            for (int j = 0; j < 8; j++) {
                const int d2 = (vw0 + j) * 2;
                Vt16[(d2    ) * 72 + vkey] = (unsigned short)(vreg[j] & 0xffffu);
                Vt16[(d2 + 1) * 72 + vkey] = (unsigned short)(vreg[j] >> 16);
            }
        }
        // prefetch next block: K via cp.async, V via LDG
        if (i + 1 < NBLK) {
            const uint32_t ko = kaddr + (uint32_t)((buf ^ 1) * 64 * AW * 4);
#pragma unroll
            for (int ii = 0; ii < 2; ii++) {
                const int c = tid + ii * 256;
                const int row = c >> 3, ch = (c & 7) * 16, el = (c & 7) * 8;
                CP_ASYNC16(ko + (uint32_t)(row * 144) + ch,
                           K + base + (size_t)((i + 1) * 64 + row) * DD + el);
            }
        }
        CP_COMMIT();
        if (i + 1 < NBLK) {
            const uint32_t* vg =
                (const uint32_t*)(V + base + (size_t)((i + 1) * 64 + vkey) * DD) + vw0;
#pragma unroll
            for (int j = 0; j < 8; j++) vreg[j] = vg[j];
        }
        CP_WAIT1();
        __syncthreads();

        const uint32_t* K32 = sm + KW_OFF + buf * 64 * AW;
        const uint32_t* V32 = sm + VW_OFF + buf * 64 * AW;
        const uint32_t* Q32 = sm + QW_OFF;

        // ---- S = Q @ K^T ----
        float sacc[8][4];
#pragma unroll
        for (int nt = 0; nt < 8; nt++)
#pragma unroll
            for (int j = 0; j < 4; j++) sacc[nt][j] = 0.f;

#pragma unroll
        for (int ks = 0; ks < 4; ks++) {
            const int kw = ks * 8;
            uint32_t aq[4];
            aq[0] = Q32[(m0 + g    ) * AW + kw + t];
            aq[1] = Q32[(m0 + g + 8) * AW + kw + t];
            aq[2] = Q32[(m0 + g    ) * AW + kw + t + 4];
            aq[3] = Q32[(m0 + g + 8) * AW + kw + t + 4];
#pragma unroll
            for (int nt = 0; nt < 8; nt++) {
                uint32_t bk[2];
                bk[0] = K32[(nt * 8 + g) * AW + kw + t];
                bk[1] = K32[(nt * 8 + g) * AW + kw + t + 4];
                mma_bf16(sacc[nt], aq, bk);
            }
        }

        // ---- online softmax (scale 0.125 folded into exp) ----
#pragma unroll
        for (int r = 0; r < 2; r++) {
            const int j0 = r * 2;
            float mx = -1e30f;
#pragma unroll
            for (int nt = 0; nt < 8; nt++)
                mx = fmaxf(mx, fmaxf(sacc[nt][j0], sacc[nt][j0 + 1]));
            mx = fmaxf(mx, __shfl_xor_sync(0xffffffffu, mx, 1));
            mx = fmaxf(mx, __shfl_xor_sync(0xffffffffu, mx, 2));
            const float mnew = fmaxf(mrow[r], mx);
            const float alpha = __expf((mrow[r] - mnew) * 0.125f);
            mrow[r] = mnew;
            float rs = 0.f;
#pragma unroll
            for (int nt = 0; nt < 8; nt++) {
                sacc[nt][j0]     = __expf((sacc[nt][j0]     - mnew) * 0.125f);
                sacc[nt][j0 + 1] = __expf((sacc[nt][j0 + 1] - mnew) * 0.125f);
                rs += sacc[nt][j0] + sacc[nt][j0 + 1];
            }
            rs += __shfl_xor_sync(0xffffffffu, rs, 1);
            rs += __shfl_xor_sync(0xffffffffu, rs, 2);
            lrow[r] = lrow[r] * alpha + rs;
#pragma unroll
            for (int nt = 0; nt < 8; nt++) {
                oacc[nt][j0]     *= alpha;
                oacc[nt][j0 + 1] *= alpha;
            }
        }

        // ---- O += P @ V (P fragments straight from sacc) ----
#pragma unroll
        for (int j = 0; j < 4; j++) {
            uint32_t ap[4];
            ap[0] = pack_bf16(sacc[2 * j][0],     sacc[2 * j][1]);
            ap[1] = pack_bf16(sacc[2 * j][2],     sacc[2 * j][3]);
            ap[2] = pack_bf16(sacc[2 * j + 1][0], sacc[2 * j + 1][1]);
            ap[3] = pack_bf16(sacc[2 * j + 1][2], sacc[2 * j + 1][3]);
#pragma unroll
            for (int nt = 0; nt < 8; nt++) {
                uint32_t bv[2];
                bv[0] = V32[(nt * 8 + g) * AW + j * 8 + t];
                bv[1] = V32[(nt * 8 + g) * AW + j * 8 + t + 4];
                mma_bf16(oacc[nt], ap, bv);
            }
        }
        __syncthreads();
    }

    // ---- normalize + store (bf16) ----
    const float inv0 = 1.f / lrow[0];
    const float inv1 = 1.f / lrow[1];
#pragma unroll
    for (int nt = 0; nt < 8; nt++) {
        const int col = nt * 8 + 2 * t;
        const size_t o0 = base + (size_t)(q0 + m0 + g    ) * DD + col;
        const size_t o1 = base + (size_t)(q0 + m0 + g + 8) * DD + col;
        *(uint32_t*)(O + o0) = pack_bf16(oacc[nt][0] * inv0, oacc[nt][1] * inv0);
        *(uint32_t*)(O + o1) = pack_bf16(oacc[nt][2] * inv1, oacc[nt][3] * inv1);
    }
}

// ------------------------- LayerNorm -----------------------------------------
__global__ __launch_bounds__(256) void ln_kernel(
    const float* __restrict__ X, const float* __restrict__ gamma,
    const float* __restrict__ beta, float* __restrict__ out)
{
    __shared__ float ssum[8], ssq[8];
    const int row = blockIdx.x;
    const int tid = threadIdx.x;
    const float* x = X + (size_t)row * DD;

    float4 v = *(const float4*)(x + tid * 4);
    float s = v.x + v.y + v.z + v.w;
    float q = v.x * v.x + v.y * v.y + v.z * v.z + v.w * v.w;
#pragma unroll
    for (int off = 16; off > 0; off >>= 1) {
        s += __shfl_xor_sync(0xffffffffu, s, off);
        q += __shfl_xor_sync(0xffffffffu, q, off);
    }
    if ((tid & 31) == 0) { ssum[tid >> 5] = s; ssq[tid >> 5] = q; }
    __syncthreads();
    float ts = 0.f, tq = 0.f;
#pragma unroll
    for (int i = 0; i < 8; i++) { ts += ssum[i]; tq += ssq[i]; }

    const float mean = ts * (1.f / DD);
    const float var = tq * (1.f / DD) - mean * mean;
    const float inv = rsqrtf(var + 1e-5f);

    float4 gmv = *(const float4*)(gamma + tid * 4);
    float4 btv = *(const float4*)(beta + tid * 4);
    float4 o4;
    o4.x = (v.x - mean) * inv * gmv.x + btv.x;
    o4.y = (v.y - mean) * inv * gmv.y + btv.y;
    o4.z = (v.z - mean) * inv * gmv.z + btv.z;
    o4.w = (v.w - mean) * inv * gmv.w + btv.w;
    *(float4*)(out + (size_t)row * DD + tid * 4) = o4;
}

// ------------------------- launch --------------------------------------------
extern "C" void kernel_launch(void* const* d_in, const int* in_sizes, int n_in,
                              void* d_out, int out_size)
{
    const float* X     = (const float*)d_in[0];
    const float* Wq    = (const float*)d_in[1];
    const float* bq    = (const float*)d_in[2];
    const float* Wk    = (const float*)d_in[3];
    const float* bk    = (const float*)d_in[4];
    const float* Wv    = (const float*)d_in[5];
    const float* bv    = (const float*)d_in[6];
    const float* Wo    = (const float*)d_in[7];
    const float* bo    = (const float*)d_in[8];
    const float* gamma = (const float*)d_in[9];
    const float* beta  = (const float*)d_in[10];
    float* out = (float*)d_out;

    __nv_bfloat16 *Xb, *Qb, *Kb, *Vb, *Ob, *Wqt, *Wkt, *Wvt, *Wot;
    float* Rp;
    cudaGetSymbolAddress((void**)&Xb, g_Xb);
    cudaGetSymbolAddress((void**)&Qb, g_Qb);
    cudaGetSymbolAddress((void**)&Kb, g_Kb);
    cudaGetSymbolAddress((void**)&Vb, g_Vb);
    cudaGetSymbolAddress((void**)&Ob, g_Ob);
    cudaGetSymbolAddress((void**)&Wqt, g_Wqt);
    cudaGetSymbolAddress((void**)&Wkt, g_Wkt);
    cudaGetSymbolAddress((void**)&Wvt, g_Wvt);
    cudaGetSymbolAddress((void**)&Wot, g_Wot);
    cudaGetSymbolAddress((void**)&Rp, g_R);

    cudaFuncSetAttribute(gemm_bf16<true>,
                         cudaFuncAttributeMaxDynamicSharedMemorySize, GEMM_SMEM);
    cudaFuncSetAttribute(gemm_bf16<false>,
                         cudaFuncAttributeMaxDynamicSharedMemorySize, GEMM_SMEM);
    cudaFuncSetAttribute(attn_bf16,
                         cudaFuncAttributeMaxDynamicSharedMemorySize, ATT_SMEM);

    dim3 gemm_grid(DD / 128, MM / 128);   // (8, 64)
    dim3 tgrid(DD / 32, DD / 32);
    dim3 tblk(32, 8);

    cvt_kernel<<<MM * DD / 4 / 256, 256>>>(X, Xb);
    wtrans_kernel<<<tgrid, tblk>>>(Wq, Wqt);
    wtrans_kernel<<<tgrid, tblk>>>(Wk, Wkt);
    wtrans_kernel<<<tgrid, tblk>>>(Wv, Wvt);
    wtrans_kernel<<<tgrid, tblk>>>(Wo, Wot);

    gemm_bf16<true><<<gemm_grid, 256, GEMM_SMEM>>>(Xb, Wqt, bq, nullptr, Qb);
    gemm_bf16<true><<<gemm_grid, 256, GEMM_SMEM>>>(Xb, Wkt, bk, nullptr, Kb);
    gemm_bf16<true><<<gemm_grid, 256, GEMM_SMEM>>>(Xb, Wvt, bv, nullptr, Vb);

    attn_bf16<<<dim3(LL / 128, BB * HH), 256, ATT_SMEM>>>(Qb, Kb, Vb, Ob);

    gemm_bf16<false><<<gemm_grid, 256, GEMM_SMEM>>>(Ob, Wot, bo, X, Rp);

    ln_kernel<<<MM, 256>>>(Rp, gamma, beta, out);
}

// round 9
// speedup vs baseline: 4.1624x; 1.0240x over previous
#include <cuda_runtime.h>
#include <cuda_bf16.h>
#include <math.h>
#include <stdint.h>

// Problem dims
#define BB 4
#define LL 2048
#define DD 1024
#define HH 16
#define HD 64
#define MM (BB * LL)   // 8192

// ------------------------- scratch (static device globals) -------------------
__device__ __nv_bfloat16 g_Xb[MM * DD];
__device__ __nv_bfloat16 g_Qb[MM * DD];
__device__ __nv_bfloat16 g_Kb[MM * DD];
__device__ __nv_bfloat16 g_Vb[MM * DD];
__device__ __nv_bfloat16 g_Ob[MM * DD];
__device__ __nv_bfloat16 g_Wqt[DD * DD];
__device__ __nv_bfloat16 g_Wkt[DD * DD];
__device__ __nv_bfloat16 g_Wvt[DD * DD];
__device__ __nv_bfloat16 g_Wot[DD * DD];
__device__ float g_R[MM * DD];

// ========================= helpers ==========================================
__device__ __forceinline__ uint32_t smem_u32(const void* p) {
    uint32_t a;
    asm("{ .reg .u64 t; cvta.to.shared.u64 t, %1; cvt.u32.u64 %0, t; }"
        : "=r"(a) : "l"(p));
    return a;
}
#define CP_ASYNC16(dst, src) \
    asm volatile("cp.async.ca.shared.global [%0], [%1], 16;" :: "r"(dst), "l"(src))
#define CP_COMMIT() asm volatile("cp.async.commit_group;")
#define CP_WAIT1()  asm volatile("cp.async.wait_group 1;")

__device__ __forceinline__ uint32_t pack_bf16(float lo, float hi) {
    uint32_t r;
    asm("cvt.rn.bf16x2.f32 %0, %1, %2;" : "=r"(r) : "f"(hi), "f"(lo));
    return r;
}
__device__ __forceinline__ void ldsm4(uint32_t* r, uint32_t addr) {
    asm volatile("ldmatrix.sync.aligned.m8n8.x4.shared.b16 {%0,%1,%2,%3}, [%4];"
                 : "=r"(r[0]), "=r"(r[1]), "=r"(r[2]), "=r"(r[3]) : "r"(addr));
}
__device__ __forceinline__ void mma_bf16(float* c, const uint32_t* a, const uint32_t* b) {
    asm volatile(
        "mma.sync.aligned.m16n8k16.row.col.f32.bf16.bf16.f32 "
        "{%0,%1,%2,%3}, {%4,%5,%6,%7}, {%8,%9}, {%0,%1,%2,%3};"
        : "+f"(c[0]), "+f"(c[1]), "+f"(c[2]), "+f"(c[3])
        : "r"(a[0]), "r"(a[1]), "r"(a[2]), "r"(a[3]), "r"(b[0]), "r"(b[1]));
}

// ========================= fp32 -> bf16 convert =============================
__global__ __launch_bounds__(256) void cvt_kernel(const float* __restrict__ X,
                                                  __nv_bfloat16* __restrict__ Y)
{
    const int i = blockIdx.x * 256 + threadIdx.x;
    float4 v = ((const float4*)X)[i];
    uint2 o;
    o.x = pack_bf16(v.x, v.y);
    o.y = pack_bf16(v.z, v.w);
    ((uint2*)Y)[i] = o;
}

// ======== weight transpose+convert: W[K][N] f32 -> Wt[N][K] bf16 ============
__global__ __launch_bounds__(256) void wtrans_kernel(const float* __restrict__ W,
                                                     __nv_bfloat16* __restrict__ Wt)
{
    __shared__ float tile[32][33];
    const int n0 = blockIdx.x * 32, k0 = blockIdx.y * 32;
    const int tx = threadIdx.x, ty = threadIdx.y;   // 32 x 8
#pragma unroll
    for (int i = 0; i < 32; i += 8)
        tile[ty + i][tx] = W[(size_t)(k0 + ty + i) * DD + n0 + tx];
    __syncthreads();
#pragma unroll
    for (int i = 0; i < 32; i += 8)
        Wt[(size_t)(n0 + ty + i) * DD + k0 + tx] = __float2bfloat16(tile[tx][ty + i]);
}

// ========================= bf16 mma GEMM (3-stage cp.async, ldmatrix) ========
// C[M,N] = A[M,K]_bf16 @ Wt[N,K]_bf16^T + bias (+ R). CTA 128x128, BK=32, 8 warps.
#define GW 20                          // words per smem row (32 bf16 + pad)
#define GTILEW (128 * GW)              // 2560 words per tile
#define GEMM_SMEM (3 * 2 * GTILEW * 4) // 61440 B

template <bool OUT_BF16>
__global__ __launch_bounds__(256)
void gemm_bf16(const __nv_bfloat16* __restrict__ A, const __nv_bfloat16* __restrict__ Bt,
               const float* __restrict__ bias, const float* __restrict__ R,
               void* __restrict__ Cout)
{
    extern __shared__ uint32_t sm[];
    const uint32_t sbase = smem_u32(sm);

    const int tid = threadIdx.x;
    const int wid = tid >> 5, lane = tid & 31;
    const int g = lane >> 2, t = lane & 3;
    const int lr = lane & 15, lc = lane >> 4;
    const int wm = wid >> 2, wn = wid & 3;
    const int bx = blockIdx.x, by = blockIdx.y;

    const __nv_bfloat16* Ab = A  + (size_t)(by * 128) * DD;
    const __nv_bfloat16* Bb = Bt + (size_t)(bx * 128) * DD;

    const int L_row = tid >> 2;             // 0..63
    const int L_ch  = (tid & 3) * 16;       // byte offset in row
    const int L_el  = (tid & 3) * 8;        // element offset

#define GEMM_ISSUE(kb, st) do {                                                  \
    const uint32_t ao_ = sbase + (uint32_t)(st) * 2 * GTILEW * 4;                \
    const uint32_t bo_ = ao_ + GTILEW * 4;                                       \
    _Pragma("unroll")                                                            \
    for (int i_ = 0; i_ < 2; i_++) {                                             \
        const int row_ = L_row + i_ * 64;                                        \
        CP_ASYNC16(ao_ + (uint32_t)(row_ * 80) + L_ch,                           \
                   Ab + (size_t)row_ * DD + (kb) * 32 + L_el);                   \
        CP_ASYNC16(bo_ + (uint32_t)(row_ * 80) + L_ch,                           \
                   Bb + (size_t)row_ * DD + (kb) * 32 + L_el);                   \
    }                                                                            \
} while (0)

    GEMM_ISSUE(0, 0); CP_COMMIT();
    GEMM_ISSUE(1, 1); CP_COMMIT();

    float acc[4][4][4];
#pragma unroll
    for (int mt = 0; mt < 4; mt++)
#pragma unroll
        for (int nt = 0; nt < 4; nt++)
#pragma unroll
            for (int j = 0; j < 4; j++) acc[mt][nt][j] = 0.f;

    const int NKT = DD / 32;
    for (int kb = 0; kb < NKT; kb++) {
        CP_WAIT1();
        __syncthreads();
        const int st = kb % 3;
        const uint32_t abase = sbase + (uint32_t)st * 2 * GTILEW * 4;
        const uint32_t bbase = abase + GTILEW * 4;
#pragma unroll
        for (int ks = 0; ks < 2; ks++) {
            uint32_t af[4][4], bq[2][4];
#pragma unroll
            for (int mt = 0; mt < 4; mt++)
                ldsm4(af[mt], abase +
                      (uint32_t)(((wm * 64 + mt * 16 + lr) * GW + ks * 8 + lc * 4) * 4));
#pragma unroll
            for (int p = 0; p < 2; p++)
                ldsm4(bq[p], bbase +
                      (uint32_t)(((wn * 32 + p * 16 + lr) * GW + ks * 8 + lc * 4) * 4));
            uint32_t bf[4][2] = {
                { bq[0][0], bq[0][2] }, { bq[0][1], bq[0][3] },
                { bq[1][0], bq[1][2] }, { bq[1][1], bq[1][3] } };
#pragma unroll
            for (int mt = 0; mt < 4; mt++)
#pragma unroll
                for (int nt = 0; nt < 4; nt++)
                    mma_bf16(acc[mt][nt], af[mt], bf[nt]);
        }
        __syncthreads();
        if (kb + 2 < NKT) GEMM_ISSUE(kb + 2, (kb + 2) % 3);
        CP_COMMIT();
    }
#undef GEMM_ISSUE

    // ---- epilogue ----
#pragma unroll
    for (int nt = 0; nt < 4; nt++) {
        const int col = bx * 128 + wn * 32 + nt * 8 + 2 * t;
        const float b0 = bias[col], b1 = bias[col + 1];
#pragma unroll
        for (int mt = 0; mt < 4; mt++) {
            const int row = by * 128 + wm * 64 + mt * 16 + g;
            const size_t o0 = (size_t)row * DD + col;
            const size_t o1 = (size_t)(row + 8) * DD + col;
            float v00 = acc[mt][nt][0] + b0, v01 = acc[mt][nt][1] + b1;
            float v10 = acc[mt][nt][2] + b0, v11 = acc[mt][nt][3] + b1;
            if (OUT_BF16) {
                *(uint32_t*)((__nv_bfloat16*)Cout + o0) = pack_bf16(v00, v01);
                *(uint32_t*)((__nv_bfloat16*)Cout + o1) = pack_bf16(v10, v11);
            } else {
                float* C = (float*)Cout;
                if (R) {
                    float2 r0 = *(const float2*)(R + o0);
                    float2 r1 = *(const float2*)(R + o1);
                    v00 += r0.x; v01 += r0.y; v10 += r1.x; v11 += r1.y;
                }
                *(float2*)(C + o0) = make_float2(v00, v01);
                *(float2*)(C + o1) = make_float2(v10, v11);
            }
        }
    }
}

// ========================= bf16 flash attention (R8, unchanged) ==============
#define AW 36                                   // word stride (72 bf16, 144 B)
#define QW_OFF 0
#define KW_OFF (128 * AW)                       // Q: 128 rows
#define VW_OFF (KW_OFF + 2 * 64 * AW)           // K: 2 bufs x 64 rows
#define ATT_WORDS (VW_OFF + 2 * 64 * AW)        // V: 2 bufs x 64 rows -> 13824 w
#define ATT_SMEM (ATT_WORDS * 4)                // 55296 B

__global__ __launch_bounds__(256, 2)
void attn_bf16(const __nv_bfloat16* __restrict__ Q, const __nv_bfloat16* __restrict__ K,
               const __nv_bfloat16* __restrict__ V, __nv_bfloat16* __restrict__ O)
{
    extern __shared__ uint32_t sm[];
    const uint32_t sbase = smem_u32(sm);
    const uint32_t qaddr = sbase + QW_OFF * 4;
    const uint32_t kaddr = sbase + KW_OFF * 4;

    const int tid = threadIdx.x;
    const int wid = tid >> 5, lane = tid & 31;
    const int g = lane >> 2, t = lane & 3;
    const int m0 = wid * 16;

    const int bh = blockIdx.y;
    const int b = bh >> 4, h = bh & 15;
    const int q0 = blockIdx.x * 128;
    const size_t base = (size_t)b * LL * DD + (size_t)h * HD;

    const int vkey = tid & 63;
    const int vw0 = (tid >> 6) * 8;

    // ---- prologue: Q + K0 cp.async (group 0), V0 LDG ----
    {
#pragma unroll
        for (int i = 0; i < 4; i++) {
            const int c = tid + i * 256;
            const int row = c >> 3, ch = (c & 7) * 16, el = (c & 7) * 8;
            CP_ASYNC16(qaddr + (uint32_t)(row * 144) + ch,
                       Q + base + (size_t)(q0 + row) * DD + el);
        }
#pragma unroll
        for (int i = 0; i < 2; i++) {
            const int c = tid + i * 256;
            const int row = c >> 3, ch = (c & 7) * 16, el = (c & 7) * 8;
            CP_ASYNC16(kaddr + (uint32_t)(row * 144) + ch,
                       K + base + (size_t)row * DD + el);
        }
        CP_COMMIT();
    }
    uint32_t vreg[8];
    {
        const uint32_t* vg = (const uint32_t*)(V + base + (size_t)vkey * DD) + vw0;
#pragma unroll
        for (int j = 0; j < 8; j++) vreg[j] = vg[j];
    }

    float oacc[8][4];
    float mrow[2] = { -1e30f, -1e30f };
    float lrow[2] = { 0.f, 0.f };
#pragma unroll
    for (int nt = 0; nt < 8; nt++)
#pragma unroll
        for (int j = 0; j < 4; j++) oacc[nt][j] = 0.f;

    const int NBLK = LL / 64;
    for (int i = 0; i < NBLK; i++) {
        const int buf = i & 1;
        // STS-transpose this block's V registers into Vt[buf]
        {
            unsigned short* Vt16 = (unsigned short*)(sm + VW_OFF + buf * 64 * AW);
#pragma unroll
            for (int j = 0; j < 8; j++) {
                const int d2 = (vw0 + j) * 2;
                Vt16[(d2    ) * 72 + vkey] = (unsigned short)(vreg[j] & 0xffffu);
                Vt16[(d2 + 1) * 72 + vkey] = (unsigned short)(vreg[j] >> 16);
            }
        }
        // prefetch next block: K via cp.async, V via LDG
        if (i + 1 < NBLK) {
            const uint32_t ko = kaddr + (uint32_t)((buf ^ 1) * 64 * AW * 4);
#pragma unroll
            for (int ii = 0; ii < 2; ii++) {
                const int c = tid + ii * 256;
                const int row = c >> 3, ch = (c & 7) * 16, el = (c & 7) * 8;
                CP_ASYNC16(ko + (uint32_t)(row * 144) + ch,
                           K + base + (size_t)((i + 1) * 64 + row) * DD + el);
            }
        }
        CP_COMMIT();
        if (i + 1 < NBLK) {
            const uint32_t* vg =
                (const uint32_t*)(V + base + (size_t)((i + 1) * 64 + vkey) * DD) + vw0;
#pragma unroll
            for (int j = 0; j < 8; j++) vreg[j] = vg[j];
        }
        CP_WAIT1();
        __syncthreads();

        const uint32_t* K32 = sm + KW_OFF + buf * 64 * AW;
        const uint32_t* V32 = sm + VW_OFF + buf * 64 * AW;
        const uint32_t* Q32 = sm + QW_OFF;

        // ---- S = Q @ K^T ----
        float sacc[8][4];
#pragma unroll
        for (int nt = 0; nt < 8; nt++)
#pragma unroll
            for (int j = 0; j < 4; j++) sacc[nt][j] = 0.f;

#pragma unroll
        for (int ks = 0; ks < 4; ks++) {
            const int kw = ks * 8;
            uint32_t aq[4];
            aq[0] = Q32[(m0 + g    ) * AW + kw + t];
            aq[1] = Q32[(m0 + g + 8) * AW + kw + t];
            aq[2] = Q32[(m0 + g    ) * AW + kw + t + 4];
            aq[3] = Q32[(m0 + g + 8) * AW + kw + t + 4];
#pragma unroll
            for (int nt = 0; nt < 8; nt++) {
                uint32_t bk[2];
                bk[0] = K32[(nt * 8 + g) * AW + kw + t];
                bk[1] = K32[(nt * 8 + g) * AW + kw + t + 4];
                mma_bf16(sacc[nt], aq, bk);
            }
        }

        // ---- online softmax (scale 0.125 folded into exp) ----
#pragma unroll
        for (int r = 0; r < 2; r++) {
            const int j0 = r * 2;
            float mx = -1e30f;
#pragma unroll
            for (int nt = 0; nt < 8; nt++)
                mx = fmaxf(mx, fmaxf(sacc[nt][j0], sacc[nt][j0 + 1]));
            mx = fmaxf(mx, __shfl_xor_sync(0xffffffffu, mx, 1));
            mx = fmaxf(mx, __shfl_xor_sync(0xffffffffu, mx, 2));
            const float mnew = fmaxf(mrow[r], mx);
            const float alpha = __expf((mrow[r] - mnew) * 0.125f);
            mrow[r] = mnew;
            float rs = 0.f;
#pragma unroll
            for (int nt = 0; nt < 8; nt++) {
                sacc[nt][j0]     = __expf((sacc[nt][j0]     - mnew) * 0.125f);
                sacc[nt][j0 + 1] = __expf((sacc[nt][j0 + 1] - mnew) * 0.125f);
                rs += sacc[nt][j0] + sacc[nt][j0 + 1];
            }
            rs += __shfl_xor_sync(0xffffffffu, rs, 1);
            rs += __shfl_xor_sync(0xffffffffu, rs, 2);
            lrow[r] = lrow[r] * alpha + rs;
#pragma unroll
            for (int nt = 0; nt < 8; nt++) {
                oacc[nt][j0]     *= alpha;
                oacc[nt][j0 + 1] *= alpha;
            }
        }

        // ---- O += P @ V (P fragments straight from sacc) ----
#pragma unroll
        for (int j = 0; j < 4; j++) {
            uint32_t ap[4];
            ap[0] = pack_bf16(sacc[2 * j][0],     sacc[2 * j][1]);
            ap[1] = pack_bf16(sacc[2 * j][2],     sacc[2 * j][3]);
            ap[2] = pack_bf16(sacc[2 * j + 1][0], sacc[2 * j + 1][1]);
            ap[3] = pack_bf16(sacc[2 * j + 1][2], sacc[2 * j + 1][3]);
#pragma unroll
            for (int nt = 0; nt < 8; nt++) {
                uint32_t bv[2];
                bv[0] = V32[(nt * 8 + g) * AW + j * 8 + t];
                bv[1] = V32[(nt * 8 + g) * AW + j * 8 + t + 4];
                mma_bf16(oacc[nt], ap, bv);
            }
        }
        __syncthreads();
    }

    // ---- normalize + store (bf16) ----
    const float inv0 = 1.f / lrow[0];
    const float inv1 = 1.f / lrow[1];
#pragma unroll
    for (int nt = 0; nt < 8; nt++) {
        const int col = nt * 8 + 2 * t;
        const size_t o0 = base + (size_t)(q0 + m0 + g    ) * DD + col;
        const size_t o1 = base + (size_t)(q0 + m0 + g + 8) * DD + col;
        *(uint32_t*)(O + o0) = pack_bf16(oacc[nt][0] * inv0, oacc[nt][1] * inv0);
        *(uint32_t*)(O + o1) = pack_bf16(oacc[nt][2] * inv1, oacc[nt][3] * inv1);
    }
}

// ------------------------- LayerNorm -----------------------------------------
__global__ __launch_bounds__(256) void ln_kernel(
    const float* __restrict__ X, const float* __restrict__ gamma,
    const float* __restrict__ beta, float* __restrict__ out)
{
    __shared__ float ssum[8], ssq[8];
    const int row = blockIdx.x;
    const int tid = threadIdx.x;
    const float* x = X + (size_t)row * DD;

    float4 v = *(const float4*)(x + tid * 4);
    float s = v.x + v.y + v.z + v.w;
    float q = v.x * v.x + v.y * v.y + v.z * v.z + v.w * v.w;
#pragma unroll
    for (int off = 16; off > 0; off >>= 1) {
        s += __shfl_xor_sync(0xffffffffu, s, off);
        q += __shfl_xor_sync(0xffffffffu, q, off);
    }
    if ((tid & 31) == 0) { ssum[tid >> 5] = s; ssq[tid >> 5] = q; }
    __syncthreads();
    float ts = 0.f, tq = 0.f;
#pragma unroll
    for (int i = 0; i < 8; i++) { ts += ssum[i]; tq += ssq[i]; }

    const float mean = ts * (1.f / DD);
    const float var = tq * (1.f / DD) - mean * mean;
    const float inv = rsqrtf(var + 1e-5f);

    float4 gmv = *(const float4*)(gamma + tid * 4);
    float4 btv = *(const float4*)(beta + tid * 4);
    float4 o4;
    o4.x = (v.x - mean) * inv * gmv.x + btv.x;
    o4.y = (v.y - mean) * inv * gmv.y + btv.y;
    o4.z = (v.z - mean) * inv * gmv.z + btv.z;
    o4.w = (v.w - mean) * inv * gmv.w + btv.w;
    *(float4*)(out + (size_t)row * DD + tid * 4) = o4;
}

// ------------------------- launch --------------------------------------------
extern "C" void kernel_launch(void* const* d_in, const int* in_sizes, int n_in,
                              void* d_out, int out_size)
{
    const float* X     = (const float*)d_in[0];
    const float* Wq    = (const float*)d_in[1];
    const float* bq    = (const float*)d_in[2];
    const float* Wk    = (const float*)d_in[3];
    const float* bk    = (const float*)d_in[4];
    const float* Wv    = (const float*)d_in[5];
    const float* bv    = (const float*)d_in[6];
    const float* Wo    = (const float*)d_in[7];
    const float* bo    = (const float*)d_in[8];
    const float* gamma = (const float*)d_in[9];
    const float* beta  = (const float*)d_in[10];
    float* out = (float*)d_out;

    __nv_bfloat16 *Xb, *Qb, *Kb, *Vb, *Ob, *Wqt, *Wkt, *Wvt, *Wot;
    float* Rp;
    cudaGetSymbolAddress((void**)&Xb, g_Xb);
    cudaGetSymbolAddress((void**)&Qb, g_Qb);
    cudaGetSymbolAddress((void**)&Kb, g_Kb);
    cudaGetSymbolAddress((void**)&Vb, g_Vb);
    cudaGetSymbolAddress((void**)&Ob, g_Ob);
    cudaGetSymbolAddress((void**)&Wqt, g_Wqt);
    cudaGetSymbolAddress((void**)&Wkt, g_Wkt);
    cudaGetSymbolAddress((void**)&Wvt, g_Wvt);
    cudaGetSymbolAddress((void**)&Wot, g_Wot);
    cudaGetSymbolAddress((void**)&Rp, g_R);

    cudaFuncSetAttribute(gemm_bf16<true>,
                         cudaFuncAttributeMaxDynamicSharedMemorySize, GEMM_SMEM);
    cudaFuncSetAttribute(gemm_bf16<false>,
                         cudaFuncAttributeMaxDynamicSharedMemorySize, GEMM_SMEM);
    cudaFuncSetAttribute(attn_bf16,
                         cudaFuncAttributeMaxDynamicSharedMemorySize, ATT_SMEM);

    dim3 gemm_grid(DD / 128, MM / 128);   // (8, 64)
    dim3 tgrid(DD / 32, DD / 32);
    dim3 tblk(32, 8);

    cvt_kernel<<<MM * DD / 4 / 256, 256>>>(X, Xb);
    wtrans_kernel<<<tgrid, tblk>>>(Wq, Wqt);
    wtrans_kernel<<<tgrid, tblk>>>(Wk, Wkt);
    wtrans_kernel<<<tgrid, tblk>>>(Wv, Wvt);
    wtrans_kernel<<<tgrid, tblk>>>(Wo, Wot);

    gemm_bf16<true><<<gemm_grid, 256, GEMM_SMEM>>>(Xb, Wqt, bq, nullptr, Qb);
    gemm_bf16<true><<<gemm_grid, 256, GEMM_SMEM>>>(Xb, Wkt, bk, nullptr, Kb);
    gemm_bf16<true><<<gemm_grid, 256, GEMM_SMEM>>>(Xb, Wvt, bv, nullptr, Vb);

    attn_bf16<<<dim3(LL / 128, BB * HH), 256, ATT_SMEM>>>(Qb, Kb, Vb, Ob);

    gemm_bf16<false><<<gemm_grid, 256, GEMM_SMEM>>>(Ob, Wot, bo, X, Rp);

    ln_kernel<<<MM, 256>>>(Rp, gamma, beta, out);
}

// round 10
// speedup vs baseline: 4.3479x; 1.0446x over previous
#include <cuda_runtime.h>
#include <cuda_bf16.h>
#include <math.h>
#include <stdint.h>

// Problem dims
#define BB 4
#define LL 2048
#define DD 1024
#define HH 16
#define HD 64
#define MM (BB * LL)   // 8192

// ------------------------- scratch (static device globals) -------------------
__device__ __nv_bfloat16 g_Xb[MM * DD];
__device__ __nv_bfloat16 g_Qb[MM * DD];
__device__ __nv_bfloat16 g_Kb[MM * DD];
__device__ __nv_bfloat16 g_Vb[MM * DD];
__device__ __nv_bfloat16 g_Ob[MM * DD];
__device__ __nv_bfloat16 g_Wqt[DD * DD];
__device__ __nv_bfloat16 g_Wkt[DD * DD];
__device__ __nv_bfloat16 g_Wvt[DD * DD];
__device__ __nv_bfloat16 g_Wot[DD * DD];
__device__ float g_R[MM * DD];

// ========================= helpers ==========================================
__device__ __forceinline__ uint32_t smem_u32(const void* p) {
    uint32_t a;
    asm("{ .reg .u64 t; cvta.to.shared.u64 t, %1; cvt.u32.u64 %0, t; }"
        : "=r"(a) : "l"(p));
    return a;
}
#define CP_ASYNC16(dst, src) \
    asm volatile("cp.async.ca.shared.global [%0], [%1], 16;" :: "r"(dst), "l"(src))
#define CP_COMMIT() asm volatile("cp.async.commit_group;")
#define CP_WAIT1()  asm volatile("cp.async.wait_group 1;")

__device__ __forceinline__ uint32_t pack_bf16(float lo, float hi) {
    uint32_t r;
    asm("cvt.rn.bf16x2.f32 %0, %1, %2;" : "=r"(r) : "f"(hi), "f"(lo));
    return r;
}
__device__ __forceinline__ void ldsm4(uint32_t* r, uint32_t addr) {
    asm volatile("ldmatrix.sync.aligned.m8n8.x4.shared.b16 {%0,%1,%2,%3}, [%4];"
                 : "=r"(r[0]), "=r"(r[1]), "=r"(r[2]), "=r"(r[3]) : "r"(addr));
}
__device__ __forceinline__ void mma_bf16(float* c, const uint32_t* a, const uint32_t* b) {
    asm volatile(
        "mma.sync.aligned.m16n8k16.row.col.f32.bf16.bf16.f32 "
        "{%0,%1,%2,%3}, {%4,%5,%6,%7}, {%8,%9}, {%0,%1,%2,%3};"
        : "+f"(c[0]), "+f"(c[1]), "+f"(c[2]), "+f"(c[3])
        : "r"(a[0]), "r"(a[1]), "r"(a[2]), "r"(a[3]), "r"(b[0]), "r"(b[1]));
}

// ========================= fp32 -> bf16 convert =============================
__global__ __launch_bounds__(256) void cvt_kernel(const float* __restrict__ X,
                                                  __nv_bfloat16* __restrict__ Y)
{
    const int i = blockIdx.x * 256 + threadIdx.x;
    float4 v = ((const float4*)X)[i];
    uint2 o;
    o.x = pack_bf16(v.x, v.y);
    o.y = pack_bf16(v.z, v.w);
    ((uint2*)Y)[i] = o;
}

// ======== weight transpose+convert: W[K][N] f32 -> Wt[N][K] bf16 ============
__global__ __launch_bounds__(256) void wtrans_kernel(const float* __restrict__ W,
                                                     __nv_bfloat16* __restrict__ Wt)
{
    __shared__ float tile[32][33];
    const int n0 = blockIdx.x * 32, k0 = blockIdx.y * 32;
    const int tx = threadIdx.x, ty = threadIdx.y;   // 32 x 8
#pragma unroll
    for (int i = 0; i < 32; i += 8)
        tile[ty + i][tx] = W[(size_t)(k0 + ty + i) * DD + n0 + tx];
    __syncthreads();
#pragma unroll
    for (int i = 0; i < 32; i += 8)
        Wt[(size_t)(n0 + ty + i) * DD + k0 + tx] = __float2bfloat16(tile[tx][ty + i]);
}

// ========================= bf16 mma GEMM (3-stage cp.async, ldmatrix) ========
// C[M,N] = A[M,K]_bf16 @ Wt[N,K]_bf16^T + bias (+ R). CTA 128x128, BK=32, 8 warps.
#define GW 20                          // words per smem row (32 bf16 + pad)
#define GTILEW (128 * GW)              // 2560 words per tile
#define GEMM_SMEM (3 * 2 * GTILEW * 4) // 61440 B

template <bool OUT_BF16>
__global__ __launch_bounds__(256)
void gemm_bf16(const __nv_bfloat16* __restrict__ A, const __nv_bfloat16* __restrict__ Bt,
               const float* __restrict__ bias, const float* __restrict__ R,
               void* __restrict__ Cout)
{
    extern __shared__ uint32_t sm[];
    const uint32_t sbase = smem_u32(sm);

    const int tid = threadIdx.x;
    const int wid = tid >> 5, lane = tid & 31;
    const int g = lane >> 2, t = lane & 3;
    const int lr = lane & 15, lc = lane >> 4;
    const int wm = wid >> 2, wn = wid & 3;
    const int bx = blockIdx.x, by = blockIdx.y;

    const __nv_bfloat16* Ab = A  + (size_t)(by * 128) * DD;
    const __nv_bfloat16* Bb = Bt + (size_t)(bx * 128) * DD;

    const int L_row = tid >> 2;             // 0..63
    const int L_ch  = (tid & 3) * 16;       // byte offset in row
    const int L_el  = (tid & 3) * 8;        // element offset

#define GEMM_ISSUE(kb, st) do {                                                  \
    const uint32_t ao_ = sbase + (uint32_t)(st) * 2 * GTILEW * 4;                \
    const uint32_t bo_ = ao_ + GTILEW * 4;                                       \
    _Pragma("unroll")                                                            \
    for (int i_ = 0; i_ < 2; i_++) {                                             \
        const int row_ = L_row + i_ * 64;                                        \
        CP_ASYNC16(ao_ + (uint32_t)(row_ * 80) + L_ch,                           \
                   Ab + (size_t)row_ * DD + (kb) * 32 + L_el);                   \
        CP_ASYNC16(bo_ + (uint32_t)(row_ * 80) + L_ch,                           \
                   Bb + (size_t)row_ * DD + (kb) * 32 + L_el);                   \
    }                                                                            \
} while (0)

    GEMM_ISSUE(0, 0); CP_COMMIT();
    GEMM_ISSUE(1, 1); CP_COMMIT();

    float acc[4][4][4];
#pragma unroll
    for (int mt = 0; mt < 4; mt++)
#pragma unroll
        for (int nt = 0; nt < 4; nt++)
#pragma unroll
            for (int j = 0; j < 4; j++) acc[mt][nt][j] = 0.f;

    const int NKT = DD / 32;
    for (int kb = 0; kb < NKT; kb++) {
        CP_WAIT1();
        __syncthreads();
        const int st = kb % 3;
        const uint32_t abase = sbase + (uint32_t)st * 2 * GTILEW * 4;
        const uint32_t bbase = abase + GTILEW * 4;
#pragma unroll
        for (int ks = 0; ks < 2; ks++) {
            uint32_t af[4][4], bq[2][4];
#pragma unroll
            for (int mt = 0; mt < 4; mt++)
                ldsm4(af[mt], abase +
                      (uint32_t)(((wm * 64 + mt * 16 + lr) * GW + ks * 8 + lc * 4) * 4));
#pragma unroll
            for (int p = 0; p < 2; p++)
                ldsm4(bq[p], bbase +
                      (uint32_t)(((wn * 32 + p * 16 + lr) * GW + ks * 8 + lc * 4) * 4));
            uint32_t bf[4][2] = {
                { bq[0][0], bq[0][2] }, { bq[0][1], bq[0][3] },
                { bq[1][0], bq[1][2] }, { bq[1][1], bq[1][3] } };
#pragma unroll
            for (int mt = 0; mt < 4; mt++)
#pragma unroll
                for (int nt = 0; nt < 4; nt++)
                    mma_bf16(acc[mt][nt], af[mt], bf[nt]);
        }
        __syncthreads();
        if (kb + 2 < NKT) GEMM_ISSUE(kb + 2, (kb + 2) % 3);
        CP_COMMIT();
    }
#undef GEMM_ISSUE

    // ---- epilogue ----
#pragma unroll
    for (int nt = 0; nt < 4; nt++) {
        const int col = bx * 128 + wn * 32 + nt * 8 + 2 * t;
        const float b0 = bias[col], b1 = bias[col + 1];
#pragma unroll
        for (int mt = 0; mt < 4; mt++) {
            const int row = by * 128 + wm * 64 + mt * 16 + g;
            const size_t o0 = (size_t)row * DD + col;
            const size_t o1 = (size_t)(row + 8) * DD + col;
            float v00 = acc[mt][nt][0] + b0, v01 = acc[mt][nt][1] + b1;
            float v10 = acc[mt][nt][2] + b0, v11 = acc[mt][nt][3] + b1;
            if (OUT_BF16) {
                *(uint32_t*)((__nv_bfloat16*)Cout + o0) = pack_bf16(v00, v01);
                *(uint32_t*)((__nv_bfloat16*)Cout + o1) = pack_bf16(v10, v11);
            } else {
                float* C = (float*)Cout;
                if (R) {
                    float2 r0 = *(const float2*)(R + o0);
                    float2 r1 = *(const float2*)(R + o1);
                    v00 += r0.x; v01 += r0.y; v10 += r1.x; v11 += r1.y;
                }
                *(float2*)(C + o0) = make_float2(v00, v01);
                *(float2*)(C + o1) = make_float2(v10, v11);
            }
        }
    }
}

// ========================= bf16 flash attention (ldmatrix frags) =============
#define AW 36                                   // word stride (72 bf16, 144 B)
#define QW_OFF 0
#define KW_OFF (128 * AW)                       // Q: 128 rows
#define VW_OFF (KW_OFF + 2 * 64 * AW)           // K: 2 bufs x 64 rows
#define ATT_WORDS (VW_OFF + 2 * 64 * AW)        // V: 2 bufs x 64 rows -> 13824 w
#define ATT_SMEM (ATT_WORDS * 4)                // 55296 B

__global__ __launch_bounds__(256, 2)
void attn_bf16(const __nv_bfloat16* __restrict__ Q, const __nv_bfloat16* __restrict__ K,
               const __nv_bfloat16* __restrict__ V, __nv_bfloat16* __restrict__ O)
{
    extern __shared__ uint32_t sm[];
    const uint32_t sbase = smem_u32(sm);
    const uint32_t qaddr = sbase + QW_OFF * 4;
    const uint32_t kaddr = sbase + KW_OFF * 4;
    const uint32_t vaddr = sbase + VW_OFF * 4;

    const int tid = threadIdx.x;
    const int wid = tid >> 5, lane = tid & 31;
    const int g = lane >> 2, t = lane & 3;
    const int lr = lane & 15, lc = lane >> 4;
    const int m0 = wid * 16;

    const int bh = blockIdx.y;
    const int b = bh >> 4, h = bh & 15;
    const int q0 = blockIdx.x * 128;
    const size_t base = (size_t)b * LL * DD + (size_t)h * HD;

    const int vkey = tid & 63;
    const int vw0 = (tid >> 6) * 8;

    // ---- prologue: Q + K0 cp.async (group 0), V0 LDG ----
    {
#pragma unroll
        for (int i = 0; i < 4; i++) {
            const int c = tid + i * 256;
            const int row = c >> 3, ch = (c & 7) * 16, el = (c & 7) * 8;
            CP_ASYNC16(qaddr + (uint32_t)(row * 144) + ch,
                       Q + base + (size_t)(q0 + row) * DD + el);
        }
#pragma unroll
        for (int i = 0; i < 2; i++) {
            const int c = tid + i * 256;
            const int row = c >> 3, ch = (c & 7) * 16, el = (c & 7) * 8;
            CP_ASYNC16(kaddr + (uint32_t)(row * 144) + ch,
                       K + base + (size_t)row * DD + el);
        }
        CP_COMMIT();
    }
    uint32_t vreg[8];
    {
        const uint32_t* vg = (const uint32_t*)(V + base + (size_t)vkey * DD) + vw0;
#pragma unroll
        for (int j = 0; j < 8; j++) vreg[j] = vg[j];
    }

    float oacc[8][4];
    float mrow[2] = { -1e30f, -1e30f };
    float lrow[2] = { 0.f, 0.f };
#pragma unroll
    for (int nt = 0; nt < 8; nt++)
#pragma unroll
        for (int j = 0; j < 4; j++) oacc[nt][j] = 0.f;

    const int NBLK = LL / 64;
    for (int i = 0; i < NBLK; i++) {
        const int buf = i & 1;
        // STS-transpose this block's V registers into Vt[buf]
        {
            unsigned short* Vt16 = (unsigned short*)(sm + VW_OFF + buf * 64 * AW);
#pragma unroll
            for (int j = 0; j < 8; j++) {
                const int d2 = (vw0 + j) * 2;
                Vt16[(d2    ) * 72 + vkey] = (unsigned short)(vreg[j] & 0xffffu);
                Vt16[(d2 + 1) * 72 + vkey] = (unsigned short)(vreg[j] >> 16);
            }
        }
        // prefetch next block: K via cp.async, V via LDG
        if (i + 1 < NBLK) {
            const uint32_t ko = kaddr + (uint32_t)((buf ^ 1) * 64 * AW * 4);
#pragma unroll
            for (int ii = 0; ii < 2; ii++) {
                const int c = tid + ii * 256;
                const int row = c >> 3, ch = (c & 7) * 16, el = (c & 7) * 8;
                CP_ASYNC16(ko + (uint32_t)(row * 144) + ch,
                           K + base + (size_t)((i + 1) * 64 + row) * DD + el);
            }
        }
        CP_COMMIT();
        if (i + 1 < NBLK) {
            const uint32_t* vg =
                (const uint32_t*)(V + base + (size_t)((i + 1) * 64 + vkey) * DD) + vw0;
#pragma unroll
            for (int j = 0; j < 8; j++) vreg[j] = vg[j];
        }
        CP_WAIT1();
        __syncthreads();

        const uint32_t kbuf = kaddr + (uint32_t)(buf * 64 * AW * 4);
        const uint32_t vbuf = vaddr + (uint32_t)(buf * 64 * AW * 4);

        // ---- S = Q @ K^T (ldmatrix frags, verified mapping) ----
        float sacc[8][4];
#pragma unroll
        for (int nt = 0; nt < 8; nt++)
#pragma unroll
            for (int j = 0; j < 4; j++) sacc[nt][j] = 0.f;

#pragma unroll
        for (int ks = 0; ks < 4; ks++) {
            uint32_t aq[4];
            ldsm4(aq, qaddr + (uint32_t)(((m0 + lr) * AW + ks * 8 + lc * 4) * 4));
#pragma unroll
            for (int p = 0; p < 4; p++) {
                uint32_t bq[4];
                ldsm4(bq, kbuf + (uint32_t)(((p * 16 + lr) * AW + ks * 8 + lc * 4) * 4));
                uint32_t b0[2] = { bq[0], bq[2] };
                uint32_t b1[2] = { bq[1], bq[3] };
                mma_bf16(sacc[p * 2 + 0], aq, b0);
                mma_bf16(sacc[p * 2 + 1], aq, b1);
            }
        }

        // ---- online softmax (scale 0.125 folded into exp) ----
#pragma unroll
        for (int r = 0; r < 2; r++) {
            const int j0 = r * 2;
            float mx = -1e30f;
#pragma unroll
            for (int nt = 0; nt < 8; nt++)
                mx = fmaxf(mx, fmaxf(sacc[nt][j0], sacc[nt][j0 + 1]));
            mx = fmaxf(mx, __shfl_xor_sync(0xffffffffu, mx, 1));
            mx = fmaxf(mx, __shfl_xor_sync(0xffffffffu, mx, 2));
            const float mnew = fmaxf(mrow[r], mx);
            const float alpha = __expf((mrow[r] - mnew) * 0.125f);
            mrow[r] = mnew;
            float rs = 0.f;
#pragma unroll
            for (int nt = 0; nt < 8; nt++) {
                sacc[nt][j0]     = __expf((sacc[nt][j0]     - mnew) * 0.125f);
                sacc[nt][j0 + 1] = __expf((sacc[nt][j0 + 1] - mnew) * 0.125f);
                rs += sacc[nt][j0] + sacc[nt][j0 + 1];
            }
            rs += __shfl_xor_sync(0xffffffffu, rs, 1);
            rs += __shfl_xor_sync(0xffffffffu, rs, 2);
            lrow[r] = lrow[r] * alpha + rs;
#pragma unroll
            for (int nt = 0; nt < 8; nt++) {
                oacc[nt][j0]     *= alpha;
                oacc[nt][j0 + 1] *= alpha;
            }
        }

        // ---- O += P @ V (P from sacc registers; V frags via ldmatrix) ----
#pragma unroll
        for (int j = 0; j < 4; j++) {
            uint32_t ap[4];
            ap[0] = pack_bf16(sacc[2 * j][0],     sacc[2 * j][1]);
            ap[1] = pack_bf16(sacc[2 * j][2],     sacc[2 * j][3]);
            ap[2] = pack_bf16(sacc[2 * j + 1][0], sacc[2 * j + 1][1]);
            ap[3] = pack_bf16(sacc[2 * j + 1][2], sacc[2 * j + 1][3]);
#pragma unroll
            for (int p = 0; p < 4; p++) {
                uint32_t bq[4];
                ldsm4(bq, vbuf + (uint32_t)(((p * 16 + lr) * AW + j * 8 + lc * 4) * 4));
                uint32_t b0[2] = { bq[0], bq[2] };
                uint32_t b1[2] = { bq[1], bq[3] };
                mma_bf16(oacc[p * 2 + 0], ap, b0);
                mma_bf16(oacc[p * 2 + 1], ap, b1);
            }
        }
        __syncthreads();
    }

    // ---- normalize + store (bf16) ----
    const float inv0 = 1.f / lrow[0];
    const float inv1 = 1.f / lrow[1];
#pragma unroll
    for (int nt = 0; nt < 8; nt++) {
        const int col = nt * 8 + 2 * t;
        const size_t o0 = base + (size_t)(q0 + m0 + g    ) * DD + col;
        const size_t o1 = base + (size_t)(q0 + m0 + g + 8) * DD + col;
        *(uint32_t*)(O + o0) = pack_bf16(oacc[nt][0] * inv0, oacc[nt][1] * inv0);
        *(uint32_t*)(O + o1) = pack_bf16(oacc[nt][2] * inv1, oacc[nt][3] * inv1);
    }
}

// ------------------------- LayerNorm -----------------------------------------
__global__ __launch_bounds__(256) void ln_kernel(
    const float* __restrict__ X, const float* __restrict__ gamma,
    const float* __restrict__ beta, float* __restrict__ out)
{
    __shared__ float ssum[8], ssq[8];
    const int row = blockIdx.x;
    const int tid = threadIdx.x;
    const float* x = X + (size_t)row * DD;

    float4 v = *(const float4*)(x + tid * 4);
    float s = v.x + v.y + v.z + v.w;
    float q = v.x * v.x + v.y * v.y + v.z * v.z + v.w * v.w;
#pragma unroll
    for (int off = 16; off > 0; off >>= 1) {
        s += __shfl_xor_sync(0xffffffffu, s, off);
        q += __shfl_xor_sync(0xffffffffu, q, off);
    }
    if ((tid & 31) == 0) { ssum[tid >> 5] = s; ssq[tid >> 5] = q; }
    __syncthreads();
    float ts = 0.f, tq = 0.f;
#pragma unroll
    for (int i = 0; i < 8; i++) { ts += ssum[i]; tq += ssq[i]; }

    const float mean = ts * (1.f / DD);
    const float var = tq * (1.f / DD) - mean * mean;
    const float inv = rsqrtf(var + 1e-5f);

    float4 gmv = *(const float4*)(gamma + tid * 4);
    float4 btv = *(const float4*)(beta + tid * 4);
    float4 o4;
    o4.x = (v.x - mean) * inv * gmv.x + btv.x;
    o4.y = (v.y - mean) * inv * gmv.y + btv.y;
    o4.z = (v.z - mean) * inv * gmv.z + btv.z;
    o4.w = (v.w - mean) * inv * gmv.w + btv.w;
    *(float4*)(out + (size_t)row * DD + tid * 4) = o4;
}

// ------------------------- launch --------------------------------------------
extern "C" void kernel_launch(void* const* d_in, const int* in_sizes, int n_in,
                              void* d_out, int out_size)
{
    const float* X     = (const float*)d_in[0];
    const float* Wq    = (const float*)d_in[1];
    const float* bq    = (const float*)d_in[2];
    const float* Wk    = (const float*)d_in[3];
    const float* bk    = (const float*)d_in[4];
    const float* Wv    = (const float*)d_in[5];
    const float* bv    = (const float*)d_in[6];
    const float* Wo    = (const float*)d_in[7];
    const float* bo    = (const float*)d_in[8];
    const float* gamma = (const float*)d_in[9];
    const float* beta  = (const float*)d_in[10];
    float* out = (float*)d_out;

    __nv_bfloat16 *Xb, *Qb, *Kb, *Vb, *Ob, *Wqt, *Wkt, *Wvt, *Wot;
    float* Rp;
    cudaGetSymbolAddress((void**)&Xb, g_Xb);
    cudaGetSymbolAddress((void**)&Qb, g_Qb);
    cudaGetSymbolAddress((void**)&Kb, g_Kb);
    cudaGetSymbolAddress((void**)&Vb, g_Vb);
    cudaGetSymbolAddress((void**)&Ob, g_Ob);
    cudaGetSymbolAddress((void**)&Wqt, g_Wqt);
    cudaGetSymbolAddress((void**)&Wkt, g_Wkt);
    cudaGetSymbolAddress((void**)&Wvt, g_Wvt);
    cudaGetSymbolAddress((void**)&Wot, g_Wot);
    cudaGetSymbolAddress((void**)&Rp, g_R);

    cudaFuncSetAttribute(gemm_bf16<true>,
                         cudaFuncAttributeMaxDynamicSharedMemorySize, GEMM_SMEM);
    cudaFuncSetAttribute(gemm_bf16<false>,
                         cudaFuncAttributeMaxDynamicSharedMemorySize, GEMM_SMEM);
    cudaFuncSetAttribute(attn_bf16,
                         cudaFuncAttributeMaxDynamicSharedMemorySize, ATT_SMEM);

    dim3 gemm_grid(DD / 128, MM / 128);   // (8, 64)
    dim3 tgrid(DD / 32, DD / 32);
    dim3 tblk(32, 8);

    cvt_kernel<<<MM * DD / 4 / 256, 256>>>(X, Xb);
    wtrans_kernel<<<tgrid, tblk>>>(Wq, Wqt);
    wtrans_kernel<<<tgrid, tblk>>>(Wk, Wkt);
    wtrans_kernel<<<tgrid, tblk>>>(Wv, Wvt);
    wtrans_kernel<<<tgrid, tblk>>>(Wo, Wot);

    gemm_bf16<true><<<gemm_grid, 256, GEMM_SMEM>>>(Xb, Wqt, bq, nullptr, Qb);
    gemm_bf16<true><<<gemm_grid, 256, GEMM_SMEM>>>(Xb, Wkt, bk, nullptr, Kb);
    gemm_bf16<true><<<gemm_grid, 256, GEMM_SMEM>>>(Xb, Wvt, bv, nullptr, Vb);

    attn_bf16<<<dim3(LL / 128, BB * HH), 256, ATT_SMEM>>>(Qb, Kb, Vb, Ob);

    gemm_bf16<false><<<gemm_grid, 256, GEMM_SMEM>>>(Ob, Wot, bo, X, Rp);

    ln_kernel<<<MM, 256>>>(Rp, gamma, beta, out);
}

// round 13
// speedup vs baseline: 4.4655x; 1.0271x over previous
#include <cuda_runtime.h>
#include <cuda_bf16.h>
#include <math.h>
#include <stdint.h>

// Problem dims
#define BB 4
#define LL 2048
#define DD 1024
#define HH 16
#define HD 64
#define MM (BB * LL)   // 8192

// ------------------------- scratch (static device globals) -------------------
__device__ __nv_bfloat16 g_Xb[MM * DD];
__device__ __nv_bfloat16 g_Qb[MM * DD];
__device__ __nv_bfloat16 g_Kb[MM * DD];
__device__ __nv_bfloat16 g_Vb[MM * DD];
__device__ __nv_bfloat16 g_Ob[MM * DD];
__device__ __nv_bfloat16 g_Wqkvt[3 * DD * DD];   // [Q|K|V] transposed bf16
__device__ __nv_bfloat16 g_Wot[DD * DD];
__device__ float g_R[MM * DD];

// ========================= helpers ==========================================
__device__ __forceinline__ uint32_t smem_u32(const void* p) {
    uint32_t a;
    asm("{ .reg .u64 t; cvta.to.shared.u64 t, %1; cvt.u32.u64 %0, t; }"
        : "=r"(a) : "l"(p));
    return a;
}
#define CP_ASYNC16(dst, src) \
    asm volatile("cp.async.ca.shared.global [%0], [%1], 16;" :: "r"(dst), "l"(src))
#define CP_COMMIT() asm volatile("cp.async.commit_group;")
#define CP_WAIT1()  asm volatile("cp.async.wait_group 1;")

__device__ __forceinline__ uint32_t pack_bf16(float lo, float hi) {
    uint32_t r;
    asm("cvt.rn.bf16x2.f32 %0, %1, %2;" : "=r"(r) : "f"(hi), "f"(lo));
    return r;
}
__device__ __forceinline__ float ex2(float x) {
    float y;
    asm("ex2.approx.f32 %0, %1;" : "=f"(y) : "f"(x));
    return y;
}
__device__ __forceinline__ void ldsm4(uint32_t* r, uint32_t addr) {
    asm volatile("ldmatrix.sync.aligned.m8n8.x4.shared.b16 {%0,%1,%2,%3}, [%4];"
                 : "=r"(r[0]), "=r"(r[1]), "=r"(r[2]), "=r"(r[3]) : "r"(addr));
}
__device__ __forceinline__ void mma_bf16(float* c, const uint32_t* a, const uint32_t* b) {
    asm volatile(
        "mma.sync.aligned.m16n8k16.row.col.f32.bf16.bf16.f32 "
        "{%0,%1,%2,%3}, {%4,%5,%6,%7}, {%8,%9}, {%0,%1,%2,%3};"
        : "+f"(c[0]), "+f"(c[1]), "+f"(c[2]), "+f"(c[3])
        : "r"(a[0]), "r"(a[1]), "r"(a[2]), "r"(a[3]), "r"(b[0]), "r"(b[1]));
}

// ========================= fp32 -> bf16 convert =============================
__global__ __launch_bounds__(256) void cvt_kernel(const float* __restrict__ X,
                                                  __nv_bfloat16* __restrict__ Y)
{
    const int i = blockIdx.x * 256 + threadIdx.x;
    float4 v = ((const float4*)X)[i];
    uint2 o;
    o.x = pack_bf16(v.x, v.y);
    o.y = pack_bf16(v.z, v.w);
    ((uint2*)Y)[i] = o;
}

// ======== weight transpose+convert: W[K][N] f32 -> Wt[N][K] bf16 ============
__global__ __launch_bounds__(256) void wtrans_kernel(const float* __restrict__ W,
                                                     __nv_bfloat16* __restrict__ Wt)
{
    __shared__ float tile[32][33];
    const int n0 = blockIdx.x * 32, k0 = blockIdx.y * 32;
    const int tx = threadIdx.x, ty = threadIdx.y;   // 32 x 8
#pragma unroll
    for (int i = 0; i < 32; i += 8)
        tile[ty + i][tx] = W[(size_t)(k0 + ty + i) * DD + n0 + tx];
    __syncthreads();
#pragma unroll
    for (int i = 0; i < 32; i += 8)
        Wt[(size_t)(n0 + ty + i) * DD + k0 + tx] = __float2bfloat16(tile[tx][ty + i]);
}

// ========================= GEMM common pieces (R10-proven pipeline) ==========
#define GW 20                          // words per smem row (32 bf16 + pad)
#define GTILEW (128 * GW)              // 2560 words per tile
#define GEMM_SMEM (3 * 2 * GTILEW * 4) // 61440 B

#define GEMM_ISSUE(kb, st) do {                                                  \
    const uint32_t ao_ = sbase + (uint32_t)(st) * 2 * GTILEW * 4;                \
    const uint32_t bo_ = ao_ + GTILEW * 4;                                       \
    _Pragma("unroll")                                                            \
    for (int i_ = 0; i_ < 2; i_++) {                                             \
        const int row_ = L_row + i_ * 64;                                        \
        CP_ASYNC16(ao_ + (uint32_t)(row_ * 80) + L_ch,                           \
                   Ab + (size_t)row_ * DD + (kb) * 32 + L_el);                   \
        CP_ASYNC16(bo_ + (uint32_t)(row_ * 80) + L_ch,                           \
                   Bb + (size_t)row_ * DD + (kb) * 32 + L_el);                   \
    }                                                                            \
} while (0)

// R10-proven mainloop: wait1 / sync / compute / sync / issue+commit.
#define GEMM_MAINLOOP()                                                          \
    GEMM_ISSUE(0, 0); CP_COMMIT();                                               \
    GEMM_ISSUE(1, 1); CP_COMMIT();                                               \
    float acc[4][4][4];                                                          \
    _Pragma("unroll")                                                            \
    for (int mt = 0; mt < 4; mt++)                                               \
        _Pragma("unroll")                                                        \
        for (int nt = 0; nt < 4; nt++)                                           \
            _Pragma("unroll")                                                    \
            for (int j = 0; j < 4; j++) acc[mt][nt][j] = 0.f;                    \
    const int NKT = DD / 32;                                                     \
    for (int kb = 0; kb < NKT; kb++) {                                           \
        CP_WAIT1();                                                              \
        __syncthreads();                                                         \
        const int st = kb % 3;                                                   \
        const uint32_t abase = sbase + (uint32_t)st * 2 * GTILEW * 4;            \
        const uint32_t bbase = abase + GTILEW * 4;                               \
        _Pragma("unroll")                                                        \
        for (int ks = 0; ks < 2; ks++) {                                         \
            uint32_t af[4][4], bq[2][4];                                         \
            _Pragma("unroll")                                                    \
            for (int mt = 0; mt < 4; mt++)                                       \
                ldsm4(af[mt], abase +                                            \
                      (uint32_t)(((wm * 64 + mt * 16 + lr) * GW + ks * 8 + lc * 4) * 4)); \
            _Pragma("unroll")                                                    \
            for (int p = 0; p < 2; p++)                                          \
                ldsm4(bq[p], bbase +                                             \
                      (uint32_t)(((wn * 32 + p * 16 + lr) * GW + ks * 8 + lc * 4) * 4)); \
            uint32_t bf[4][2] = {                                                \
                { bq[0][0], bq[0][2] }, { bq[0][1], bq[0][3] },                  \
                { bq[1][0], bq[1][2] }, { bq[1][1], bq[1][3] } };                \
            _Pragma("unroll")                                                    \
            for (int mt = 0; mt < 4; mt++)                                       \
                _Pragma("unroll")                                                 \
                for (int nt = 0; nt < 4; nt++)                                   \
                    mma_bf16(acc[mt][nt], af[mt], bf[nt]);                       \
        }                                                                        \
        __syncthreads();                                                         \
        if (kb + 2 < NKT) GEMM_ISSUE(kb + 2, (kb + 2) % 3);                      \
        CP_COMMIT();                                                             \
    }

// ---------------- merged QKV GEMM: grid.x = 24 (3 weights x 8 n-blocks) ------
__global__ __launch_bounds__(256)
void gemm_qkv(const __nv_bfloat16* __restrict__ A,
              const __nv_bfloat16* __restrict__ Wqkvt,
              const float* __restrict__ bq, const float* __restrict__ bk,
              const float* __restrict__ bv,
              __nv_bfloat16* __restrict__ Qo, __nv_bfloat16* __restrict__ Ko,
              __nv_bfloat16* __restrict__ Vo)
{
    extern __shared__ uint32_t sm[];
    const uint32_t sbase = smem_u32(sm);

    const int tid = threadIdx.x;
    const int wid = tid >> 5, lane = tid & 31;
    const int g = lane >> 2, t = lane & 3;
    const int lr = lane & 15, lc = lane >> 4;
    const int wm = wid >> 2, wn = wid & 3;
    const int by = blockIdx.y;
    const int wsel = blockIdx.x >> 3;
    const int bx = blockIdx.x & 7;

    const float* bias = (wsel == 0) ? bq : (wsel == 1) ? bk : bv;
    __nv_bfloat16* Cout = (wsel == 0) ? Qo : (wsel == 1) ? Ko : Vo;

    const __nv_bfloat16* Ab = A + (size_t)(by * 128) * DD;
    const __nv_bfloat16* Bb = Wqkvt + (size_t)wsel * DD * DD + (size_t)(bx * 128) * DD;

    const int L_row = tid >> 2;
    const int L_ch  = (tid & 3) * 16;
    const int L_el  = (tid & 3) * 8;

    GEMM_MAINLOOP();

    // epilogue (bf16 out)
#pragma unroll
    for (int nt = 0; nt < 4; nt++) {
        const int col = bx * 128 + wn * 32 + nt * 8 + 2 * t;
        const float b0 = bias[col], b1 = bias[col + 1];
#pragma unroll
        for (int mt = 0; mt < 4; mt++) {
            const int row = by * 128 + wm * 64 + mt * 16 + g;
            const size_t o0 = (size_t)row * DD + col;
            const size_t o1 = (size_t)(row + 8) * DD + col;
            *(uint32_t*)(Cout + o0) = pack_bf16(acc[mt][nt][0] + b0, acc[mt][nt][1] + b1);
            *(uint32_t*)(Cout + o1) = pack_bf16(acc[mt][nt][2] + b0, acc[mt][nt][3] + b1);
        }
    }
}

// ---------------- out-projection GEMM (f32 out + residual) -------------------
__global__ __launch_bounds__(256)
void gemm_out(const __nv_bfloat16* __restrict__ A, const __nv_bfloat16* __restrict__ Bt,
              const float* __restrict__ bias, const float* __restrict__ R,
              float* __restrict__ C)
{
    extern __shared__ uint32_t sm[];
    const uint32_t sbase = smem_u32(sm);

    const int tid = threadIdx.x;
    const int wid = tid >> 5, lane = tid & 31;
    const int g = lane >> 2, t = lane & 3;
    const int lr = lane & 15, lc = lane >> 4;
    const int wm = wid >> 2, wn = wid & 3;
    const int bx = blockIdx.x, by = blockIdx.y;

    const __nv_bfloat16* Ab = A  + (size_t)(by * 128) * DD;
    const __nv_bfloat16* Bb = Bt + (size_t)(bx * 128) * DD;

    const int L_row = tid >> 2;
    const int L_ch  = (tid & 3) * 16;
    const int L_el  = (tid & 3) * 8;

    GEMM_MAINLOOP();

#pragma unroll
    for (int nt = 0; nt < 4; nt++) {
        const int col = bx * 128 + wn * 32 + nt * 8 + 2 * t;
        const float b0 = bias[col], b1 = bias[col + 1];
#pragma unroll
        for (int mt = 0; mt < 4; mt++) {
            const int row = by * 128 + wm * 64 + mt * 16 + g;
            const size_t o0 = (size_t)row * DD + col;
            const size_t o1 = (size_t)(row + 8) * DD + col;
            float2 r0 = *(const float2*)(R + o0);
            float2 r1 = *(const float2*)(R + o1);
            *(float2*)(C + o0) = make_float2(acc[mt][nt][0] + b0 + r0.x,
                                             acc[mt][nt][1] + b1 + r0.y);
            *(float2*)(C + o1) = make_float2(acc[mt][nt][2] + b0 + r1.x,
                                             acc[mt][nt][3] + b1 + r1.y);
        }
    }
}

// ========================= bf16 flash attention ==============================
// R10-proven pipeline structure (two syncs per block); exp2-form softmax.
#define AW 36                                   // word stride (72 bf16, 144 B)
#define QW_OFF 0
#define KW_OFF (128 * AW)
#define VW_OFF (KW_OFF + 2 * 64 * AW)
#define ATT_WORDS (VW_OFF + 2 * 64 * AW)
#define ATT_SMEM (ATT_WORDS * 4)                // 55296 B

__global__ __launch_bounds__(256, 2)
void attn_bf16(const __nv_bfloat16* __restrict__ Q, const __nv_bfloat16* __restrict__ K,
               const __nv_bfloat16* __restrict__ V, __nv_bfloat16* __restrict__ O)
{
    extern __shared__ uint32_t sm[];
    const uint32_t sbase = smem_u32(sm);
    const uint32_t qaddr = sbase + QW_OFF * 4;
    const uint32_t kaddr = sbase + KW_OFF * 4;
    const uint32_t vaddr = sbase + VW_OFF * 4;

    const int tid = threadIdx.x;
    const int wid = tid >> 5, lane = tid & 31;
    const int g = lane >> 2, t = lane & 3;
    const int lr = lane & 15, lc = lane >> 4;
    const int m0 = wid * 16;

    const int bh = blockIdx.y;
    const int b = bh >> 4, h = bh & 15;
    const int q0 = blockIdx.x * 128;
    const size_t base = (size_t)b * LL * DD + (size_t)h * HD;

    const int vkey = tid & 63;
    const int vw0 = (tid >> 6) * 8;

    // ---- prologue: Q + K0 cp.async (one group), V0 LDG ----
    {
#pragma unroll
        for (int i = 0; i < 4; i++) {
            const int c = tid + i * 256;
            const int row = c >> 3, ch = (c & 7) * 16, el = (c & 7) * 8;
            CP_ASYNC16(qaddr + (uint32_t)(row * 144) + ch,
                       Q + base + (size_t)(q0 + row) * DD + el);
        }
#pragma unroll
        for (int i = 0; i < 2; i++) {
            const int c = tid + i * 256;
            const int row = c >> 3, ch = (c & 7) * 16, el = (c & 7) * 8;
            CP_ASYNC16(kaddr + (uint32_t)(row * 144) + ch,
                       K + base + (size_t)row * DD + el);
        }
        CP_COMMIT();
    }
    uint32_t vreg[8];
    {
        const uint32_t* vg = (const uint32_t*)(V + base + (size_t)vkey * DD) + vw0;
#pragma unroll
        for (int j = 0; j < 8; j++) vreg[j] = vg[j];
    }

    float oacc[8][4];
    float mrow[2] = { -1e30f, -1e30f };
    float lrow[2] = { 0.f, 0.f };
#pragma unroll
    for (int nt = 0; nt < 8; nt++)
#pragma unroll
        for (int j = 0; j < 4; j++) oacc[nt][j] = 0.f;

    const float SC = 0.18033688011112042f;   // 0.125 * log2(e)
    const int NBLK = LL / 64;
    for (int i = 0; i < NBLK; i++) {
        const int buf = i & 1;
        // STS-transpose this block's V registers into Vt[buf]
        {
            unsigned short* Vt16 = (unsigned short*)(sm + VW_OFF + buf * 64 * AW);
#pragma unroll
            for (int j = 0; j < 8; j++) {
                const int d2 = (vw0 + j) * 2;
                Vt16[(d2    ) * 72 + vkey] = (unsigned short)(vreg[j] & 0xffffu);
                Vt16[(d2 + 1) * 72 + vkey] = (unsigned short)(vreg[j] >> 16);
            }
        }
        // prefetch next block: K via cp.async, V via LDG
        if (i + 1 < NBLK) {
            const uint32_t ko = kaddr + (uint32_t)((buf ^ 1) * 64 * AW * 4);
#pragma unroll
            for (int ii = 0; ii < 2; ii++) {
                const int c = tid + ii * 256;
                const int row = c >> 3, ch = (c & 7) * 16, el = (c & 7) * 8;
                CP_ASYNC16(ko + (uint32_t)(row * 144) + ch,
                           K + base + (size_t)((i + 1) * 64 + row) * DD + el);
            }
        }
        CP_COMMIT();
        if (i + 1 < NBLK) {
            const uint32_t* vg =
                (const uint32_t*)(V + base + (size_t)((i + 1) * 64 + vkey) * DD) + vw0;
#pragma unroll
            for (int j = 0; j < 8; j++) vreg[j] = vg[j];
        }
        CP_WAIT1();
        __syncthreads();

        const uint32_t kbuf = kaddr + (uint32_t)(buf * 64 * AW * 4);
        const uint32_t vbuf = vaddr + (uint32_t)(buf * 64 * AW * 4);

        // ---- S = Q @ K^T ----
        float sacc[8][4];
#pragma unroll
        for (int nt = 0; nt < 8; nt++)
#pragma unroll
            for (int j = 0; j < 4; j++) sacc[nt][j] = 0.f;

#pragma unroll
        for (int ks = 0; ks < 4; ks++) {
            uint32_t aq[4];
            ldsm4(aq, qaddr + (uint32_t)(((m0 + lr) * AW + ks * 8 + lc * 4) * 4));
#pragma unroll
            for (int p = 0; p < 4; p++) {
                uint32_t bq[4];
                ldsm4(bq, kbuf + (uint32_t)(((p * 16 + lr) * AW + ks * 8 + lc * 4) * 4));
                uint32_t b0[2] = { bq[0], bq[2] };
                uint32_t b1[2] = { bq[1], bq[3] };
                mma_bf16(sacc[p * 2 + 0], aq, b0);
                mma_bf16(sacc[p * 2 + 1], aq, b1);
            }
        }

        // ---- online softmax (exp2 form; scale folded into FFMA) ----
#pragma unroll
        for (int r = 0; r < 2; r++) {
            const int j0 = r * 2;
            float mx = -1e30f;
#pragma unroll
            for (int nt = 0; nt < 8; nt++)
                mx = fmaxf(mx, fmaxf(sacc[nt][j0], sacc[nt][j0 + 1]));
            mx = fmaxf(mx, __shfl_xor_sync(0xffffffffu, mx, 1));
            mx = fmaxf(mx, __shfl_xor_sync(0xffffffffu, mx, 2));
            const float mnew = fmaxf(mrow[r], mx);
            const float nmc = -mnew * SC;
            const float alpha = ex2(fmaf(mrow[r], SC, nmc));
            mrow[r] = mnew;
            float rs = 0.f;
#pragma unroll
            for (int nt = 0; nt < 8; nt++) {
                sacc[nt][j0]     = ex2(fmaf(sacc[nt][j0],     SC, nmc));
                sacc[nt][j0 + 1] = ex2(fmaf(sacc[nt][j0 + 1], SC, nmc));
                rs += sacc[nt][j0] + sacc[nt][j0 + 1];
            }
            rs += __shfl_xor_sync(0xffffffffu, rs, 1);
            rs += __shfl_xor_sync(0xffffffffu, rs, 2);
            lrow[r] = lrow[r] * alpha + rs;
#pragma unroll
            for (int nt = 0; nt < 8; nt++) {
                oacc[nt][j0]     *= alpha;
                oacc[nt][j0 + 1] *= alpha;
            }
        }

        // ---- O += P @ V (P from sacc registers; V frags via ldmatrix) ----
#pragma unroll
        for (int j = 0; j < 4; j++) {
            uint32_t ap[4];
            ap[0] = pack_bf16(sacc[2 * j][0],     sacc[2 * j][1]);
            ap[1] = pack_bf16(sacc[2 * j][2],     sacc[2 * j][3]);
            ap[2] = pack_bf16(sacc[2 * j + 1][0], sacc[2 * j + 1][1]);
            ap[3] = pack_bf16(sacc[2 * j + 1][2], sacc[2 * j + 1][3]);
#pragma unroll
            for (int p = 0; p < 4; p++) {
                uint32_t bq[4];
                ldsm4(bq, vbuf + (uint32_t)(((p * 16 + lr) * AW + j * 8 + lc * 4) * 4));
                uint32_t b0[2] = { bq[0], bq[2] };
                uint32_t b1[2] = { bq[1], bq[3] };
                mma_bf16(oacc[p * 2 + 0], ap, b0);
                mma_bf16(oacc[p * 2 + 1], ap, b1);
            }
        }
        __syncthreads();
    }

    // ---- normalize + store (bf16) ----
    const float inv0 = 1.f / lrow[0];
    const float inv1 = 1.f / lrow[1];
#pragma unroll
    for (int nt = 0; nt < 8; nt++) {
        const int col = nt * 8 + 2 * t;
        const size_t o0 = base + (size_t)(q0 + m0 + g    ) * DD + col;
        const size_t o1 = base + (size_t)(q0 + m0 + g + 8) * DD + col;
        *(uint32_t*)(O + o0) = pack_bf16(oacc[nt][0] * inv0, oacc[nt][1] * inv0);
        *(uint32_t*)(O + o1) = pack_bf16(oacc[nt][2] * inv1, oacc[nt][3] * inv1);
    }
}

// ------------------------- LayerNorm -----------------------------------------
__global__ __launch_bounds__(256) void ln_kernel(
    const float* __restrict__ X, const float* __restrict__ gamma,
    const float* __restrict__ beta, float* __restrict__ out)
{
    __shared__ float ssum[8], ssq[8];
    const int row = blockIdx.x;
    const int tid = threadIdx.x;
    const float* x = X + (size_t)row * DD;

    float4 v = *(const float4*)(x + tid * 4);
    float s = v.x + v.y + v.z + v.w;
    float q = v.x * v.x + v.y * v.y + v.z * v.z + v.w * v.w;
#pragma unroll
    for (int off = 16; off > 0; off >>= 1) {
        s += __shfl_xor_sync(0xffffffffu, s, off);
        q += __shfl_xor_sync(0xffffffffu, q, off);
    }
    if ((tid & 31) == 0) { ssum[tid >> 5] = s; ssq[tid >> 5] = q; }
    __syncthreads();
    float ts = 0.f, tq = 0.f;
#pragma unroll
    for (int i = 0; i < 8; i++) { ts += ssum[i]; tq += ssq[i]; }

    const float mean = ts * (1.f / DD);
    const float var = tq * (1.f / DD) - mean * mean;
    const float inv = rsqrtf(var + 1e-5f);

    float4 gmv = *(const float4*)(gamma + tid * 4);
    float4 btv = *(const float4*)(beta + tid * 4);
    float4 o4;
    o4.x = (v.x - mean) * inv * gmv.x + btv.x;
    o4.y = (v.y - mean) * inv * gmv.y + btv.y;
    o4.z = (v.z - mean) * inv * gmv.z + btv.z;
    o4.w = (v.w - mean) * inv * gmv.w + btv.w;
    *(float4*)(out + (size_t)row * DD + tid * 4) = o4;
}

// ------------------------- launch --------------------------------------------
extern "C" void kernel_launch(void* const* d_in, const int* in_sizes, int n_in,
                              void* d_out, int out_size)
{
    const float* X     = (const float*)d_in[0];
    const float* Wq    = (const float*)d_in[1];
    const float* bq    = (const float*)d_in[2];
    const float* Wk    = (const float*)d_in[3];
    const float* bk    = (const float*)d_in[4];
    const float* Wv    = (const float*)d_in[5];
    const float* bv    = (const float*)d_in[6];
    const float* Wo    = (const float*)d_in[7];
    const float* bo    = (const float*)d_in[8];
    const float* gamma = (const float*)d_in[9];
    const float* beta  = (const float*)d_in[10];
    float* out = (float*)d_out;

    __nv_bfloat16 *Xb, *Qb, *Kb, *Vb, *Ob, *Wqkvt, *Wot;
    float* Rp;
    cudaGetSymbolAddress((void**)&Xb, g_Xb);
    cudaGetSymbolAddress((void**)&Qb, g_Qb);
    cudaGetSymbolAddress((void**)&Kb, g_Kb);
    cudaGetSymbolAddress((void**)&Vb, g_Vb);
    cudaGetSymbolAddress((void**)&Ob, g_Ob);
    cudaGetSymbolAddress((void**)&Wqkvt, g_Wqkvt);
    cudaGetSymbolAddress((void**)&Wot, g_Wot);
    cudaGetSymbolAddress((void**)&Rp, g_R);

    cudaFuncSetAttribute(gemm_qkv,
                         cudaFuncAttributeMaxDynamicSharedMemorySize, GEMM_SMEM);
    cudaFuncSetAttribute(gemm_out,
                         cudaFuncAttributeMaxDynamicSharedMemorySize, GEMM_SMEM);
    cudaFuncSetAttribute(attn_bf16,
                         cudaFuncAttributeMaxDynamicSharedMemorySize, ATT_SMEM);

    dim3 tgrid(DD / 32, DD / 32);
    dim3 tblk(32, 8);

    cvt_kernel<<<MM * DD / 4 / 256, 256>>>(X, Xb);
    wtrans_kernel<<<tgrid, tblk>>>(Wq, Wqkvt);
    wtrans_kernel<<<tgrid, tblk>>>(Wk, Wqkvt + (size_t)DD * DD);
    wtrans_kernel<<<tgrid, tblk>>>(Wv, Wqkvt + (size_t)2 * DD * DD);
    wtrans_kernel<<<tgrid, tblk>>>(Wo, Wot);

    gemm_qkv<<<dim3(24, MM / 128), 256, GEMM_SMEM>>>(Xb, Wqkvt, bq, bk, bv,
                                                     Qb, Kb, Vb);

    attn_bf16<<<dim3(LL / 128, BB * HH), 256, ATT_SMEM>>>(Qb, Kb, Vb, Ob);

    gemm_out<<<dim3(DD / 128, MM / 128), 256, GEMM_SMEM>>>(Ob, Wot, bo, X, Rp);

    ln_kernel<<<MM, 256>>>(Rp, gamma, beta, out);
}

// round 14
// speedup vs baseline: 4.5302x; 1.0145x over previous
#include <cuda_runtime.h>
#include <cuda_bf16.h>
#include <math.h>
#include <stdint.h>

// Problem dims
#define BB 4
#define LL 2048
#define DD 1024
#define HH 16
#define HD 64
#define MM (BB * LL)   // 8192

// ------------------------- scratch (static device globals) -------------------
__device__ __nv_bfloat16 g_Xb[MM * DD];
__device__ __nv_bfloat16 g_Qb[MM * DD];
__device__ __nv_bfloat16 g_Kb[MM * DD];
__device__ __nv_bfloat16 g_Vb[MM * DD];
__device__ __nv_bfloat16 g_Ob[MM * DD];
__device__ __nv_bfloat16 g_Wqkvt[3 * DD * DD];   // [Q|K|V] transposed bf16
__device__ __nv_bfloat16 g_Wot[DD * DD];
__device__ float g_R[MM * DD];

// ========================= helpers ==========================================
__device__ __forceinline__ uint32_t smem_u32(const void* p) {
    uint32_t a;
    asm("{ .reg .u64 t; cvta.to.shared.u64 t, %1; cvt.u32.u64 %0, t; }"
        : "=r"(a) : "l"(p));
    return a;
}
#define CP_ASYNC16(dst, src) \
    asm volatile("cp.async.ca.shared.global [%0], [%1], 16;" :: "r"(dst), "l"(src))
#define CP_COMMIT() asm volatile("cp.async.commit_group;")
#define CP_WAIT1()  asm volatile("cp.async.wait_group 1;")

__device__ __forceinline__ uint32_t pack_bf16(float lo, float hi) {
    uint32_t r;
    asm("cvt.rn.bf16x2.f32 %0, %1, %2;" : "=r"(r) : "f"(hi), "f"(lo));
    return r;
}
__device__ __forceinline__ float ex2(float x) {
    float y;
    asm("ex2.approx.f32 %0, %1;" : "=f"(y) : "f"(x));
    return y;
}
__device__ __forceinline__ void ldsm4(uint32_t* r, uint32_t addr) {
    asm volatile("ldmatrix.sync.aligned.m8n8.x4.shared.b16 {%0,%1,%2,%3}, [%4];"
                 : "=r"(r[0]), "=r"(r[1]), "=r"(r[2]), "=r"(r[3]) : "r"(addr));
}
__device__ __forceinline__ void mma_bf16(float* c, const uint32_t* a, const uint32_t* b) {
    asm volatile(
        "mma.sync.aligned.m16n8k16.row.col.f32.bf16.bf16.f32 "
        "{%0,%1,%2,%3}, {%4,%5,%6,%7}, {%8,%9}, {%0,%1,%2,%3};"
        : "+f"(c[0]), "+f"(c[1]), "+f"(c[2]), "+f"(c[3])
        : "r"(a[0]), "r"(a[1]), "r"(a[2]), "r"(a[3]), "r"(b[0]), "r"(b[1]));
}

// ========================= fp32 -> bf16 convert =============================
__global__ __launch_bounds__(256) void cvt_kernel(const float* __restrict__ X,
                                                  __nv_bfloat16* __restrict__ Y)
{
    const int i = blockIdx.x * 256 + threadIdx.x;
    float4 v = ((const float4*)X)[i];
    uint2 o;
    o.x = pack_bf16(v.x, v.y);
    o.y = pack_bf16(v.z, v.w);
    ((uint2*)Y)[i] = o;
}

// ======== weight transpose+convert: W[K][N] f32 -> Wt[N][K] bf16 ============
__global__ __launch_bounds__(256) void wtrans_kernel(const float* __restrict__ W,
                                                     __nv_bfloat16* __restrict__ Wt)
{
    __shared__ float tile[32][33];
    const int n0 = blockIdx.x * 32, k0 = blockIdx.y * 32;
    const int tx = threadIdx.x, ty = threadIdx.y;   // 32 x 8
#pragma unroll
    for (int i = 0; i < 32; i += 8)
        tile[ty + i][tx] = W[(size_t)(k0 + ty + i) * DD + n0 + tx];
    __syncthreads();
#pragma unroll
    for (int i = 0; i < 32; i += 8)
        Wt[(size_t)(n0 + ty + i) * DD + k0 + tx] = __float2bfloat16(tile[tx][ty + i]);
}

// ========================= GEMM common pieces (R10-proven pipeline) ==========
#define GW 20                          // words per smem row (32 bf16 + pad)
#define GTILEW (128 * GW)              // 2560 words per tile
#define GEMM_SMEM (3 * 2 * GTILEW * 4) // 61440 B

#define GEMM_ISSUE(kb, st) do {                                                  \
    const uint32_t ao_ = sbase + (uint32_t)(st) * 2 * GTILEW * 4;                \
    const uint32_t bo_ = ao_ + GTILEW * 4;                                       \
    _Pragma("unroll")                                                            \
    for (int i_ = 0; i_ < 2; i_++) {                                             \
        const int row_ = L_row + i_ * 64;                                        \
        CP_ASYNC16(ao_ + (uint32_t)(row_ * 80) + L_ch,                           \
                   Ab + (size_t)row_ * DD + (kb) * 32 + L_el);                   \
        CP_ASYNC16(bo_ + (uint32_t)(row_ * 80) + L_ch,                           \
                   Bb + (size_t)row_ * DD + (kb) * 32 + L_el);                   \
    }                                                                            \
} while (0)

// R10-proven mainloop: wait1 / sync / compute / sync / issue+commit.
#define GEMM_MAINLOOP()                                                          \
    GEMM_ISSUE(0, 0); CP_COMMIT();                                               \
    GEMM_ISSUE(1, 1); CP_COMMIT();                                               \
    float acc[4][4][4];                                                          \
    _Pragma("unroll")                                                            \
    for (int mt = 0; mt < 4; mt++)                                               \
        _Pragma("unroll")                                                        \
        for (int nt = 0; nt < 4; nt++)                                           \
            _Pragma("unroll")                                                    \
            for (int j = 0; j < 4; j++) acc[mt][nt][j] = 0.f;                    \
    const int NKT = DD / 32;                                                     \
    for (int kb = 0; kb < NKT; kb++) {                                           \
        CP_WAIT1();                                                              \
        __syncthreads();                                                         \
        const int st = kb % 3;                                                   \
        const uint32_t abase = sbase + (uint32_t)st * 2 * GTILEW * 4;            \
        const uint32_t bbase = abase + GTILEW * 4;                               \
        _Pragma("unroll")                                                        \
        for (int ks = 0; ks < 2; ks++) {                                         \
            uint32_t af[4][4], bq[2][4];                                         \
            _Pragma("unroll")                                                    \
            for (int mt = 0; mt < 4; mt++)                                       \
                ldsm4(af[mt], abase +                                            \
                      (uint32_t)(((wm * 64 + mt * 16 + lr) * GW + ks * 8 + lc * 4) * 4)); \
            _Pragma("unroll")                                                    \
            for (int p = 0; p < 2; p++)                                          \
                ldsm4(bq[p], bbase +                                             \
                      (uint32_t)(((wn * 32 + p * 16 + lr) * GW + ks * 8 + lc * 4) * 4)); \
            uint32_t bf[4][2] = {                                                \
                { bq[0][0], bq[0][2] }, { bq[0][1], bq[0][3] },                  \
                { bq[1][0], bq[1][2] }, { bq[1][1], bq[1][3] } };                \
            _Pragma("unroll")                                                    \
            for (int mt = 0; mt < 4; mt++)                                       \
                _Pragma("unroll")                                                 \
                for (int nt = 0; nt < 4; nt++)                                   \
                    mma_bf16(acc[mt][nt], af[mt], bf[nt]);                       \
        }                                                                        \
        __syncthreads();                                                         \
        if (kb + 2 < NKT) GEMM_ISSUE(kb + 2, (kb + 2) % 3);                      \
        CP_COMMIT();                                                             \
    }

// ---------------- merged QKV GEMM: grid.x = 24 (3 weights x 8 n-blocks) ------
__global__ __launch_bounds__(256)
void gemm_qkv(const __nv_bfloat16* __restrict__ A,
              const __nv_bfloat16* __restrict__ Wqkvt,
              const float* __restrict__ bq, const float* __restrict__ bk,
              const float* __restrict__ bv,
              __nv_bfloat16* __restrict__ Qo, __nv_bfloat16* __restrict__ Ko,
              __nv_bfloat16* __restrict__ Vo)
{
    extern __shared__ uint32_t sm[];
    const uint32_t sbase = smem_u32(sm);

    const int tid = threadIdx.x;
    const int wid = tid >> 5, lane = tid & 31;
    const int g = lane >> 2, t = lane & 3;
    const int lr = lane & 15, lc = lane >> 4;
    const int wm = wid >> 2, wn = wid & 3;
    const int by = blockIdx.y;
    const int wsel = blockIdx.x >> 3;
    const int bx = blockIdx.x & 7;

    const float* bias = (wsel == 0) ? bq : (wsel == 1) ? bk : bv;
    __nv_bfloat16* Cout = (wsel == 0) ? Qo : (wsel == 1) ? Ko : Vo;

    const __nv_bfloat16* Ab = A + (size_t)(by * 128) * DD;
    const __nv_bfloat16* Bb = Wqkvt + (size_t)wsel * DD * DD + (size_t)(bx * 128) * DD;

    const int L_row = tid >> 2;
    const int L_ch  = (tid & 3) * 16;
    const int L_el  = (tid & 3) * 8;

    GEMM_MAINLOOP();

    // epilogue (bf16 out)
#pragma unroll
    for (int nt = 0; nt < 4; nt++) {
        const int col = bx * 128 + wn * 32 + nt * 8 + 2 * t;
        const float b0 = bias[col], b1 = bias[col + 1];
#pragma unroll
        for (int mt = 0; mt < 4; mt++) {
            const int row = by * 128 + wm * 64 + mt * 16 + g;
            const size_t o0 = (size_t)row * DD + col;
            const size_t o1 = (size_t)(row + 8) * DD + col;
            *(uint32_t*)(Cout + o0) = pack_bf16(acc[mt][nt][0] + b0, acc[mt][nt][1] + b1);
            *(uint32_t*)(Cout + o1) = pack_bf16(acc[mt][nt][2] + b0, acc[mt][nt][3] + b1);
        }
    }
}

// ---------------- out-projection GEMM (f32 out + residual) -------------------
__global__ __launch_bounds__(256)
void gemm_out(const __nv_bfloat16* __restrict__ A, const __nv_bfloat16* __restrict__ Bt,
              const float* __restrict__ bias, const float* __restrict__ R,
              float* __restrict__ C)
{
    extern __shared__ uint32_t sm[];
    const uint32_t sbase = smem_u32(sm);

    const int tid = threadIdx.x;
    const int wid = tid >> 5, lane = tid & 31;
    const int g = lane >> 2, t = lane & 3;
    const int lr = lane & 15, lc = lane >> 4;
    const int wm = wid >> 2, wn = wid & 3;
    const int bx = blockIdx.x, by = blockIdx.y;

    const __nv_bfloat16* Ab = A  + (size_t)(by * 128) * DD;
    const __nv_bfloat16* Bb = Bt + (size_t)(bx * 128) * DD;

    const int L_row = tid >> 2;
    const int L_ch  = (tid & 3) * 16;
    const int L_el  = (tid & 3) * 8;

    GEMM_MAINLOOP();

#pragma unroll
    for (int nt = 0; nt < 4; nt++) {
        const int col = bx * 128 + wn * 32 + nt * 8 + 2 * t;
        const float b0 = bias[col], b1 = bias[col + 1];
#pragma unroll
        for (int mt = 0; mt < 4; mt++) {
            const int row = by * 128 + wm * 64 + mt * 16 + g;
            const size_t o0 = (size_t)row * DD + col;
            const size_t o1 = (size_t)(row + 8) * DD + col;
            float2 r0 = *(const float2*)(R + o0);
            float2 r1 = *(const float2*)(R + o1);
            *(float2*)(C + o0) = make_float2(acc[mt][nt][0] + b0 + r0.x,
                                             acc[mt][nt][1] + b1 + r0.y);
            *(float2*)(C + o1) = make_float2(acc[mt][nt][2] + b0 + r1.x,
                                             acc[mt][nt][3] + b1 + r1.y);
        }
    }
}

// ========================= bf16 flash attention ==============================
// R13 pipeline structure; Q fragments hoisted (loop-invariant); exact lazy
// rescale: skip alpha/oacc-rescale when no row max changes (alpha == 1).
#define AW 36                                   // word stride (72 bf16, 144 B)
#define QW_OFF 0
#define KW_OFF (128 * AW)
#define VW_OFF (KW_OFF + 2 * 64 * AW)
#define ATT_WORDS (VW_OFF + 2 * 64 * AW)
#define ATT_SMEM (ATT_WORDS * 4)                // 55296 B

__global__ __launch_bounds__(256, 2)
void attn_bf16(const __nv_bfloat16* __restrict__ Q, const __nv_bfloat16* __restrict__ K,
               const __nv_bfloat16* __restrict__ V, __nv_bfloat16* __restrict__ O)
{
    extern __shared__ uint32_t sm[];
    const uint32_t sbase = smem_u32(sm);
    const uint32_t qaddr = sbase + QW_OFF * 4;
    const uint32_t kaddr = sbase + KW_OFF * 4;
    const uint32_t vaddr = sbase + VW_OFF * 4;

    const int tid = threadIdx.x;
    const int wid = tid >> 5, lane = tid & 31;
    const int g = lane >> 2, t = lane & 3;
    const int lr = lane & 15, lc = lane >> 4;
    const int m0 = wid * 16;

    const int bh = blockIdx.y;
    const int b = bh >> 4, h = bh & 15;
    const int q0 = blockIdx.x * 128;
    const size_t base = (size_t)b * LL * DD + (size_t)h * HD;

    const int vkey = tid & 63;
    const int vw0 = (tid >> 6) * 8;

    // ---- prologue: Q + K0 cp.async (one group), V0 LDG ----
    {
#pragma unroll
        for (int i = 0; i < 4; i++) {
            const int c = tid + i * 256;
            const int row = c >> 3, ch = (c & 7) * 16, el = (c & 7) * 8;
            CP_ASYNC16(qaddr + (uint32_t)(row * 144) + ch,
                       Q + base + (size_t)(q0 + row) * DD + el);
        }
#pragma unroll
        for (int i = 0; i < 2; i++) {
            const int c = tid + i * 256;
            const int row = c >> 3, ch = (c & 7) * 16, el = (c & 7) * 8;
            CP_ASYNC16(kaddr + (uint32_t)(row * 144) + ch,
                       K + base + (size_t)row * DD + el);
        }
        CP_COMMIT();
    }
    uint32_t vreg[8];
    {
        const uint32_t* vg = (const uint32_t*)(V + base + (size_t)vkey * DD) + vw0;
#pragma unroll
        for (int j = 0; j < 8; j++) vreg[j] = vg[j];
    }

    float oacc[8][4];
    float mrow[2] = { -1e30f, -1e30f };
    float lrow[2] = { 0.f, 0.f };
    uint32_t aqf[4][4];                 // hoisted Q fragments (loop-invariant)
#pragma unroll
    for (int nt = 0; nt < 8; nt++)
#pragma unroll
        for (int j = 0; j < 4; j++) oacc[nt][j] = 0.f;

    const float SC = 0.18033688011112042f;   // 0.125 * log2(e)
    const int NBLK = LL / 64;
    for (int i = 0; i < NBLK; i++) {
        const int buf = i & 1;
        // STS-transpose this block's V registers into Vt[buf]
        {
            unsigned short* Vt16 = (unsigned short*)(sm + VW_OFF + buf * 64 * AW);
#pragma unroll
            for (int j = 0; j < 8; j++) {
                const int d2 = (vw0 + j) * 2;
                Vt16[(d2    ) * 72 + vkey] = (unsigned short)(vreg[j] & 0xffffu);
                Vt16[(d2 + 1) * 72 + vkey] = (unsigned short)(vreg[j] >> 16);
            }
        }
        // prefetch next block: K via cp.async, V via LDG
        if (i + 1 < NBLK) {
            const uint32_t ko = kaddr + (uint32_t)((buf ^ 1) * 64 * AW * 4);
#pragma unroll
            for (int ii = 0; ii < 2; ii++) {
                const int c = tid + ii * 256;
                const int row = c >> 3, ch = (c & 7) * 16, el = (c & 7) * 8;
                CP_ASYNC16(ko + (uint32_t)(row * 144) + ch,
                           K + base + (size_t)((i + 1) * 64 + row) * DD + el);
            }
        }
        CP_COMMIT();
        if (i + 1 < NBLK) {
            const uint32_t* vg =
                (const uint32_t*)(V + base + (size_t)((i + 1) * 64 + vkey) * DD) + vw0;
#pragma unroll
            for (int j = 0; j < 8; j++) vreg[j] = vg[j];
        }
        CP_WAIT1();
        __syncthreads();

        if (i == 0) {
            // Q resident now (same group as K0); load fragments ONCE.
#pragma unroll
            for (int ks = 0; ks < 4; ks++)
                ldsm4(aqf[ks], qaddr + (uint32_t)(((m0 + lr) * AW + ks * 8 + lc * 4) * 4));
        }

        const uint32_t kbuf = kaddr + (uint32_t)(buf * 64 * AW * 4);
        const uint32_t vbuf = vaddr + (uint32_t)(buf * 64 * AW * 4);

        // ---- S = Q @ K^T ----
        float sacc[8][4];
#pragma unroll
        for (int nt = 0; nt < 8; nt++)
#pragma unroll
            for (int j = 0; j < 4; j++) sacc[nt][j] = 0.f;

#pragma unroll
        for (int ks = 0; ks < 4; ks++) {
#pragma unroll
            for (int p = 0; p < 4; p++) {
                uint32_t bq[4];
                ldsm4(bq, kbuf + (uint32_t)(((p * 16 + lr) * AW + ks * 8 + lc * 4) * 4));
                uint32_t b0[2] = { bq[0], bq[2] };
                uint32_t b1[2] = { bq[1], bq[3] };
                mma_bf16(sacc[p * 2 + 0], aqf[ks], b0);
                mma_bf16(sacc[p * 2 + 1], aqf[ks], b1);
            }
        }

        // ---- online softmax (exp2 form; exact lazy rescale) ----
#pragma unroll
        for (int r = 0; r < 2; r++) {
            const int j0 = r * 2;
            float mx = -1e30f;
#pragma unroll
            for (int nt = 0; nt < 8; nt++)
                mx = fmaxf(mx, fmaxf(sacc[nt][j0], sacc[nt][j0 + 1]));
            mx = fmaxf(mx, __shfl_xor_sync(0xffffffffu, mx, 1));
            mx = fmaxf(mx, __shfl_xor_sync(0xffffffffu, mx, 2));
            const float mnew = fmaxf(mrow[r], mx);
            const float nmc = -mnew * SC;
            const bool changed = mnew > mrow[r];
            if (__any_sync(0xffffffffu, changed)) {
                // alpha == 1 exactly for unchanged lanes; compute & apply.
                const float alpha = ex2(fmaf(mrow[r], SC, nmc));
                lrow[r] *= alpha;
#pragma unroll
                for (int nt = 0; nt < 8; nt++) {
                    oacc[nt][j0]     *= alpha;
                    oacc[nt][j0 + 1] *= alpha;
                }
            }
            mrow[r] = mnew;
            float rs = 0.f;
#pragma unroll
            for (int nt = 0; nt < 8; nt++) {
                sacc[nt][j0]     = ex2(fmaf(sacc[nt][j0],     SC, nmc));
                sacc[nt][j0 + 1] = ex2(fmaf(sacc[nt][j0 + 1], SC, nmc));
                rs += sacc[nt][j0] + sacc[nt][j0 + 1];
            }
            rs += __shfl_xor_sync(0xffffffffu, rs, 1);
            rs += __shfl_xor_sync(0xffffffffu, rs, 2);
            lrow[r] += rs;
        }

        // ---- O += P @ V (P from sacc registers; V frags via ldmatrix) ----
#pragma unroll
        for (int j = 0; j < 4; j++) {
            uint32_t ap[4];
            ap[0] = pack_bf16(sacc[2 * j][0],     sacc[2 * j][1]);
            ap[1] = pack_bf16(sacc[2 * j][2],     sacc[2 * j][3]);
            ap[2] = pack_bf16(sacc[2 * j + 1][0], sacc[2 * j + 1][1]);
            ap[3] = pack_bf16(sacc[2 * j + 1][2], sacc[2 * j + 1][3]);
#pragma unroll
            for (int p = 0; p < 4; p++) {
                uint32_t bq[4];
                ldsm4(bq, vbuf + (uint32_t)(((p * 16 + lr) * AW + j * 8 + lc * 4) * 4));
                uint32_t b0[2] = { bq[0], bq[2] };
                uint32_t b1[2] = { bq[1], bq[3] };
                mma_bf16(oacc[p * 2 + 0], ap, b0);
                mma_bf16(oacc[p * 2 + 1], ap, b1);
            }
        }
        __syncthreads();
    }

    // ---- normalize + store (bf16) ----
    const float inv0 = 1.f / lrow[0];
    const float inv1 = 1.f / lrow[1];
#pragma unroll
    for (int nt = 0; nt < 8; nt++) {
        const int col = nt * 8 + 2 * t;
        const size_t o0 = base + (size_t)(q0 + m0 + g    ) * DD + col;
        const size_t o1 = base + (size_t)(q0 + m0 + g + 8) * DD + col;
        *(uint32_t*)(O + o0) = pack_bf16(oacc[nt][0] * inv0, oacc[nt][1] * inv0);
        *(uint32_t*)(O + o1) = pack_bf16(oacc[nt][2] * inv1, oacc[nt][3] * inv1);
    }
}

// ------------------------- LayerNorm -----------------------------------------
__global__ __launch_bounds__(256) void ln_kernel(
    const float* __restrict__ X, const float* __restrict__ gamma,
    const float* __restrict__ beta, float* __restrict__ out)
{
    __shared__ float ssum[8], ssq[8];
    const int row = blockIdx.x;
    const int tid = threadIdx.x;
    const float* x = X + (size_t)row * DD;

    float4 v = *(const float4*)(x + tid * 4);
    float s = v.x + v.y + v.z + v.w;
    float q = v.x * v.x + v.y * v.y + v.z * v.z + v.w * v.w;
#pragma unroll
    for (int off = 16; off > 0; off >>= 1) {
        s += __shfl_xor_sync(0xffffffffu, s, off);
        q += __shfl_xor_sync(0xffffffffu, q, off);
    }
    if ((tid & 31) == 0) { ssum[tid >> 5] = s; ssq[tid >> 5] = q; }
    __syncthreads();
    float ts = 0.f, tq = 0.f;
#pragma unroll
    for (int i = 0; i < 8; i++) { ts += ssum[i]; tq += ssq[i]; }

    const float mean = ts * (1.f / DD);
    const float var = tq * (1.f / DD) - mean * mean;
    const float inv = rsqrtf(var + 1e-5f);

    float4 gmv = *(const float4*)(gamma + tid * 4);
    float4 btv = *(const float4*)(beta + tid * 4);
    float4 o4;
    o4.x = (v.x - mean) * inv * gmv.x + btv.x;
    o4.y = (v.y - mean) * inv * gmv.y + btv.y;
    o4.z = (v.z - mean) * inv * gmv.z + btv.z;
    o4.w = (v.w - mean) * inv * gmv.w + btv.w;
    *(float4*)(out + (size_t)row * DD + tid * 4) = o4;
}

// ------------------------- launch --------------------------------------------
extern "C" void kernel_launch(void* const* d_in, const int* in_sizes, int n_in,
                              void* d_out, int out_size)
{
    const float* X     = (const float*)d_in[0];
    const float* Wq    = (const float*)d_in[1];
    const float* bq    = (const float*)d_in[2];
    const float* Wk    = (const float*)d_in[3];
    const float* bk    = (const float*)d_in[4];
    const float* Wv    = (const float*)d_in[5];
    const float* bv    = (const float*)d_in[6];
    const float* Wo    = (const float*)d_in[7];
    const float* bo    = (const float*)d_in[8];
    const float* gamma = (const float*)d_in[9];
    const float* beta  = (const float*)d_in[10];
    float* out = (float*)d_out;

    __nv_bfloat16 *Xb, *Qb, *Kb, *Vb, *Ob, *Wqkvt, *Wot;
    float* Rp;
    cudaGetSymbolAddress((void**)&Xb, g_Xb);
    cudaGetSymbolAddress((void**)&Qb, g_Qb);
    cudaGetSymbolAddress((void**)&Kb, g_Kb);
    cudaGetSymbolAddress((void**)&Vb, g_Vb);
    cudaGetSymbolAddress((void**)&Ob, g_Ob);
    cudaGetSymbolAddress((void**)&Wqkvt, g_Wqkvt);
    cudaGetSymbolAddress((void**)&Wot, g_Wot);
    cudaGetSymbolAddress((void**)&Rp, g_R);

    cudaFuncSetAttribute(gemm_qkv,
                         cudaFuncAttributeMaxDynamicSharedMemorySize, GEMM_SMEM);
    cudaFuncSetAttribute(gemm_out,
                         cudaFuncAttributeMaxDynamicSharedMemorySize, GEMM_SMEM);
    cudaFuncSetAttribute(attn_bf16,
                         cudaFuncAttributeMaxDynamicSharedMemorySize, ATT_SMEM);

    dim3 tgrid(DD / 32, DD / 32);
    dim3 tblk(32, 8);

    cvt_kernel<<<MM * DD / 4 / 256, 256>>>(X, Xb);
    wtrans_kernel<<<tgrid, tblk>>>(Wq, Wqkvt);
    wtrans_kernel<<<tgrid, tblk>>>(Wk, Wqkvt + (size_t)DD * DD);
    wtrans_kernel<<<tgrid, tblk>>>(Wv, Wqkvt + (size_t)2 * DD * DD);
    wtrans_kernel<<<tgrid, tblk>>>(Wo, Wot);

    gemm_qkv<<<dim3(24, MM / 128), 256, GEMM_SMEM>>>(Xb, Wqkvt, bq, bk, bv,
                                                     Qb, Kb, Vb);

    attn_bf16<<<dim3(LL / 128, BB * HH), 256, ATT_SMEM>>>(Qb, Kb, Vb, Ob);

    gemm_out<<<dim3(DD / 128, MM / 128), 256, GEMM_SMEM>>>(Ob, Wot, bo, X, Rp);

    ln_kernel<<<MM, 256>>>(Rp, gamma, beta, out);
}

// round 15
// speedup vs baseline: 6.0295x; 1.3310x over previous
#include <cuda_runtime.h>
#include <cuda_bf16.h>
#include <math.h>
#include <stdint.h>

// Problem dims
#define BB 4
#define LL 2048
#define DD 1024
#define HH 16
#define HD 64
#define MM (BB * LL)   // 8192

// ------------------------- scratch (static device globals) -------------------
__device__ __nv_bfloat16 g_Xb[MM * DD];
__device__ __nv_bfloat16 g_Qb[MM * DD];
__device__ __nv_bfloat16 g_Kb[MM * DD];
__device__ __nv_bfloat16 g_Vb[MM * DD];
__device__ __nv_bfloat16 g_Ob[MM * DD];
__device__ __nv_bfloat16 g_Wqkvt[3 * DD * DD];   // [Q|K|V] transposed bf16
__device__ __nv_bfloat16 g_Wot[DD * DD];
__device__ float g_R[MM * DD];

// ========================= helpers ==========================================
__device__ __forceinline__ uint32_t smem_u32(const void* p) {
    uint32_t a;
    asm("{ .reg .u64 t; cvta.to.shared.u64 t, %1; cvt.u32.u64 %0, t; }"
        : "=r"(a) : "l"(p));
    return a;
}
#define CP_ASYNC16(dst, src) \
    asm volatile("cp.async.ca.shared.global [%0], [%1], 16;" :: "r"(dst), "l"(src))
#define CP_COMMIT() asm volatile("cp.async.commit_group;")
#define CP_WAIT1()  asm volatile("cp.async.wait_group 1;")

__device__ __forceinline__ uint32_t pack_bf16(float lo, float hi) {
    uint32_t r;
    asm("cvt.rn.bf16x2.f32 %0, %1, %2;" : "=r"(r) : "f"(hi), "f"(lo));
    return r;
}
__device__ __forceinline__ float ex2(float x) {
    float y;
    asm("ex2.approx.f32 %0, %1;" : "=f"(y) : "f"(x));
    return y;
}
__device__ __forceinline__ void ldsm4(uint32_t* r, uint32_t addr) {
    asm volatile("ldmatrix.sync.aligned.m8n8.x4.shared.b16 {%0,%1,%2,%3}, [%4];"
                 : "=r"(r[0]), "=r"(r[1]), "=r"(r[2]), "=r"(r[3]) : "r"(addr));
}
__device__ __forceinline__ void ldsm4t(uint32_t* r, uint32_t addr) {
    asm volatile("ldmatrix.sync.aligned.m8n8.x4.trans.shared.b16 {%0,%1,%2,%3}, [%4];"
                 : "=r"(r[0]), "=r"(r[1]), "=r"(r[2]), "=r"(r[3]) : "r"(addr));
}
__device__ __forceinline__ void mma_bf16(float* c, const uint32_t* a, const uint32_t* b) {
    asm volatile(
        "mma.sync.aligned.m16n8k16.row.col.f32.bf16.bf16.f32 "
        "{%0,%1,%2,%3}, {%4,%5,%6,%7}, {%8,%9}, {%0,%1,%2,%3};"
        : "+f"(c[0]), "+f"(c[1]), "+f"(c[2]), "+f"(c[3])
        : "r"(a[0]), "r"(a[1]), "r"(a[2]), "r"(a[3]), "r"(b[0]), "r"(b[1]));
}

// ========================= fp32 -> bf16 convert =============================
__global__ __launch_bounds__(256) void cvt_kernel(const float* __restrict__ X,
                                                  __nv_bfloat16* __restrict__ Y)
{
    const int i = blockIdx.x * 256 + threadIdx.x;
    float4 v = ((const float4*)X)[i];
    uint2 o;
    o.x = pack_bf16(v.x, v.y);
    o.y = pack_bf16(v.z, v.w);
    ((uint2*)Y)[i] = o;
}

// ======== weight transpose+convert: W[K][N] f32 -> Wt[N][K] bf16 ============
__global__ __launch_bounds__(256) void wtrans_kernel(const float* __restrict__ W,
                                                     __nv_bfloat16* __restrict__ Wt)
{
    __shared__ float tile[32][33];
    const int n0 = blockIdx.x * 32, k0 = blockIdx.y * 32;
    const int tx = threadIdx.x, ty = threadIdx.y;   // 32 x 8
#pragma unroll
    for (int i = 0; i < 32; i += 8)
        tile[ty + i][tx] = W[(size_t)(k0 + ty + i) * DD + n0 + tx];
    __syncthreads();
#pragma unroll
    for (int i = 0; i < 32; i += 8)
        Wt[(size_t)(n0 + ty + i) * DD + k0 + tx] = __float2bfloat16(tile[tx][ty + i]);
}

// ========================= GEMM common pieces (R10-proven pipeline) ==========
#define GW 20                          // words per smem row (32 bf16 + pad)
#define GTILEW (128 * GW)              // 2560 words per tile
#define GEMM_SMEM (3 * 2 * GTILEW * 4) // 61440 B

#define GEMM_ISSUE(kb, st) do {                                                  \
    const uint32_t ao_ = sbase + (uint32_t)(st) * 2 * GTILEW * 4;                \
    const uint32_t bo_ = ao_ + GTILEW * 4;                                       \
    _Pragma("unroll")                                                            \
    for (int i_ = 0; i_ < 2; i_++) {                                             \
        const int row_ = L_row + i_ * 64;                                        \
        CP_ASYNC16(ao_ + (uint32_t)(row_ * 80) + L_ch,                           \
                   Ab + (size_t)row_ * DD + (kb) * 32 + L_el);                   \
        CP_ASYNC16(bo_ + (uint32_t)(row_ * 80) + L_ch,                           \
                   Bb + (size_t)row_ * DD + (kb) * 32 + L_el);                   \
    }                                                                            \
} while (0)

// R10-proven mainloop: wait1 / sync / compute / sync / issue+commit.
#define GEMM_MAINLOOP()                                                          \
    GEMM_ISSUE(0, 0); CP_COMMIT();                                               \
    GEMM_ISSUE(1, 1); CP_COMMIT();                                               \
    float acc[4][4][4];                                                          \
    _Pragma("unroll")                                                            \
    for (int mt = 0; mt < 4; mt++)                                               \
        _Pragma("unroll")                                                        \
        for (int nt = 0; nt < 4; nt++)                                           \
            _Pragma("unroll")                                                    \
            for (int j = 0; j < 4; j++) acc[mt][nt][j] = 0.f;                    \
    const int NKT = DD / 32;                                                     \
    for (int kb = 0; kb < NKT; kb++) {                                           \
        CP_WAIT1();                                                              \
        __syncthreads();                                                         \
        const int st = kb % 3;                                                   \
        const uint32_t abase = sbase + (uint32_t)st * 2 * GTILEW * 4;            \
        const uint32_t bbase = abase + GTILEW * 4;                               \
        _Pragma("unroll")                                                        \
        for (int ks = 0; ks < 2; ks++) {                                         \
            uint32_t af[4][4], bq[2][4];                                         \
            _Pragma("unroll")                                                    \
            for (int mt = 0; mt < 4; mt++)                                       \
                ldsm4(af[mt], abase +                                            \
                      (uint32_t)(((wm * 64 + mt * 16 + lr) * GW + ks * 8 + lc * 4) * 4)); \
            _Pragma("unroll")                                                    \
            for (int p = 0; p < 2; p++)                                          \
                ldsm4(bq[p], bbase +                                             \
                      (uint32_t)(((wn * 32 + p * 16 + lr) * GW + ks * 8 + lc * 4) * 4)); \
            uint32_t bf[4][2] = {                                                \
                { bq[0][0], bq[0][2] }, { bq[0][1], bq[0][3] },                  \
                { bq[1][0], bq[1][2] }, { bq[1][1], bq[1][3] } };                \
            _Pragma("unroll")                                                    \
            for (int mt = 0; mt < 4; mt++)                                       \
                _Pragma("unroll")                                                 \
                for (int nt = 0; nt < 4; nt++)                                   \
                    mma_bf16(acc[mt][nt], af[mt], bf[nt]);                       \
        }                                                                        \
        __syncthreads();                                                         \
        if (kb + 2 < NKT) GEMM_ISSUE(kb + 2, (kb + 2) % 3);                      \
        CP_COMMIT();                                                             \
    }

// ---------------- merged QKV GEMM: grid.x = 24 (3 weights x 8 n-blocks) ------
__global__ __launch_bounds__(256)
void gemm_qkv(const __nv_bfloat16* __restrict__ A,
              const __nv_bfloat16* __restrict__ Wqkvt,
              const float* __restrict__ bq, const float* __restrict__ bk,
              const float* __restrict__ bv,
              __nv_bfloat16* __restrict__ Qo, __nv_bfloat16* __restrict__ Ko,
              __nv_bfloat16* __restrict__ Vo)
{
    extern __shared__ uint32_t sm[];
    const uint32_t sbase = smem_u32(sm);

    const int tid = threadIdx.x;
    const int wid = tid >> 5, lane = tid & 31;
    const int g = lane >> 2, t = lane & 3;
    const int lr = lane & 15, lc = lane >> 4;
    const int wm = wid >> 2, wn = wid & 3;
    const int by = blockIdx.y;
    const int wsel = blockIdx.x >> 3;
    const int bx = blockIdx.x & 7;

    const float* bias = (wsel == 0) ? bq : (wsel == 1) ? bk : bv;
    __nv_bfloat16* Cout = (wsel == 0) ? Qo : (wsel == 1) ? Ko : Vo;

    const __nv_bfloat16* Ab = A + (size_t)(by * 128) * DD;
    const __nv_bfloat16* Bb = Wqkvt + (size_t)wsel * DD * DD + (size_t)(bx * 128) * DD;

    const int L_row = tid >> 2;
    const int L_ch  = (tid & 3) * 16;
    const int L_el  = (tid & 3) * 8;

    GEMM_MAINLOOP();

    // epilogue (bf16 out)
#pragma unroll
    for (int nt = 0; nt < 4; nt++) {
        const int col = bx * 128 + wn * 32 + nt * 8 + 2 * t;
        const float b0 = bias[col], b1 = bias[col + 1];
#pragma unroll
        for (int mt = 0; mt < 4; mt++) {
            const int row = by * 128 + wm * 64 + mt * 16 + g;
            const size_t o0 = (size_t)row * DD + col;
            const size_t o1 = (size_t)(row + 8) * DD + col;
            *(uint32_t*)(Cout + o0) = pack_bf16(acc[mt][nt][0] + b0, acc[mt][nt][1] + b1);
            *(uint32_t*)(Cout + o1) = pack_bf16(acc[mt][nt][2] + b0, acc[mt][nt][3] + b1);
        }
    }
}

// ---------------- out-projection GEMM (f32 out + residual) -------------------
__global__ __launch_bounds__(256)
void gemm_out(const __nv_bfloat16* __restrict__ A, const __nv_bfloat16* __restrict__ Bt,
              const float* __restrict__ bias, const float* __restrict__ R,
              float* __restrict__ C)
{
    extern __shared__ uint32_t sm[];
    const uint32_t sbase = smem_u32(sm);

    const int tid = threadIdx.x;
    const int wid = tid >> 5, lane = tid & 31;
    const int g = lane >> 2, t = lane & 3;
    const int lr = lane & 15, lc = lane >> 4;
    const int wm = wid >> 2, wn = wid & 3;
    const int bx = blockIdx.x, by = blockIdx.y;

    const __nv_bfloat16* Ab = A  + (size_t)(by * 128) * DD;
    const __nv_bfloat16* Bb = Bt + (size_t)(bx * 128) * DD;

    const int L_row = tid >> 2;
    const int L_ch  = (tid & 3) * 16;
    const int L_el  = (tid & 3) * 8;

    GEMM_MAINLOOP();

#pragma unroll
    for (int nt = 0; nt < 4; nt++) {
        const int col = bx * 128 + wn * 32 + nt * 8 + 2 * t;
        const float b0 = bias[col], b1 = bias[col + 1];
#pragma unroll
        for (int mt = 0; mt < 4; mt++) {
            const int row = by * 128 + wm * 64 + mt * 16 + g;
            const size_t o0 = (size_t)row * DD + col;
            const size_t o1 = (size_t)(row + 8) * DD + col;
            float2 r0 = *(const float2*)(R + o0);
            float2 r1 = *(const float2*)(R + o1);
            *(float2*)(C + o0) = make_float2(acc[mt][nt][0] + b0 + r0.x,
                                             acc[mt][nt][1] + b1 + r0.y);
            *(float2*)(C + o1) = make_float2(acc[mt][nt][2] + b0 + r1.x,
                                             acc[mt][nt][3] + b1 + r1.y);
        }
    }
}

// ========================= bf16 flash attention ==============================
// R14 structure; V now streamed row-major via cp.async (same group as K) and
// PV B-fragments loaded with ldmatrix.trans — STS transpose + LDG staging gone.
#define AW 36                                   // word stride (72 bf16, 144 B)
#define QW_OFF 0
#define KW_OFF (128 * AW)
#define VW_OFF (KW_OFF + 2 * 64 * AW)
#define ATT_WORDS (VW_OFF + 2 * 64 * AW)
#define ATT_SMEM (ATT_WORDS * 4)                // 55296 B

__global__ __launch_bounds__(256, 2)
void attn_bf16(const __nv_bfloat16* __restrict__ Q, const __nv_bfloat16* __restrict__ K,
               const __nv_bfloat16* __restrict__ V, __nv_bfloat16* __restrict__ O)
{
    extern __shared__ uint32_t sm[];
    const uint32_t sbase = smem_u32(sm);
    const uint32_t qaddr = sbase + QW_OFF * 4;
    const uint32_t kaddr = sbase + KW_OFF * 4;
    const uint32_t vaddr = sbase + VW_OFF * 4;

    const int tid = threadIdx.x;
    const int wid = tid >> 5, lane = tid & 31;
    const int g = lane >> 2, t = lane & 3;
    const int lr = lane & 15, lc = lane >> 4;
    const int m0 = wid * 16;

    const int bh = blockIdx.y;
    const int b = bh >> 4, h = bh & 15;
    const int q0 = blockIdx.x * 128;
    const size_t base = (size_t)b * LL * DD + (size_t)h * HD;

    // KV load mapping: 64 rows x 128B each for K and V
#define KV_ISSUE(blk, buf) do {                                                  \
    const uint32_t ko_ = kaddr + (uint32_t)((buf) * 64 * AW * 4);                \
    const uint32_t vo_ = vaddr + (uint32_t)((buf) * 64 * AW * 4);                \
    _Pragma("unroll")                                                            \
    for (int ii_ = 0; ii_ < 2; ii_++) {                                          \
        const int c_ = tid + ii_ * 256;                                          \
        const int row_ = c_ >> 3, ch_ = (c_ & 7) * 16, el_ = (c_ & 7) * 8;       \
        const size_t go_ = base + (size_t)((blk) * 64 + row_) * DD + el_;        \
        CP_ASYNC16(ko_ + (uint32_t)(row_ * 144) + ch_, K + go_);                 \
        CP_ASYNC16(vo_ + (uint32_t)(row_ * 144) + ch_, V + go_);                 \
    }                                                                            \
} while (0)

    // ---- prologue: Q + K0 + V0 cp.async (one group) ----
    {
#pragma unroll
        for (int i = 0; i < 4; i++) {
            const int c = tid + i * 256;
            const int row = c >> 3, ch = (c & 7) * 16, el = (c & 7) * 8;
            CP_ASYNC16(qaddr + (uint32_t)(row * 144) + ch,
                       Q + base + (size_t)(q0 + row) * DD + el);
        }
        KV_ISSUE(0, 0);
        CP_COMMIT();
    }

    float oacc[8][4];
    float mrow[2] = { -1e30f, -1e30f };
    float lrow[2] = { 0.f, 0.f };
    uint32_t aqf[4][4];                 // hoisted Q fragments (loop-invariant)
#pragma unroll
    for (int nt = 0; nt < 8; nt++)
#pragma unroll
        for (int j = 0; j < 4; j++) oacc[nt][j] = 0.f;

    const float SC = 0.18033688011112042f;   // 0.125 * log2(e)
    const int NBLK = LL / 64;
    for (int i = 0; i < NBLK; i++) {
        const int buf = i & 1;
        // prefetch next block's K+V (one group), overlapping this block's wait
        if (i + 1 < NBLK) KV_ISSUE(i + 1, buf ^ 1);
        CP_COMMIT();
        CP_WAIT1();
        __syncthreads();

        if (i == 0) {
            // Q resident now (same group as K0/V0); load fragments ONCE.
#pragma unroll
            for (int ks = 0; ks < 4; ks++)
                ldsm4(aqf[ks], qaddr + (uint32_t)(((m0 + lr) * AW + ks * 8 + lc * 4) * 4));
        }

        const uint32_t kbuf = kaddr + (uint32_t)(buf * 64 * AW * 4);
        const uint32_t vbuf = vaddr + (uint32_t)(buf * 64 * AW * 4);

        // ---- S = Q @ K^T ----
        float sacc[8][4];
#pragma unroll
        for (int nt = 0; nt < 8; nt++)
#pragma unroll
            for (int j = 0; j < 4; j++) sacc[nt][j] = 0.f;

#pragma unroll
        for (int ks = 0; ks < 4; ks++) {
#pragma unroll
            for (int p = 0; p < 4; p++) {
                uint32_t bq[4];
                ldsm4(bq, kbuf + (uint32_t)(((p * 16 + lr) * AW + ks * 8 + lc * 4) * 4));
                uint32_t b0[2] = { bq[0], bq[2] };
                uint32_t b1[2] = { bq[1], bq[3] };
                mma_bf16(sacc[p * 2 + 0], aqf[ks], b0);
                mma_bf16(sacc[p * 2 + 1], aqf[ks], b1);
            }
        }

        // ---- online softmax (exp2 form; exact lazy rescale) ----
#pragma unroll
        for (int r = 0; r < 2; r++) {
            const int j0 = r * 2;
            float mx = -1e30f;
#pragma unroll
            for (int nt = 0; nt < 8; nt++)
                mx = fmaxf(mx, fmaxf(sacc[nt][j0], sacc[nt][j0 + 1]));
            mx = fmaxf(mx, __shfl_xor_sync(0xffffffffu, mx, 1));
            mx = fmaxf(mx, __shfl_xor_sync(0xffffffffu, mx, 2));
            const float mnew = fmaxf(mrow[r], mx);
            const float nmc = -mnew * SC;
            const bool changed = mnew > mrow[r];
            if (__any_sync(0xffffffffu, changed)) {
                const float alpha = ex2(fmaf(mrow[r], SC, nmc));
                lrow[r] *= alpha;
#pragma unroll
                for (int nt = 0; nt < 8; nt++) {
                    oacc[nt][j0]     *= alpha;
                    oacc[nt][j0 + 1] *= alpha;
                }
            }
            mrow[r] = mnew;
            float rs = 0.f;
#pragma unroll
            for (int nt = 0; nt < 8; nt++) {
                sacc[nt][j0]     = ex2(fmaf(sacc[nt][j0],     SC, nmc));
                sacc[nt][j0 + 1] = ex2(fmaf(sacc[nt][j0 + 1], SC, nmc));
                rs += sacc[nt][j0] + sacc[nt][j0 + 1];
            }
            rs += __shfl_xor_sync(0xffffffffu, rs, 1);
            rs += __shfl_xor_sync(0xffffffffu, rs, 2);
            lrow[r] += rs;
        }

        // ---- O += P @ V : V frags via ldmatrix.trans on row-major V ----
        // Source M0..M3 at (key row j*16+lr, d-word p*8+lc*4) transpose to
        // {d0-7 x keys0-7, d0-7 x keys8-15, d8-15 x keys0-7, d8-15 x keys8-15}
        // => b0 = {rv[0], rv[1]}, b1 = {rv[2], rv[3]}.
#pragma unroll
        for (int j = 0; j < 4; j++) {          // key chunks of 16
            uint32_t ap[4];
            ap[0] = pack_bf16(sacc[2 * j][0],     sacc[2 * j][1]);
            ap[1] = pack_bf16(sacc[2 * j][2],     sacc[2 * j][3]);
            ap[2] = pack_bf16(sacc[2 * j + 1][0], sacc[2 * j + 1][1]);
            ap[3] = pack_bf16(sacc[2 * j + 1][2], sacc[2 * j + 1][3]);
#pragma unroll
            for (int p = 0; p < 4; p++) {      // d chunks of 16
                uint32_t rv[4];
                ldsm4t(rv, vbuf + (uint32_t)(((j * 16 + lr) * AW + p * 8 + lc * 4) * 4));
                uint32_t b0[2] = { rv[0], rv[1] };
                uint32_t b1[2] = { rv[2], rv[3] };
                mma_bf16(oacc[p * 2 + 0], ap, b0);
                mma_bf16(oacc[p * 2 + 1], ap, b1);
            }
        }
        __syncthreads();
    }
#undef KV_ISSUE

    // ---- normalize + store (bf16) ----
    const float inv0 = 1.f / lrow[0];
    const float inv1 = 1.f / lrow[1];
#pragma unroll
    for (int nt = 0; nt < 8; nt++) {
        const int col = nt * 8 + 2 * t;
        const size_t o0 = base + (size_t)(q0 + m0 + g    ) * DD + col;
        const size_t o1 = base + (size_t)(q0 + m0 + g + 8) * DD + col;
        *(uint32_t*)(O + o0) = pack_bf16(oacc[nt][0] * inv0, oacc[nt][1] * inv0);
        *(uint32_t*)(O + o1) = pack_bf16(oacc[nt][2] * inv1, oacc[nt][3] * inv1);
    }
}

// ------------------------- LayerNorm -----------------------------------------
__global__ __launch_bounds__(256) void ln_kernel(
    const float* __restrict__ X, const float* __restrict__ gamma,
    const float* __restrict__ beta, float* __restrict__ out)
{
    __shared__ float ssum[8], ssq[8];
    const int row = blockIdx.x;
    const int tid = threadIdx.x;
    const float* x = X + (size_t)row * DD;

    float4 v = *(const float4*)(x + tid * 4);
    float s = v.x + v.y + v.z + v.w;
    float q = v.x * v.x + v.y * v.y + v.z * v.z + v.w * v.w;
#pragma unroll
    for (int off = 16; off > 0; off >>= 1) {
        s += __shfl_xor_sync(0xffffffffu, s, off);
        q += __shfl_xor_sync(0xffffffffu, q, off);
    }
    if ((tid & 31) == 0) { ssum[tid >> 5] = s; ssq[tid >> 5] = q; }
    __syncthreads();
    float ts = 0.f, tq = 0.f;
#pragma unroll
    for (int i = 0; i < 8; i++) { ts += ssum[i]; tq += ssq[i]; }

    const float mean = ts * (1.f / DD);
    const float var = tq * (1.f / DD) - mean * mean;
    const float inv = rsqrtf(var + 1e-5f);

    float4 gmv = *(const float4*)(gamma + tid * 4);
    float4 btv = *(const float4*)(beta + tid * 4);
    float4 o4;
    o4.x = (v.x - mean) * inv * gmv.x + btv.x;
    o4.y = (v.y - mean) * inv * gmv.y + btv.y;
    o4.z = (v.z - mean) * inv * gmv.z + btv.z;
    o4.w = (v.w - mean) * inv * gmv.w + btv.w;
    *(float4*)(out + (size_t)row * DD + tid * 4) = o4;
}

// ------------------------- launch --------------------------------------------
extern "C" void kernel_launch(void* const* d_in, const int* in_sizes, int n_in,
                              void* d_out, int out_size)
{
    const float* X     = (const float*)d_in[0];
    const float* Wq    = (const float*)d_in[1];
    const float* bq    = (const float*)d_in[2];
    const float* Wk    = (const float*)d_in[3];
    const float* bk    = (const float*)d_in[4];
    const float* Wv    = (const float*)d_in[5];
    const float* bv    = (const float*)d_in[6];
    const float* Wo    = (const float*)d_in[7];
    const float* bo    = (const float*)d_in[8];
    const float* gamma = (const float*)d_in[9];
    const float* beta  = (const float*)d_in[10];
    float* out = (float*)d_out;

    __nv_bfloat16 *Xb, *Qb, *Kb, *Vb, *Ob, *Wqkvt, *Wot;
    float* Rp;
    cudaGetSymbolAddress((void**)&Xb, g_Xb);
    cudaGetSymbolAddress((void**)&Qb, g_Qb);
    cudaGetSymbolAddress((void**)&Kb, g_Kb);
    cudaGetSymbolAddress((void**)&Vb, g_Vb);
    cudaGetSymbolAddress((void**)&Ob, g_Ob);
    cudaGetSymbolAddress((void**)&Wqkvt, g_Wqkvt);
    cudaGetSymbolAddress((void**)&Wot, g_Wot);
    cudaGetSymbolAddress((void**)&Rp, g_R);

    cudaFuncSetAttribute(gemm_qkv,
                         cudaFuncAttributeMaxDynamicSharedMemorySize, GEMM_SMEM);
    cudaFuncSetAttribute(gemm_out,
                         cudaFuncAttributeMaxDynamicSharedMemorySize, GEMM_SMEM);
    cudaFuncSetAttribute(attn_bf16,
                         cudaFuncAttributeMaxDynamicSharedMemorySize, ATT_SMEM);

    dim3 tgrid(DD / 32, DD / 32);
    dim3 tblk(32, 8);

    cvt_kernel<<<MM * DD / 4 / 256, 256>>>(X, Xb);
    wtrans_kernel<<<tgrid, tblk>>>(Wq, Wqkvt);
    wtrans_kernel<<<tgrid, tblk>>>(Wk, Wqkvt + (size_t)DD * DD);
    wtrans_kernel<<<tgrid, tblk>>>(Wv, Wqkvt + (size_t)2 * DD * DD);
    wtrans_kernel<<<tgrid, tblk>>>(Wo, Wot);

    gemm_qkv<<<dim3(24, MM / 128), 256, GEMM_SMEM>>>(Xb, Wqkvt, bq, bk, bv,
                                                     Qb, Kb, Vb);

    attn_bf16<<<dim3(LL / 128, BB * HH), 256, ATT_SMEM>>>(Qb, Kb, Vb, Ob);

    gemm_out<<<dim3(DD / 128, MM / 128), 256, GEMM_SMEM>>>(Ob, Wot, bo, X, Rp);

    ln_kernel<<<MM, 256>>>(Rp, gamma, beta, out);
}

// round 16
// speedup vs baseline: 6.1216x; 1.0153x over previous
#include <cuda_runtime.h>
#include <cuda_bf16.h>
#include <math.h>
#include <stdint.h>

// Problem dims
#define BB 4
#define LL 2048
#define DD 1024
#define HH 16
#define HD 64
#define MM (BB * LL)   // 8192

// ------------------------- scratch (static device globals) -------------------
__device__ __nv_bfloat16 g_Xb[MM * DD];
__device__ __nv_bfloat16 g_Qb[MM * DD];
__device__ __nv_bfloat16 g_Kb[MM * DD];
__device__ __nv_bfloat16 g_Vb[MM * DD];
__device__ __nv_bfloat16 g_Ob[MM * DD];
__device__ __nv_bfloat16 g_Wall[4 * DD * DD];    // [Wq|Wk|Wv|Wo] transposed bf16
__device__ float g_R[MM * DD];

// ========================= helpers ==========================================
__device__ __forceinline__ uint32_t smem_u32(const void* p) {
    uint32_t a;
    asm("{ .reg .u64 t; cvta.to.shared.u64 t, %1; cvt.u32.u64 %0, t; }"
        : "=r"(a) : "l"(p));
    return a;
}
#define CP_ASYNC16(dst, src) \
    asm volatile("cp.async.ca.shared.global [%0], [%1], 16;" :: "r"(dst), "l"(src))
#define CP_COMMIT() asm volatile("cp.async.commit_group;")
#define CP_WAIT1()  asm volatile("cp.async.wait_group 1;")

__device__ __forceinline__ uint32_t pack_bf16(float lo, float hi) {
    uint32_t r;
    asm("cvt.rn.bf16x2.f32 %0, %1, %2;" : "=r"(r) : "f"(hi), "f"(lo));
    return r;
}
__device__ __forceinline__ float ex2(float x) {
    float y;
    asm("ex2.approx.f32 %0, %1;" : "=f"(y) : "f"(x));
    return y;
}
__device__ __forceinline__ void ldsm4(uint32_t* r, uint32_t addr) {
    asm volatile("ldmatrix.sync.aligned.m8n8.x4.shared.b16 {%0,%1,%2,%3}, [%4];"
                 : "=r"(r[0]), "=r"(r[1]), "=r"(r[2]), "=r"(r[3]) : "r"(addr));
}
__device__ __forceinline__ void ldsm4t(uint32_t* r, uint32_t addr) {
    asm volatile("ldmatrix.sync.aligned.m8n8.x4.trans.shared.b16 {%0,%1,%2,%3}, [%4];"
                 : "=r"(r[0]), "=r"(r[1]), "=r"(r[2]), "=r"(r[3]) : "r"(addr));
}
__device__ __forceinline__ void mma_bf16(float* c, const uint32_t* a, const uint32_t* b) {
    asm volatile(
        "mma.sync.aligned.m16n8k16.row.col.f32.bf16.bf16.f32 "
        "{%0,%1,%2,%3}, {%4,%5,%6,%7}, {%8,%9}, {%0,%1,%2,%3};"
        : "+f"(c[0]), "+f"(c[1]), "+f"(c[2]), "+f"(c[3])
        : "r"(a[0]), "r"(a[1]), "r"(a[2]), "r"(a[3]), "r"(b[0]), "r"(b[1]));
}

// ========================= fp32 -> bf16 convert =============================
__global__ __launch_bounds__(256) void cvt_kernel(const float* __restrict__ X,
                                                  __nv_bfloat16* __restrict__ Y)
{
    const int i = blockIdx.x * 256 + threadIdx.x;
    float4 v = ((const float4*)X)[i];
    uint2 o;
    o.x = pack_bf16(v.x, v.y);
    o.y = pack_bf16(v.z, v.w);
    ((uint2*)Y)[i] = o;
}

// ======== 4-in-1 weight transpose: W[K][N] f32 -> Wall[z][N][K] bf16 ========
__global__ __launch_bounds__(256)
void wtrans4_kernel(const float* __restrict__ Wq, const float* __restrict__ Wk,
                    const float* __restrict__ Wv, const float* __restrict__ Wo,
                    __nv_bfloat16* __restrict__ Wall)
{
    __shared__ float tile[32][33];
    const int z = blockIdx.z;
    const float* W = (z == 0) ? Wq : (z == 1) ? Wk : (z == 2) ? Wv : Wo;
    __nv_bfloat16* Wt = Wall + (size_t)z * DD * DD;

    const int n0 = blockIdx.x * 32, k0 = blockIdx.y * 32;
    const int tx = threadIdx.x & 31, ty = threadIdx.x >> 5;   // 32 x 8
#pragma unroll
    for (int i = 0; i < 32; i += 8)
        tile[ty + i][tx] = W[(size_t)(k0 + ty + i) * DD + n0 + tx];
    __syncthreads();
#pragma unroll
    for (int i = 0; i < 32; i += 8)
        Wt[(size_t)(n0 + ty + i) * DD + k0 + tx] = __float2bfloat16(tile[tx][ty + i]);
}

// ========================= GEMM common pieces ================================
// 4-stage pipeline; barrier period covers TWO 32-k tiles (barriers halved);
// each period keeps the proven wait / sync / compute / sync / issue skeleton.
#define GW 20                          // words per smem row (32 bf16 + pad)
#define GTILEW (128 * GW)              // 2560 words per tile
#define GEMM_SMEM (4 * 2 * GTILEW * 4) // 81920 B

#define GEMM_ISSUE(kb, st) do {                                                  \
    const uint32_t ao_ = sbase + (uint32_t)(st) * 2 * GTILEW * 4;                \
    const uint32_t bo_ = ao_ + GTILEW * 4;                                       \
    _Pragma("unroll")                                                            \
    for (int i_ = 0; i_ < 2; i_++) {                                             \
        const int row_ = L_row + i_ * 64;                                        \
        CP_ASYNC16(ao_ + (uint32_t)(row_ * 80) + L_ch,                           \
                   Ab + (size_t)row_ * DD + (kb) * 32 + L_el);                   \
        CP_ASYNC16(bo_ + (uint32_t)(row_ * 80) + L_ch,                           \
                   Bb + (size_t)row_ * DD + (kb) * 32 + L_el);                   \
    }                                                                            \
} while (0)

#define GEMM_MAINLOOP()                                                          \
    GEMM_ISSUE(0, 0); GEMM_ISSUE(1, 1); CP_COMMIT();                             \
    GEMM_ISSUE(2, 2); GEMM_ISSUE(3, 3); CP_COMMIT();                             \
    float acc[4][4][4];                                                          \
    _Pragma("unroll")                                                            \
    for (int mt = 0; mt < 4; mt++)                                               \
        _Pragma("unroll")                                                        \
        for (int nt = 0; nt < 4; nt++)                                           \
            _Pragma("unroll")                                                    \
            for (int j = 0; j < 4; j++) acc[mt][nt][j] = 0.f;                    \
    const int NKT = DD / 32;                                                     \
    const int NP = NKT / 2;                                                      \
    for (int p = 0; p < NP; p++) {                                               \
        CP_WAIT1();                                                              \
        __syncthreads();                                                         \
        _Pragma("unroll")                                                        \
        for (int half = 0; half < 2; half++) {                                   \
            const int st = (2 * p + half) & 3;                                   \
            const uint32_t abase = sbase + (uint32_t)st * 2 * GTILEW * 4;        \
            const uint32_t bbase = abase + GTILEW * 4;                           \
            _Pragma("unroll")                                                    \
            for (int ks = 0; ks < 2; ks++) {                                     \
                uint32_t af[4][4], bq[2][4];                                     \
                _Pragma("unroll")                                                \
                for (int mt = 0; mt < 4; mt++)                                   \
                    ldsm4(af[mt], abase +                                        \
                          (uint32_t)(((wm * 64 + mt * 16 + lr) * GW + ks * 8 + lc * 4) * 4)); \
                _Pragma("unroll")                                                \
                for (int pp = 0; pp < 2; pp++)                                   \
                    ldsm4(bq[pp], bbase +                                        \
                          (uint32_t)(((wn * 32 + pp * 16 + lr) * GW + ks * 8 + lc * 4) * 4)); \
                uint32_t bf[4][2] = {                                            \
                    { bq[0][0], bq[0][2] }, { bq[0][1], bq[0][3] },              \
                    { bq[1][0], bq[1][2] }, { bq[1][1], bq[1][3] } };            \
                _Pragma("unroll")                                                \
                for (int mt = 0; mt < 4; mt++)                                   \
                    _Pragma("unroll")                                            \
                    for (int nt = 0; nt < 4; nt++)                               \
                        mma_bf16(acc[mt][nt], af[mt], bf[nt]);                   \
            }                                                                    \
        }                                                                        \
        __syncthreads();                                                         \
        if (2 * p + 4 < NKT) {                                                   \
            GEMM_ISSUE(2 * p + 4, (2 * p + 4) & 3);                              \
            GEMM_ISSUE(2 * p + 5, (2 * p + 5) & 3);                              \
        }                                                                        \
        CP_COMMIT();                                                             \
    }

// ---------------- merged QKV GEMM: grid.x = 24 (3 weights x 8 n-blocks) ------
__global__ __launch_bounds__(256)
void gemm_qkv(const __nv_bfloat16* __restrict__ A,
              const __nv_bfloat16* __restrict__ Wall,
              const float* __restrict__ bq, const float* __restrict__ bk,
              const float* __restrict__ bv,
              __nv_bfloat16* __restrict__ Qo, __nv_bfloat16* __restrict__ Ko,
              __nv_bfloat16* __restrict__ Vo)
{
    extern __shared__ uint32_t sm[];
    const uint32_t sbase = smem_u32(sm);

    const int tid = threadIdx.x;
    const int wid = tid >> 5, lane = tid & 31;
    const int g = lane >> 2, t = lane & 3;
    const int lr = lane & 15, lc = lane >> 4;
    const int wm = wid >> 2, wn = wid & 3;
    const int by = blockIdx.y;
    const int wsel = blockIdx.x >> 3;
    const int bx = blockIdx.x & 7;

    const float* bias = (wsel == 0) ? bq : (wsel == 1) ? bk : bv;
    __nv_bfloat16* Cout = (wsel == 0) ? Qo : (wsel == 1) ? Ko : Vo;

    const __nv_bfloat16* Ab = A + (size_t)(by * 128) * DD;
    const __nv_bfloat16* Bb = Wall + (size_t)wsel * DD * DD + (size_t)(bx * 128) * DD;

    const int L_row = tid >> 2;
    const int L_ch  = (tid & 3) * 16;
    const int L_el  = (tid & 3) * 8;

    GEMM_MAINLOOP();

    // epilogue (bf16 out)
#pragma unroll
    for (int nt = 0; nt < 4; nt++) {
        const int col = bx * 128 + wn * 32 + nt * 8 + 2 * t;
        const float b0 = bias[col], b1 = bias[col + 1];
#pragma unroll
        for (int mt = 0; mt < 4; mt++) {
            const int row = by * 128 + wm * 64 + mt * 16 + g;
            const size_t o0 = (size_t)row * DD + col;
            const size_t o1 = (size_t)(row + 8) * DD + col;
            *(uint32_t*)(Cout + o0) = pack_bf16(acc[mt][nt][0] + b0, acc[mt][nt][1] + b1);
            *(uint32_t*)(Cout + o1) = pack_bf16(acc[mt][nt][2] + b0, acc[mt][nt][3] + b1);
        }
    }
}

// ---------------- out-projection GEMM (f32 out + residual) -------------------
__global__ __launch_bounds__(256)
void gemm_out(const __nv_bfloat16* __restrict__ A, const __nv_bfloat16* __restrict__ Wall,
              const float* __restrict__ bias, const float* __restrict__ R,
              float* __restrict__ C)
{
    extern __shared__ uint32_t sm[];
    const uint32_t sbase = smem_u32(sm);

    const int tid = threadIdx.x;
    const int wid = tid >> 5, lane = tid & 31;
    const int g = lane >> 2, t = lane & 3;
    const int lr = lane & 15, lc = lane >> 4;
    const int wm = wid >> 2, wn = wid & 3;
    const int bx = blockIdx.x, by = blockIdx.y;

    const __nv_bfloat16* Ab = A + (size_t)(by * 128) * DD;
    const __nv_bfloat16* Bb = Wall + (size_t)3 * DD * DD + (size_t)(bx * 128) * DD;

    const int L_row = tid >> 2;
    const int L_ch  = (tid & 3) * 16;
    const int L_el  = (tid & 3) * 8;

    GEMM_MAINLOOP();

#pragma unroll
    for (int nt = 0; nt < 4; nt++) {
        const int col = bx * 128 + wn * 32 + nt * 8 + 2 * t;
        const float b0 = bias[col], b1 = bias[col + 1];
#pragma unroll
        for (int mt = 0; mt < 4; mt++) {
            const int row = by * 128 + wm * 64 + mt * 16 + g;
            const size_t o0 = (size_t)row * DD + col;
            const size_t o1 = (size_t)(row + 8) * DD + col;
            float2 r0 = *(const float2*)(R + o0);
            float2 r1 = *(const float2*)(R + o1);
            *(float2*)(C + o0) = make_float2(acc[mt][nt][0] + b0 + r0.x,
                                             acc[mt][nt][1] + b1 + r0.y);
            *(float2*)(C + o1) = make_float2(acc[mt][nt][2] + b0 + r1.x,
                                             acc[mt][nt][3] + b1 + r1.y);
        }
    }
}

// ========================= bf16 flash attention (R15, unchanged) =============
#define AW 36                                   // word stride (72 bf16, 144 B)
#define QW_OFF 0
#define KW_OFF (128 * AW)
#define VW_OFF (KW_OFF + 2 * 64 * AW)
#define ATT_WORDS (VW_OFF + 2 * 64 * AW)
#define ATT_SMEM (ATT_WORDS * 4)                // 55296 B

__global__ __launch_bounds__(256, 2)
void attn_bf16(const __nv_bfloat16* __restrict__ Q, const __nv_bfloat16* __restrict__ K,
               const __nv_bfloat16* __restrict__ V, __nv_bfloat16* __restrict__ O)
{
    extern __shared__ uint32_t sm[];
    const uint32_t sbase = smem_u32(sm);
    const uint32_t qaddr = sbase + QW_OFF * 4;
    const uint32_t kaddr = sbase + KW_OFF * 4;
    const uint32_t vaddr = sbase + VW_OFF * 4;

    const int tid = threadIdx.x;
    const int wid = tid >> 5, lane = tid & 31;
    const int g = lane >> 2, t = lane & 3;
    const int lr = lane & 15, lc = lane >> 4;
    const int m0 = wid * 16;

    const int bh = blockIdx.y;
    const int b = bh >> 4, h = bh & 15;
    const int q0 = blockIdx.x * 128;
    const size_t base = (size_t)b * LL * DD + (size_t)h * HD;

#define KV_ISSUE(blk, buf) do {                                                  \
    const uint32_t ko_ = kaddr + (uint32_t)((buf) * 64 * AW * 4);                \
    const uint32_t vo_ = vaddr + (uint32_t)((buf) * 64 * AW * 4);                \
    _Pragma("unroll")                                                            \
    for (int ii_ = 0; ii_ < 2; ii_++) {                                          \
        const int c_ = tid + ii_ * 256;                                          \
        const int row_ = c_ >> 3, ch_ = (c_ & 7) * 16, el_ = (c_ & 7) * 8;       \
        const size_t go_ = base + (size_t)((blk) * 64 + row_) * DD + el_;        \
        CP_ASYNC16(ko_ + (uint32_t)(row_ * 144) + ch_, K + go_);                 \
        CP_ASYNC16(vo_ + (uint32_t)(row_ * 144) + ch_, V + go_);                 \
    }                                                                            \
} while (0)

    // ---- prologue: Q + K0 + V0 cp.async (one group) ----
    {
#pragma unroll
        for (int i = 0; i < 4; i++) {
            const int c = tid + i * 256;
            const int row = c >> 3, ch = (c & 7) * 16, el = (c & 7) * 8;
            CP_ASYNC16(qaddr + (uint32_t)(row * 144) + ch,
                       Q + base + (size_t)(q0 + row) * DD + el);
        }
        KV_ISSUE(0, 0);
        CP_COMMIT();
    }

    float oacc[8][4];
    float mrow[2] = { -1e30f, -1e30f };
    float lrow[2] = { 0.f, 0.f };
    uint32_t aqf[4][4];                 // hoisted Q fragments (loop-invariant)
#pragma unroll
    for (int nt = 0; nt < 8; nt++)
#pragma unroll
        for (int j = 0; j < 4; j++) oacc[nt][j] = 0.f;

    const float SC = 0.18033688011112042f;   // 0.125 * log2(e)
    const int NBLK = LL / 64;
    for (int i = 0; i < NBLK; i++) {
        const int buf = i & 1;
        if (i + 1 < NBLK) KV_ISSUE(i + 1, buf ^ 1);
        CP_COMMIT();
        CP_WAIT1();
        __syncthreads();

        if (i == 0) {
#pragma unroll
            for (int ks = 0; ks < 4; ks++)
                ldsm4(aqf[ks], qaddr + (uint32_t)(((m0 + lr) * AW + ks * 8 + lc * 4) * 4));
        }

        const uint32_t kbuf = kaddr + (uint32_t)(buf * 64 * AW * 4);
        const uint32_t vbuf = vaddr + (uint32_t)(buf * 64 * AW * 4);

        // ---- S = Q @ K^T ----
        float sacc[8][4];
#pragma unroll
        for (int nt = 0; nt < 8; nt++)
#pragma unroll
            for (int j = 0; j < 4; j++) sacc[nt][j] = 0.f;

#pragma unroll
        for (int ks = 0; ks < 4; ks++) {
#pragma unroll
            for (int p = 0; p < 4; p++) {
                uint32_t bq[4];
                ldsm4(bq, kbuf + (uint32_t)(((p * 16 + lr) * AW + ks * 8 + lc * 4) * 4));
                uint32_t b0[2] = { bq[0], bq[2] };
                uint32_t b1[2] = { bq[1], bq[3] };
                mma_bf16(sacc[p * 2 + 0], aqf[ks], b0);
                mma_bf16(sacc[p * 2 + 1], aqf[ks], b1);
            }
        }

        // ---- online softmax (exp2 form; exact lazy rescale) ----
#pragma unroll
        for (int r = 0; r < 2; r++) {
            const int j0 = r * 2;
            float mx = -1e30f;
#pragma unroll
            for (int nt = 0; nt < 8; nt++)
                mx = fmaxf(mx, fmaxf(sacc[nt][j0], sacc[nt][j0 + 1]));
            mx = fmaxf(mx, __shfl_xor_sync(0xffffffffu, mx, 1));
            mx = fmaxf(mx, __shfl_xor_sync(0xffffffffu, mx, 2));
            const float mnew = fmaxf(mrow[r], mx);
            const float nmc = -mnew * SC;
            const bool changed = mnew > mrow[r];
            if (__any_sync(0xffffffffu, changed)) {
                const float alpha = ex2(fmaf(mrow[r], SC, nmc));
                lrow[r] *= alpha;
#pragma unroll
                for (int nt = 0; nt < 8; nt++) {
                    oacc[nt][j0]     *= alpha;
                    oacc[nt][j0 + 1] *= alpha;
                }
            }
            mrow[r] = mnew;
            float rs = 0.f;
#pragma unroll
            for (int nt = 0; nt < 8; nt++) {
                sacc[nt][j0]     = ex2(fmaf(sacc[nt][j0],     SC, nmc));
                sacc[nt][j0 + 1] = ex2(fmaf(sacc[nt][j0 + 1], SC, nmc));
                rs += sacc[nt][j0] + sacc[nt][j0 + 1];
            }
            rs += __shfl_xor_sync(0xffffffffu, rs, 1);
            rs += __shfl_xor_sync(0xffffffffu, rs, 2);
            lrow[r] += rs;
        }

        // ---- O += P @ V : V frags via ldmatrix.trans on row-major V ----
#pragma unroll
        for (int j = 0; j < 4; j++) {
            uint32_t ap[4];
            ap[0] = pack_bf16(sacc[2 * j][0],     sacc[2 * j][1]);
            ap[1] = pack_bf16(sacc[2 * j][2],     sacc[2 * j][3]);
            ap[2] = pack_bf16(sacc[2 * j + 1][0], sacc[2 * j + 1][1]);
            ap[3] = pack_bf16(sacc[2 * j + 1][2], sacc[2 * j + 1][3]);
#pragma unroll
            for (int p = 0; p < 4; p++) {
                uint32_t rv[4];
                ldsm4t(rv, vbuf + (uint32_t)(((j * 16 + lr) * AW + p * 8 + lc * 4) * 4));
                uint32_t b0[2] = { rv[0], rv[1] };
                uint32_t b1[2] = { rv[2], rv[3] };
                mma_bf16(oacc[p * 2 + 0], ap, b0);
                mma_bf16(oacc[p * 2 + 1], ap, b1);
            }
        }
        __syncthreads();
    }
#undef KV_ISSUE

    // ---- normalize + store (bf16) ----
    const float inv0 = 1.f / lrow[0];
    const float inv1 = 1.f / lrow[1];
#pragma unroll
    for (int nt = 0; nt < 8; nt++) {
        const int col = nt * 8 + 2 * t;
        const size_t o0 = base + (size_t)(q0 + m0 + g    ) * DD + col;
        const size_t o1 = base + (size_t)(q0 + m0 + g + 8) * DD + col;
        *(uint32_t*)(O + o0) = pack_bf16(oacc[nt][0] * inv0, oacc[nt][1] * inv0);
        *(uint32_t*)(O + o1) = pack_bf16(oacc[nt][2] * inv1, oacc[nt][3] * inv1);
    }
}

// ------------------------- LayerNorm -----------------------------------------
__global__ __launch_bounds__(256) void ln_kernel(
    const float* __restrict__ X, const float* __restrict__ gamma,
    const float* __restrict__ beta, float* __restrict__ out)
{
    __shared__ float ssum[8], ssq[8];
    const int row = blockIdx.x;
    const int tid = threadIdx.x;
    const float* x = X + (size_t)row * DD;

    float4 v = *(const float4*)(x + tid * 4);
    float s = v.x + v.y + v.z + v.w;
    float q = v.x * v.x + v.y * v.y + v.z * v.z + v.w * v.w;
#pragma unroll
    for (int off = 16; off > 0; off >>= 1) {
        s += __shfl_xor_sync(0xffffffffu, s, off);
        q += __shfl_xor_sync(0xffffffffu, q, off);
    }
    if ((tid & 31) == 0) { ssum[tid >> 5] = s; ssq[tid >> 5] = q; }
    __syncthreads();
    float ts = 0.f, tq = 0.f;
#pragma unroll
    for (int i = 0; i < 8; i++) { ts += ssum[i]; tq += ssq[i]; }

    const float mean = ts * (1.f / DD);
    const float var = tq * (1.f / DD) - mean * mean;
    const float inv = rsqrtf(var + 1e-5f);

    float4 gmv = *(const float4*)(gamma + tid * 4);
    float4 btv = *(const float4*)(beta + tid * 4);
    float4 o4;
    o4.x = (v.x - mean) * inv * gmv.x + btv.x;
    o4.y = (v.y - mean) * inv * gmv.y + btv.y;
    o4.z = (v.z - mean) * inv * gmv.z + btv.z;
    o4.w = (v.w - mean) * inv * gmv.w + btv.w;
    *(float4*)(out + (size_t)row * DD + tid * 4) = o4;
}

// ------------------------- launch --------------------------------------------
extern "C" void kernel_launch(void* const* d_in, const int* in_sizes, int n_in,
                              void* d_out, int out_size)
{
    const float* X     = (const float*)d_in[0];
    const float* Wq    = (const float*)d_in[1];
    const float* bq    = (const float*)d_in[2];
    const float* Wk    = (const float*)d_in[3];
    const float* bk    = (const float*)d_in[4];
    const float* Wv    = (const float*)d_in[5];
    const float* bv    = (const float*)d_in[6];
    const float* Wo    = (const float*)d_in[7];
    const float* bo    = (const float*)d_in[8];
    const float* gamma = (const float*)d_in[9];
    const float* beta  = (const float*)d_in[10];
    float* out = (float*)d_out;

    __nv_bfloat16 *Xb, *Qb, *Kb, *Vb, *Ob, *Wall;
    float* Rp;
    cudaGetSymbolAddress((void**)&Xb, g_Xb);
    cudaGetSymbolAddress((void**)&Qb, g_Qb);
    cudaGetSymbolAddress((void**)&Kb, g_Kb);
    cudaGetSymbolAddress((void**)&Vb, g_Vb);
    cudaGetSymbolAddress((void**)&Ob, g_Ob);
    cudaGetSymbolAddress((void**)&Wall, g_Wall);
    cudaGetSymbolAddress((void**)&Rp, g_R);

    cudaFuncSetAttribute(gemm_qkv,
                         cudaFuncAttributeMaxDynamicSharedMemorySize, GEMM_SMEM);
    cudaFuncSetAttribute(gemm_out,
                         cudaFuncAttributeMaxDynamicSharedMemorySize, GEMM_SMEM);
    cudaFuncSetAttribute(attn_bf16,
                         cudaFuncAttributeMaxDynamicSharedMemorySize, ATT_SMEM);

    cvt_kernel<<<MM * DD / 4 / 256, 256>>>(X, Xb);
    wtrans4_kernel<<<dim3(DD / 32, DD / 32, 4), 256>>>(Wq, Wk, Wv, Wo, Wall);

    gemm_qkv<<<dim3(24, MM / 128), 256, GEMM_SMEM>>>(Xb, Wall, bq, bk, bv,
                                                     Qb, Kb, Vb);

    attn_bf16<<<dim3(LL / 128, BB * HH), 256, ATT_SMEM>>>(Qb, Kb, Vb, Ob);

    gemm_out<<<dim3(DD / 128, MM / 128), 256, GEMM_SMEM>>>(Ob, Wall, bo, X, Rp);

    ln_kernel<<<MM, 256>>>(Rp, gamma, beta, out);
}